// round 1
// baseline (speedup 1.0000x reference)
#include <cuda_runtime.h>
#include <math_constants.h>
#include <cstddef>

#define BB 4
#define CCH 512
#define C8 64
#define HH 128
#define WW 128
#define HWV (HH*WW)

static const size_t NTOT = (size_t)BB * CCH * HWV;   // 33,554,432

// ---------------- scratch (device globals; no runtime allocation) ----------
__device__ float g_q  [BB*C8 *HWV];
__device__ float g_k  [BB*C8 *HWV];
__device__ float g_qT [BB*C8 *HWV];   // [b][w][c][h]
__device__ float g_kT [BB*C8 *HWV];   // [b][w][c][h]
__device__ float g_v  [(size_t)BB*CCH*HWV];
__device__ float g_vT [(size_t)BB*CCH*HWV];  // [b][w][c][h(=j)]
__device__ float g_att[(size_t)BB*HH*WW*256];
__device__ float g_s1 [(size_t)BB*CCH*HWV];  // out_H, layout [b][c][w][h]
__device__ float g_s2 [(size_t)BB*CCH*HWV];  // out_W, layout [b][c][h][w]

// ---------------- conv1x1: out[b,o,n] = bias[o] + sum_c W[o,c] x[b,c,n] ----
// Tile: 64(M=o) x 128(N=n) x 16(K=c), 256 threads, 4x8 micro-tile.
__global__ void conv1x1_kernel(float* __restrict__ out,
                               const float* __restrict__ x,
                               const float* __restrict__ Wt,
                               const float* __restrict__ bias,
                               int Cout) {
    const int Cin = CCH;
    __shared__ float As[16][68];    // [k][m], transposed store, padded
    __shared__ float Bs[16][128];   // [k][n]
    int tid = threadIdx.x;
    int nblk = blockIdx.x * 128;
    int o0   = blockIdx.y * 64;
    int b    = blockIdx.z;
    int tx = tid & 15, ty = tid >> 4;
    int m0 = ty * 4, n0 = tx * 8;

    float acc[4][8];
#pragma unroll
    for (int i = 0; i < 4; i++)
#pragma unroll
        for (int j = 0; j < 8; j++) acc[i][j] = 0.f;

    const float* xb = x + (size_t)b * Cin * HWV + nblk;

    for (int k0 = 0; k0 < Cin; k0 += 16) {
#pragma unroll
        for (int i = 0; i < 4; i++) {
            int idx = tid + i * 256;
            int m = idx >> 4, kk = idx & 15;
            As[kk][m] = Wt[(o0 + m) * Cin + k0 + kk];
        }
#pragma unroll
        for (int i = 0; i < 8; i++) {
            int idx = tid + i * 256;
            int kk = idx >> 7, n = idx & 127;
            Bs[kk][n] = xb[(size_t)(k0 + kk) * HWV + n];
        }
        __syncthreads();
#pragma unroll
        for (int kk = 0; kk < 16; kk++) {
            float a[4], bb[8];
            *(float4*)a       = *(const float4*)&As[kk][m0];
            *(float4*)&bb[0]  = *(const float4*)&Bs[kk][n0];
            *(float4*)&bb[4]  = *(const float4*)&Bs[kk][n0 + 4];
#pragma unroll
            for (int i = 0; i < 4; i++)
#pragma unroll
                for (int j = 0; j < 8; j++) acc[i][j] += a[i] * bb[j];
        }
        __syncthreads();
    }
#pragma unroll
    for (int i = 0; i < 4; i++) {
        int o = o0 + m0 + i;
        float bv = bias[o];
        float4 r0, r1;
        r0.x = acc[i][0] + bv; r0.y = acc[i][1] + bv;
        r0.z = acc[i][2] + bv; r0.w = acc[i][3] + bv;
        r1.x = acc[i][4] + bv; r1.y = acc[i][5] + bv;
        r1.z = acc[i][6] + bv; r1.w = acc[i][7] + bv;
        float* op = out + ((size_t)b * Cout + o) * HWV + nblk + n0;
        *(float4*)op       = r0;
        *(float4*)(op + 4) = r1;
    }
}

// ---------------- transpose: src[b][c][h][w] -> dst[b][w][c][h] ------------
__global__ void transpose_hw_kernel(float* __restrict__ dst,
                                    const float* __restrict__ src, int Cch) {
    __shared__ float tile[32][33];
    int bc = blockIdx.z;
    int b = bc / Cch, c = bc % Cch;
    int w0 = blockIdx.x * 32, h0 = blockIdx.y * 32;
    int tx = threadIdx.x, ty = threadIdx.y;
    const float* s = src + (size_t)bc * HWV;
#pragma unroll
    for (int r = 0; r < 4; r++) {
        int h = h0 + ty + r * 8;
        tile[ty + r * 8][tx] = s[(size_t)h * WW + w0 + tx];   // tile[h_loc][w_loc]... wait
    }
    __syncthreads();
#pragma unroll
    for (int r = 0; r < 4; r++) {
        int w = w0 + ty + r * 8;
        // need src value at (h = h0 + tx, w): that is tile[tx][?]
        dst[(((size_t)b * WW + w) * Cch + c) * HH + h0 + tx] = tile[tx][ty + r * 8];
    }
}
// NOTE on indexing above: phase1 stores tile[a][b] = src[h0+a][w0+b] with a=ty+8r (h), b=tx (w).
// phase2 reads value for (h=h0+X, w=w0+Y) as tile[X][Y] with X=tx, Y=ty+8r.  Consistent.

// ---------------- energy_H: per (b,w), e[h,j] = sum_c qT[c,h]*kT[c,j] ------
__global__ void energy_h_kernel() {
    __shared__ float As[16][128];
    __shared__ float Bs[16][128];
    int w = blockIdx.x, b = blockIdx.y;
    int tid = threadIdx.x;
    int tx = tid & 15, ty = tid >> 4;
    int m0 = ty * 8, n0 = tx * 8;
    const float* qT = g_qT + ((size_t)(b * WW + w)) * C8 * HH;
    const float* kT = g_kT + ((size_t)(b * WW + w)) * C8 * HH;
    float acc[8][8];
#pragma unroll
    for (int i = 0; i < 8; i++)
#pragma unroll
        for (int j = 0; j < 8; j++) acc[i][j] = 0.f;

    for (int k0 = 0; k0 < C8; k0 += 16) {
#pragma unroll
        for (int i = 0; i < 8; i++) {
            int idx = tid + i * 256;
            int cc = idx >> 7, hh = idx & 127;
            As[cc][hh] = qT[(k0 + cc) * HH + hh];
            Bs[cc][hh] = kT[(k0 + cc) * HH + hh];
        }
        __syncthreads();
#pragma unroll
        for (int kk = 0; kk < 16; kk++) {
            float a[8], bb[8];
            *(float4*)&a[0]  = *(const float4*)&As[kk][m0];
            *(float4*)&a[4]  = *(const float4*)&As[kk][m0 + 4];
            *(float4*)&bb[0] = *(const float4*)&Bs[kk][n0];
            *(float4*)&bb[4] = *(const float4*)&Bs[kk][n0 + 4];
#pragma unroll
            for (int i = 0; i < 8; i++)
#pragma unroll
                for (int j = 0; j < 8; j++) acc[i][j] += a[i] * bb[j];
        }
        __syncthreads();
    }
#pragma unroll
    for (int i = 0; i < 8; i++) {
        int h = m0 + i;
        float* row = g_att + (((size_t)b * HH + h) * WW + w) * 256;
#pragma unroll
        for (int j = 0; j < 8; j++) {
            int jj = n0 + j;
            row[jj] = (jj == h) ? -CUDART_INF_F : acc[i][j];
        }
    }
}

// ---------------- energy_W: per (b,h), e[w,j] = sum_c q[c,w]*k[c,j] --------
__global__ void energy_w_kernel() {
    __shared__ float As[16][128];
    __shared__ float Bs[16][128];
    int h = blockIdx.x, b = blockIdx.y;
    int tid = threadIdx.x;
    int tx = tid & 15, ty = tid >> 4;
    int m0 = ty * 8, n0 = tx * 8;
    const float* qp = g_q + (size_t)b * C8 * HWV + (size_t)h * WW;
    const float* kp = g_k + (size_t)b * C8 * HWV + (size_t)h * WW;
    float acc[8][8];
#pragma unroll
    for (int i = 0; i < 8; i++)
#pragma unroll
        for (int j = 0; j < 8; j++) acc[i][j] = 0.f;

    for (int k0 = 0; k0 < C8; k0 += 16) {
#pragma unroll
        for (int i = 0; i < 8; i++) {
            int idx = tid + i * 256;
            int cc = idx >> 7, nn = idx & 127;
            As[cc][nn] = qp[(size_t)(k0 + cc) * HWV + nn];
            Bs[cc][nn] = kp[(size_t)(k0 + cc) * HWV + nn];
        }
        __syncthreads();
#pragma unroll
        for (int kk = 0; kk < 16; kk++) {
            float a[8], bb[8];
            *(float4*)&a[0]  = *(const float4*)&As[kk][m0];
            *(float4*)&a[4]  = *(const float4*)&As[kk][m0 + 4];
            *(float4*)&bb[0] = *(const float4*)&Bs[kk][n0];
            *(float4*)&bb[4] = *(const float4*)&Bs[kk][n0 + 4];
#pragma unroll
            for (int i = 0; i < 8; i++)
#pragma unroll
                for (int j = 0; j < 8; j++) acc[i][j] += a[i] * bb[j];
        }
        __syncthreads();
    }
#pragma unroll
    for (int i = 0; i < 8; i++) {
        int wv = m0 + i;
        float* row = g_att + (((size_t)b * HH + h) * WW + wv) * 256 + 128;
#pragma unroll
        for (int j = 0; j < 8; j++) row[n0 + j] = acc[i][j];
    }
}

// ---------------- softmax over rows of 256 (one warp per row) --------------
__global__ void softmax_kernel() {
    int row  = blockIdx.x * 8 + (threadIdx.x >> 5);
    int lane = threadIdx.x & 31;
    float* p = g_att + (size_t)row * 256;
    float v[8];
    float m = -CUDART_INF_F;
#pragma unroll
    for (int i = 0; i < 8; i++) { v[i] = p[lane + 32 * i]; m = fmaxf(m, v[i]); }
#pragma unroll
    for (int o = 16; o > 0; o >>= 1) m = fmaxf(m, __shfl_xor_sync(0xffffffffu, m, o));
    float s = 0.f;
#pragma unroll
    for (int i = 0; i < 8; i++) { v[i] = __expf(v[i] - m); s += v[i]; }
#pragma unroll
    for (int o = 16; o > 0; o >>= 1) s += __shfl_xor_sync(0xffffffffu, s, o);
    float inv = 1.0f / s;
#pragma unroll
    for (int i = 0; i < 8; i++) p[lane + 32 * i] = v[i] * inv;
}

// ---------------- out_H: per (b,w,ct): S1[c,h] = sum_j vT[c,j]*attH[h,j] ---
__global__ void out_h_kernel() {
    __shared__ float As[16][132];   // [j][c]
    __shared__ float Bs[16][132];   // [j][h]
    int ct = blockIdx.x, w = blockIdx.y, b = blockIdx.z;
    int tid = threadIdx.x;
    int tx = tid & 15, ty = tid >> 4;
    int m0 = ty * 8, n0 = tx * 8;
    const float* vt   = g_vT  + (((size_t)b * WW + w) * CCH + ct * 128) * HH;
    const float* attb = g_att + (((size_t)b * HH) * WW + w) * 256;
    float acc[8][8];
#pragma unroll
    for (int i = 0; i < 8; i++)
#pragma unroll
        for (int j = 0; j < 8; j++) acc[i][j] = 0.f;

    for (int k0 = 0; k0 < 128; k0 += 16) {
#pragma unroll
        for (int i = 0; i < 8; i++) {
            int idx = tid + i * 256;
            int m = idx >> 4, kk = idx & 15;
            As[kk][m] = vt[(size_t)m * HH + k0 + kk];
            Bs[kk][m] = attb[(size_t)m * WW * 256 + k0 + kk];
        }
        __syncthreads();
#pragma unroll
        for (int kk = 0; kk < 16; kk++) {
            float a[8], bb[8];
            *(float4*)&a[0]  = *(const float4*)&As[kk][m0];
            *(float4*)&a[4]  = *(const float4*)&As[kk][m0 + 4];
            *(float4*)&bb[0] = *(const float4*)&Bs[kk][n0];
            *(float4*)&bb[4] = *(const float4*)&Bs[kk][n0 + 4];
#pragma unroll
            for (int i = 0; i < 8; i++)
#pragma unroll
                for (int j = 0; j < 8; j++) acc[i][j] += a[i] * bb[j];
        }
        __syncthreads();
    }
    // write S1 layout [b][c][w][h]  (h contiguous => coalesced)
#pragma unroll
    for (int i = 0; i < 8; i++) {
        float* op = g_s1 + (((size_t)b * CCH + ct * 128 + m0 + i) * WW + w) * HH + n0;
        float4 r0, r1;
        r0.x = acc[i][0]; r0.y = acc[i][1]; r0.z = acc[i][2]; r0.w = acc[i][3];
        r1.x = acc[i][4]; r1.y = acc[i][5]; r1.z = acc[i][6]; r1.w = acc[i][7];
        *(float4*)op = r0; *(float4*)(op + 4) = r1;
    }
}

// ---------------- out_W: per (b,h,ct): S2[c,w] = sum_j v[c,h,j]*attW[w,j] --
__global__ void out_w_kernel() {
    __shared__ float As[16][132];   // [j][c]
    __shared__ float Bs[16][132];   // [j][w]
    int ct = blockIdx.x, h = blockIdx.y, b = blockIdx.z;
    int tid = threadIdx.x;
    int tx = tid & 15, ty = tid >> 4;
    int m0 = ty * 8, n0 = tx * 8;
    const float* vp   = g_v   + ((size_t)b * CCH + ct * 128) * HWV + (size_t)h * WW;
    const float* attb = g_att + (((size_t)b * HH + h) * WW) * 256 + 128;
    float acc[8][8];
#pragma unroll
    for (int i = 0; i < 8; i++)
#pragma unroll
        for (int j = 0; j < 8; j++) acc[i][j] = 0.f;

    for (int k0 = 0; k0 < 128; k0 += 16) {
#pragma unroll
        for (int i = 0; i < 8; i++) {
            int idx = tid + i * 256;
            int m = idx >> 4, kk = idx & 15;
            As[kk][m] = vp[(size_t)m * HWV + k0 + kk];
            Bs[kk][m] = attb[(size_t)m * 256 + k0 + kk];
        }
        __syncthreads();
#pragma unroll
        for (int kk = 0; kk < 16; kk++) {
            float a[8], bb[8];
            *(float4*)&a[0]  = *(const float4*)&As[kk][m0];
            *(float4*)&a[4]  = *(const float4*)&As[kk][m0 + 4];
            *(float4*)&bb[0] = *(const float4*)&Bs[kk][n0];
            *(float4*)&bb[4] = *(const float4*)&Bs[kk][n0 + 4];
#pragma unroll
            for (int i = 0; i < 8; i++)
#pragma unroll
                for (int j = 0; j < 8; j++) acc[i][j] += a[i] * bb[j];
        }
        __syncthreads();
    }
    // write S2 natural layout [b][c][h][w]  (w contiguous => coalesced)
#pragma unroll
    for (int i = 0; i < 8; i++) {
        float* op = g_s2 + (((size_t)b * CCH + ct * 128 + m0 + i) * HH + h) * WW + n0;
        float4 r0, r1;
        r0.x = acc[i][0]; r0.y = acc[i][1]; r0.z = acc[i][2]; r0.w = acc[i][3];
        r1.x = acc[i][4]; r1.y = acc[i][5]; r1.z = acc[i][6]; r1.w = acc[i][7];
        *(float4*)op = r0; *(float4*)(op + 4) = r1;
    }
}

// ---------------- combine: out1/out2 = gamma*(S1+S2+2) + residuals ---------
__global__ void combine_kernel(float* __restrict__ out,
                               const float* __restrict__ xe,
                               const float* __restrict__ xq,
                               const float* __restrict__ g1p,
                               const float* __restrict__ g2p) {
    __shared__ float tile[32][33];
    int bc = blockIdx.z;
    int w0 = blockIdx.x * 32, h0 = blockIdx.y * 32;
    int tx = threadIdx.x, ty = threadIdx.y;
    size_t base = (size_t)bc * HWV;
    // g_s1 layout [bc][w][h]: read coalesced in h, transpose via smem
#pragma unroll
    for (int r = 0; r < 4; r++) {
        int wv = w0 + ty + r * 8;
        tile[ty + r * 8][tx] = g_s1[base + (size_t)wv * HH + h0 + tx];
    }
    __syncthreads();
    float gam1 = g1p[0], gam2 = g2p[0];
#pragma unroll
    for (int r = 0; r < 4; r++) {
        int h = h0 + ty + r * 8;
        int wv = w0 + tx;
        size_t idx = base + (size_t)h * WW + wv;
        float t = tile[tx][ty + r * 8] + g_s2[idx] + 2.0f;
        out[idx]        = fmaf(gam1, t, xe[idx]);
        out[NTOT + idx] = fmaf(gam2, t, xq[idx]);
    }
}

// ---------------- launch ----------------------------------------------------
extern "C" void kernel_launch(void* const* d_in, const int* in_sizes, int n_in,
                              void* d_out, int out_size) {
    const float* xe = (const float*)d_in[0];
    const float* xq = (const float*)d_in[1];
    const float* Wq = (const float*)d_in[2];
    const float* bq = (const float*)d_in[3];
    const float* Wk = (const float*)d_in[4];
    const float* bk = (const float*)d_in[5];
    const float* Wv = (const float*)d_in[6];
    const float* bv = (const float*)d_in[7];
    const float* g1 = (const float*)d_in[8];
    const float* g2 = (const float*)d_in[9];
    float* out = (float*)d_out;

    float *pq, *pk, *pqT, *pkT, *pv, *pvT;
    cudaGetSymbolAddress((void**)&pq,  g_q);
    cudaGetSymbolAddress((void**)&pk,  g_k);
    cudaGetSymbolAddress((void**)&pqT, g_qT);
    cudaGetSymbolAddress((void**)&pkT, g_kT);
    cudaGetSymbolAddress((void**)&pv,  g_v);
    cudaGetSymbolAddress((void**)&pvT, g_vT);

    // projections
    conv1x1_kernel<<<dim3(HWV / 128, C8 / 64, BB), 256>>>(pq, xq, Wq, bq, C8);
    conv1x1_kernel<<<dim3(HWV / 128, C8 / 64, BB), 256>>>(pk, xe, Wk, bk, C8);
    conv1x1_kernel<<<dim3(HWV / 128, CCH / 64, BB), 256>>>(pv, xe, Wv, bv, CCH);

    // transposes for column-attention access
    transpose_hw_kernel<<<dim3(4, 4, BB * C8),  dim3(32, 8)>>>(pqT, pq, C8);
    transpose_hw_kernel<<<dim3(4, 4, BB * C8),  dim3(32, 8)>>>(pkT, pk, C8);
    transpose_hw_kernel<<<dim3(4, 4, BB * CCH), dim3(32, 8)>>>(pvT, pv, CCH);

    // energies + fused softmax over concat(256)
    energy_h_kernel<<<dim3(WW, BB), 256>>>();
    energy_w_kernel<<<dim3(HH, BB), 256>>>();
    softmax_kernel<<<(BB * HH * WW) / 8, 256>>>();

    // attention outputs
    out_h_kernel<<<dim3(CCH / 128, WW, BB), 256>>>();
    out_w_kernel<<<dim3(CCH / 128, HH, BB), 256>>>();

    // combine: gamma*(out_H + out_W + 2) + residuals  (diagonal branch == +2)
    combine_kernel<<<dim3(4, 4, BB * CCH), dim3(32, 8)>>>(out, xe, xq, g1, g2);
}

// round 3
// speedup vs baseline: 1.6051x; 1.6051x over previous
#include <cuda_runtime.h>
#include <cuda_fp16.h>
#include <math_constants.h>
#include <cstdint>
#include <cstddef>

#define BB 4
#define CCH 512
#define C8 64
#define HH 128
#define WW 128
#define HWV (HH*WW)

static const size_t NTOT = (size_t)BB * CCH * HWV;   // 33,554,432

// ---------------- scratch (device globals; no runtime allocation) ----------
__device__ __align__(16) float g_qT [BB*C8 *HWV];                 // [b][w][c][h]
__device__ __align__(16) float g_kT [BB*C8 *HWV];                 // [b][w][c][h]
__device__ __align__(16) float g_v  [(size_t)BB*CCH*HWV];         // [b][c][h][w]
__device__ __align__(16) float g_vT [(size_t)BB*CCH*HWV];         // [b][w][c][j]
__device__ __align__(16) float g_att[(size_t)BB*HH*WW*256];
__device__ __align__(16) float g_s1 [(size_t)BB*CCH*HWV];         // out_H [b][c][w][h]
__device__ __align__(16) float g_s2 [(size_t)BB*CCH*HWV];         // out_W [b][c][h][w]
// fp16 split planes of x (transposed to [b][n][c])
__device__ __align__(16) __half g_xqh[(size_t)BB*HWV*CCH];
__device__ __align__(16) __half g_xql[(size_t)BB*HWV*CCH];
__device__ __align__(16) __half g_xeh[(size_t)BB*HWV*CCH];
__device__ __align__(16) __half g_xel[(size_t)BB*HWV*CCH];
// packed weights (fp16 hi/lo): rows 0-63 = Wq, 64-127 = Wk ; and Wv
__device__ __align__(16) __half g_wqkh[128*CCH], g_wqkl[128*CCH];
__device__ __align__(16) __half g_wvh[CCH*CCH],  g_wvl[CCH*CCH];
__device__ float g_bqk[128];
// GEMM outputs: qk1 rows 0-63 = q (from xq); qk2 rows 64-127 = k (from xe)
__device__ __align__(16) float g_qk1[(size_t)BB*128*HWV];
__device__ __align__(16) float g_qk2[(size_t)BB*128*HWV];

// ---------------- PTX helpers (plain sm_80/90 features only) ---------------
__device__ __forceinline__ uint32_t smem_u32(const void* p) {
    uint32_t a;
    asm("{ .reg .u64 t; cvta.to.shared.u64 t, %1; cvt.u32.u64 %0, t; }" : "=r"(a) : "l"(p));
    return a;
}
#define LDMATRIX_X4(r0,r1,r2,r3,addr) \
    asm volatile("ldmatrix.sync.aligned.m8n8.x4.shared.b16 {%0,%1,%2,%3}, [%4];" \
                 : "=r"(r0),"=r"(r1),"=r"(r2),"=r"(r3) : "r"(addr))
#define MMA16816(d,a0,a1,a2,a3,b0,b1) \
    asm volatile("mma.sync.aligned.m16n8k16.row.col.f32.f16.f16.f32 " \
                 "{%0,%1,%2,%3},{%4,%5,%6,%7},{%8,%9},{%0,%1,%2,%3};" \
                 : "+f"((d)[0]),"+f"((d)[1]),"+f"((d)[2]),"+f"((d)[3]) \
                 : "r"(a0),"r"(a1),"r"(a2),"r"(a3),"r"(b0),"r"(b1))
#define CP_ASYNC16(dst,src) \
    asm volatile("cp.async.cg.shared.global [%0], [%1], 16;" :: "r"(dst),"l"(src))
#define CP_COMMIT() asm volatile("cp.async.commit_group;" ::: "memory")
#define CP_WAIT1()  asm volatile("cp.async.wait_group 1;" ::: "memory")
#define CP_WAIT0()  asm volatile("cp.async.wait_group 0;" ::: "memory")

// ---------------- split/transpose: x[b][c][n] fp32 -> [b][n][c] fp16 hi/lo -
__global__ void split_transpose_kernel(__half* __restrict__ oh,
                                       __half* __restrict__ ol,
                                       const float* __restrict__ x) {
    __shared__ float tile[32][33];
    int b = blockIdx.z;
    int n0 = blockIdx.x * 32, c0 = blockIdx.y * 32;
    int tx = threadIdx.x, ty = threadIdx.y;
    const float* xp = x + ((size_t)b * CCH + c0) * HWV + n0;
#pragma unroll
    for (int r = 0; r < 4; r++)
        tile[ty + r * 8][tx] = xp[(size_t)(ty + r * 8) * HWV + tx];  // [c_loc][n_loc]
    __syncthreads();
#pragma unroll
    for (int r = 0; r < 4; r++) {
        int nl = ty + r * 8, cl = tx;
        float v = tile[cl][nl];
        __half hi = __float2half_rn(v);
        __half lo = __float2half_rn(v - __half2float(hi));
        size_t o = ((size_t)b * HWV + n0 + nl) * CCH + c0 + cl;
        oh[o] = hi; ol[o] = lo;
    }
}

// ---------------- plain split (weights) -------------------------------------
__global__ void split_plain_kernel(__half* __restrict__ oh,
                                   __half* __restrict__ ol,
                                   const float* __restrict__ src, int n) {
    int i = blockIdx.x * 256 + threadIdx.x;
    if (i < n) {
        float v = src[i];
        __half hi = __float2half_rn(v);
        oh[i] = hi;
        ol[i] = __float2half_rn(v - __half2float(hi));
    }
}
__global__ void pack_bias_kernel(float* __restrict__ dst,
                                 const float* __restrict__ b0,
                                 const float* __restrict__ b1) {
    int i = threadIdx.x;
    dst[i] = (i < 64) ? b0[i] : b1[i - 64];
}

// ---------------- tensor-core GEMM via mma.sync (fp16 hi/lo split) ----------
// out[b][m][n] = bias[m] + sum_k A[m,k] * B[b][n,k]
// A: [Mtot x 512] fp16 hi/lo (k contiguous). B: [b][16384][512] fp16 hi/lo.
// CTA tile M=128 x N=128, K chunks of 32, double-buffered cp.async.
// 8 warps: warp_m = wid&3 (32 rows), warp_n = wid>>2 (64 cols).
#define LDR   80                      // smem bytes per row (32 fp16 + pad)
#define PLN   (128*LDR)               // 10240 B per plane
#define GBUF  (4*PLN)                 // Ah,Al,Bh,Bl = 40960 B
#define GSM   (2*GBUF)                // 81920 B dynamic smem

__global__ void __launch_bounds__(256, 1) gemm_mma_kernel(
    float* __restrict__ out,
    const __half* __restrict__ Ah, const __half* __restrict__ Al,
    const __half* __restrict__ Bh, const __half* __restrict__ Bl,
    const float* __restrict__ bias, size_t outBatch)
{
    extern __shared__ char smem[];
    uint32_t sbase = smem_u32(smem);
    int tid = threadIdx.x, wid = tid >> 5, lane = tid & 31;
    int n0 = blockIdx.x * 128, m0 = blockIdx.y * 128, b = blockIdx.z;
    int wm = wid & 3, wn = wid >> 2;

    const __half* Ahb = Ah + (size_t)m0 * CCH;
    const __half* Alb = Al + (size_t)m0 * CCH;
    const __half* Bhb = Bh + ((size_t)b * HWV + n0) * CCH;
    const __half* Blb = Bl + ((size_t)b * HWV + n0) * CCH;
    const __half* planes[4] = {Ahb, Alb, Bhb, Blb};

    float acc[2][8][4];
#pragma unroll
    for (int i = 0; i < 2; i++)
#pragma unroll
        for (int j = 0; j < 8; j++)
#pragma unroll
            for (int k = 0; k < 4; k++) acc[i][j][k] = 0.f;

    // ldmatrix lane addressing
    int lg = lane >> 3, lr = lane & 7;

    // ---- issue async load of chunk `c` into buffer `buf`
    auto issue = [&](int c, int buf) {
        int kc0 = c * 32;
#pragma unroll
        for (int i = 0; i < 8; i++) {
            int idx = i * 256 + tid;
            int plane = i >> 1;           // idx>>9, constant per i
            int j = idx & 511;
            int r = j >> 2, seg = j & 3;
            const __half* src = planes[plane] + (size_t)r * CCH + kc0 + seg * 8;
            uint32_t dst = sbase + buf * GBUF + plane * PLN + r * LDR + seg * 16;
            CP_ASYNC16(dst, src);
        }
        CP_COMMIT();
    };

    issue(0, 0);
    for (int c = 0; c < 16; c++) {
        int buf = c & 1;
        if (c < 15) { issue(c + 1, buf ^ 1); CP_WAIT1(); } else { CP_WAIT0(); }
        __syncthreads();
        uint32_t sAh = sbase + buf * GBUF;
        uint32_t sAl = sAh + PLN;
        uint32_t sBh = sAl + PLN;
        uint32_t sBl = sBh + PLN;
#pragma unroll
        for (int ks = 0; ks < 2; ks++) {
            // A fragments: 2 m-frags x (hi,lo)
            uint32_t ah[2][4], al[2][4];
#pragma unroll
            for (int mf = 0; mf < 2; mf++) {
                uint32_t roff = (wm * 32 + mf * 16 + lr + (lg & 1) * 8) * LDR
                              + (ks * 16 + (lg >> 1) * 8) * 2;
                LDMATRIX_X4(ah[mf][0], ah[mf][1], ah[mf][2], ah[mf][3], sAh + roff);
                LDMATRIX_X4(al[mf][0], al[mf][1], al[mf][2], al[mf][3], sAl + roff);
            }
            // B fragments: 8 n-frags x (hi,lo) via 4 x4-loads per plane
            uint32_t bh[8][2], bl[8][2];
#pragma unroll
            for (int np = 0; np < 4; np++) {
                uint32_t roff = (wn * 64 + np * 16 + (lg >> 1) * 8 + lr) * LDR
                              + (ks * 16 + (lg & 1) * 8) * 2;
                uint32_t r0, r1, r2, r3;
                LDMATRIX_X4(r0, r1, r2, r3, sBh + roff);
                bh[np * 2][0] = r0; bh[np * 2][1] = r1;
                bh[np * 2 + 1][0] = r2; bh[np * 2 + 1][1] = r3;
                LDMATRIX_X4(r0, r1, r2, r3, sBl + roff);
                bl[np * 2][0] = r0; bl[np * 2][1] = r1;
                bl[np * 2 + 1][0] = r2; bl[np * 2 + 1][1] = r3;
            }
#pragma unroll
            for (int mf = 0; mf < 2; mf++)
#pragma unroll
                for (int nf = 0; nf < 8; nf++) {
                    MMA16816(acc[mf][nf], ah[mf][0], ah[mf][1], ah[mf][2], ah[mf][3],
                             bh[nf][0], bh[nf][1]);
                    MMA16816(acc[mf][nf], ah[mf][0], ah[mf][1], ah[mf][2], ah[mf][3],
                             bl[nf][0], bl[nf][1]);
                    MMA16816(acc[mf][nf], al[mf][0], al[mf][1], al[mf][2], al[mf][3],
                             bh[nf][0], bh[nf][1]);
                }
        }
        __syncthreads();
    }

    // ---- epilogue: add bias, store
#pragma unroll
    for (int mf = 0; mf < 2; mf++) {
        int row = m0 + wm * 32 + mf * 16 + (lane >> 2);
        float bv0 = bias[row], bv1 = bias[row + 8];
        float* op0 = out + (size_t)b * outBatch + (size_t)row * HWV
                   + n0 + wn * 64 + (lane & 3) * 2;
        float* op1 = op0 + (size_t)8 * HWV;
#pragma unroll
        for (int nf = 0; nf < 8; nf++) {
            float2 r0 = make_float2(acc[mf][nf][0] + bv0, acc[mf][nf][1] + bv0);
            float2 r1 = make_float2(acc[mf][nf][2] + bv1, acc[mf][nf][3] + bv1);
            *(float2*)(op0 + nf * 8) = r0;
            *(float2*)(op1 + nf * 8) = r1;
        }
    }
}

// ---------------- transpose: src[b][c][h][w] -> dst[b][w][c][h] ------------
__global__ void transpose_hw_kernel(float* __restrict__ dst,
                                    const float* __restrict__ src,
                                    int planes, size_t srcBatchStride) {
    __shared__ float tile[32][33];
    int p = blockIdx.z;
    int b = p / planes, c = p % planes;
    int w0 = blockIdx.x * 32, h0 = blockIdx.y * 32;
    int tx = threadIdx.x, ty = threadIdx.y;
    const float* s = src + (size_t)b * srcBatchStride + (size_t)c * HWV;
#pragma unroll
    for (int r = 0; r < 4; r++) {
        int h = h0 + ty + r * 8;
        tile[ty + r * 8][tx] = s[(size_t)h * WW + w0 + tx];
    }
    __syncthreads();
#pragma unroll
    for (int r = 0; r < 4; r++) {
        int w = w0 + ty + r * 8;
        dst[(((size_t)b * WW + w) * planes + c) * HH + h0 + tx] = tile[tx][ty + r * 8];
    }
}

// ---------------- energy_H: per (b,w), e[h,j] = sum_c qT[c,h]*kT[c,j] ------
__global__ void energy_h_kernel() {
    __shared__ float As[16][128];
    __shared__ float Bs[16][128];
    int w = blockIdx.x, b = blockIdx.y;
    int tid = threadIdx.x;
    int tx = tid & 15, ty = tid >> 4;
    int m0 = ty * 8, n0 = tx * 8;
    const float* qT = g_qT + ((size_t)(b * WW + w)) * C8 * HH;
    const float* kT = g_kT + ((size_t)(b * WW + w)) * C8 * HH;
    float acc[8][8];
#pragma unroll
    for (int i = 0; i < 8; i++)
#pragma unroll
        for (int j = 0; j < 8; j++) acc[i][j] = 0.f;

    for (int k0 = 0; k0 < C8; k0 += 16) {
#pragma unroll
        for (int i = 0; i < 8; i++) {
            int idx = tid + i * 256;
            int cc = idx >> 7, hh = idx & 127;
            As[cc][hh] = qT[(k0 + cc) * HH + hh];
            Bs[cc][hh] = kT[(k0 + cc) * HH + hh];
        }
        __syncthreads();
#pragma unroll
        for (int kk = 0; kk < 16; kk++) {
            float a[8], bb[8];
            *(float4*)&a[0]  = *(const float4*)&As[kk][m0];
            *(float4*)&a[4]  = *(const float4*)&As[kk][m0 + 4];
            *(float4*)&bb[0] = *(const float4*)&Bs[kk][n0];
            *(float4*)&bb[4] = *(const float4*)&Bs[kk][n0 + 4];
#pragma unroll
            for (int i = 0; i < 8; i++)
#pragma unroll
                for (int j = 0; j < 8; j++) acc[i][j] += a[i] * bb[j];
        }
        __syncthreads();
    }
#pragma unroll
    for (int i = 0; i < 8; i++) {
        int h = m0 + i;
        float* row = g_att + (((size_t)b * HH + h) * WW + w) * 256;
#pragma unroll
        for (int j = 0; j < 8; j++) {
            int jj = n0 + j;
            row[jj] = (jj == h) ? -CUDART_INF_F : acc[i][j];
        }
    }
}

// ---------------- energy_W: per (b,h), e[w,j] = sum_c q[c,w]*k[c,j] --------
__global__ void energy_w_kernel(const float* __restrict__ qbase,
                                const float* __restrict__ kbase,
                                size_t bstride) {
    __shared__ float As[16][128];
    __shared__ float Bs[16][128];
    int h = blockIdx.x, b = blockIdx.y;
    int tid = threadIdx.x;
    int tx = tid & 15, ty = tid >> 4;
    int m0 = ty * 8, n0 = tx * 8;
    const float* qp = qbase + (size_t)b * bstride + (size_t)h * WW;
    const float* kp = kbase + (size_t)b * bstride + (size_t)h * WW;
    float acc[8][8];
#pragma unroll
    for (int i = 0; i < 8; i++)
#pragma unroll
        for (int j = 0; j < 8; j++) acc[i][j] = 0.f;

    for (int k0 = 0; k0 < C8; k0 += 16) {
#pragma unroll
        for (int i = 0; i < 8; i++) {
            int idx = tid + i * 256;
            int cc = idx >> 7, nn = idx & 127;
            As[cc][nn] = qp[(size_t)(k0 + cc) * HWV + nn];
            Bs[cc][nn] = kp[(size_t)(k0 + cc) * HWV + nn];
        }
        __syncthreads();
#pragma unroll
        for (int kk = 0; kk < 16; kk++) {
            float a[8], bb[8];
            *(float4*)&a[0]  = *(const float4*)&As[kk][m0];
            *(float4*)&a[4]  = *(const float4*)&As[kk][m0 + 4];
            *(float4*)&bb[0] = *(const float4*)&Bs[kk][n0];
            *(float4*)&bb[4] = *(const float4*)&Bs[kk][n0 + 4];
#pragma unroll
            for (int i = 0; i < 8; i++)
#pragma unroll
                for (int j = 0; j < 8; j++) acc[i][j] += a[i] * bb[j];
        }
        __syncthreads();
    }
#pragma unroll
    for (int i = 0; i < 8; i++) {
        int wv = m0 + i;
        float* row = g_att + (((size_t)b * HH + h) * WW + wv) * 256 + 128;
#pragma unroll
        for (int j = 0; j < 8; j++) row[n0 + j] = acc[i][j];
    }
}

// ---------------- softmax over rows of 256 (one warp per row) --------------
__global__ void softmax_kernel() {
    int row  = blockIdx.x * 8 + (threadIdx.x >> 5);
    int lane = threadIdx.x & 31;
    float* p = g_att + (size_t)row * 256;
    float v[8];
    float m = -CUDART_INF_F;
#pragma unroll
    for (int i = 0; i < 8; i++) { v[i] = p[lane + 32 * i]; m = fmaxf(m, v[i]); }
#pragma unroll
    for (int o = 16; o > 0; o >>= 1) m = fmaxf(m, __shfl_xor_sync(0xffffffffu, m, o));
    float s = 0.f;
#pragma unroll
    for (int i = 0; i < 8; i++) { v[i] = __expf(v[i] - m); s += v[i]; }
#pragma unroll
    for (int o = 16; o > 0; o >>= 1) s += __shfl_xor_sync(0xffffffffu, s, o);
    float inv = 1.0f / s;
#pragma unroll
    for (int i = 0; i < 8; i++) p[lane + 32 * i] = v[i] * inv;
}

// ---------------- out_H: per (b,w,ct): S1[c,h] = sum_j vT[c,j]*attH[h,j] ---
__global__ void out_h_kernel() {
    __shared__ float As[16][132];
    __shared__ float Bs[16][132];
    int ct = blockIdx.x, w = blockIdx.y, b = blockIdx.z;
    int tid = threadIdx.x;
    int tx = tid & 15, ty = tid >> 4;
    int m0 = ty * 8, n0 = tx * 8;
    const float* vt   = g_vT  + (((size_t)b * WW + w) * CCH + ct * 128) * HH;
    const float* attb = g_att + (((size_t)b * HH) * WW + w) * 256;
    float acc[8][8];
#pragma unroll
    for (int i = 0; i < 8; i++)
#pragma unroll
        for (int j = 0; j < 8; j++) acc[i][j] = 0.f;

    for (int k0 = 0; k0 < 128; k0 += 16) {
#pragma unroll
        for (int i = 0; i < 8; i++) {
            int idx = tid + i * 256;
            int m = idx >> 4, kk = idx & 15;
            As[kk][m] = vt[(size_t)m * HH + k0 + kk];
            Bs[kk][m] = attb[(size_t)m * WW * 256 + k0 + kk];
        }
        __syncthreads();
#pragma unroll
        for (int kk = 0; kk < 16; kk++) {
            float a[8], bb[8];
            *(float4*)&a[0]  = *(const float4*)&As[kk][m0];
            *(float4*)&a[4]  = *(const float4*)&As[kk][m0 + 4];
            *(float4*)&bb[0] = *(const float4*)&Bs[kk][n0];
            *(float4*)&bb[4] = *(const float4*)&Bs[kk][n0 + 4];
#pragma unroll
            for (int i = 0; i < 8; i++)
#pragma unroll
                for (int j = 0; j < 8; j++) acc[i][j] += a[i] * bb[j];
        }
        __syncthreads();
    }
#pragma unroll
    for (int i = 0; i < 8; i++) {
        float* op = g_s1 + (((size_t)b * CCH + ct * 128 + m0 + i) * WW + w) * HH + n0;
        float4 r0, r1;
        r0.x = acc[i][0]; r0.y = acc[i][1]; r0.z = acc[i][2]; r0.w = acc[i][3];
        r1.x = acc[i][4]; r1.y = acc[i][5]; r1.z = acc[i][6]; r1.w = acc[i][7];
        *(float4*)op = r0; *(float4*)(op + 4) = r1;
    }
}

// ---------------- out_W: per (b,h,ct): S2[c,w] = sum_j v[c,h,j]*attW[w,j] --
__global__ void out_w_kernel() {
    __shared__ float As[16][132];
    __shared__ float Bs[16][132];
    int ct = blockIdx.x, h = blockIdx.y, b = blockIdx.z;
    int tid = threadIdx.x;
    int tx = tid & 15, ty = tid >> 4;
    int m0 = ty * 8, n0 = tx * 8;
    const float* vp   = g_v   + ((size_t)b * CCH + ct * 128) * HWV + (size_t)h * WW;
    const float* attb = g_att + (((size_t)b * HH + h) * WW) * 256 + 128;
    float acc[8][8];
#pragma unroll
    for (int i = 0; i < 8; i++)
#pragma unroll
        for (int j = 0; j < 8; j++) acc[i][j] = 0.f;

    for (int k0 = 0; k0 < 128; k0 += 16) {
#pragma unroll
        for (int i = 0; i < 8; i++) {
            int idx = tid + i * 256;
            int m = idx >> 4, kk = idx & 15;
            As[kk][m] = vp[(size_t)m * HWV + k0 + kk];
            Bs[kk][m] = attb[(size_t)m * 256 + k0 + kk];
        }
        __syncthreads();
#pragma unroll
        for (int kk = 0; kk < 16; kk++) {
            float a[8], bb[8];
            *(float4*)&a[0]  = *(const float4*)&As[kk][m0];
            *(float4*)&a[4]  = *(const float4*)&As[kk][m0 + 4];
            *(float4*)&bb[0] = *(const float4*)&Bs[kk][n0];
            *(float4*)&bb[4] = *(const float4*)&Bs[kk][n0 + 4];
#pragma unroll
            for (int i = 0; i < 8; i++)
#pragma unroll
                for (int j = 0; j < 8; j++) acc[i][j] += a[i] * bb[j];
        }
        __syncthreads();
    }
#pragma unroll
    for (int i = 0; i < 8; i++) {
        float* op = g_s2 + (((size_t)b * CCH + ct * 128 + m0 + i) * HH + h) * WW + n0;
        float4 r0, r1;
        r0.x = acc[i][0]; r0.y = acc[i][1]; r0.z = acc[i][2]; r0.w = acc[i][3];
        r1.x = acc[i][4]; r1.y = acc[i][5]; r1.z = acc[i][6]; r1.w = acc[i][7];
        *(float4*)op = r0; *(float4*)(op + 4) = r1;
    }
}

// ---------------- combine: out1/out2 = gamma*(S1+S2+2) + residuals ---------
__global__ void combine_kernel(float* __restrict__ out,
                               const float* __restrict__ xe,
                               const float* __restrict__ xq,
                               const float* __restrict__ g1p,
                               const float* __restrict__ g2p) {
    __shared__ float tile[32][33];
    int bc = blockIdx.z;
    int w0 = blockIdx.x * 32, h0 = blockIdx.y * 32;
    int tx = threadIdx.x, ty = threadIdx.y;
    size_t base = (size_t)bc * HWV;
#pragma unroll
    for (int r = 0; r < 4; r++) {
        int wv = w0 + ty + r * 8;
        tile[ty + r * 8][tx] = g_s1[base + (size_t)wv * HH + h0 + tx];
    }
    __syncthreads();
    float gam1 = g1p[0], gam2 = g2p[0];
#pragma unroll
    for (int r = 0; r < 4; r++) {
        int h = h0 + ty + r * 8;
        int wv = w0 + tx;
        size_t idx = base + (size_t)h * WW + wv;
        float t = tile[tx][ty + r * 8] + g_s2[idx] + 2.0f;
        out[idx]        = fmaf(gam1, t, xe[idx]);
        out[NTOT + idx] = fmaf(gam2, t, xq[idx]);
    }
}

// ---------------- launch ----------------------------------------------------
extern "C" void kernel_launch(void* const* d_in, const int* in_sizes, int n_in,
                              void* d_out, int out_size) {
    const float* xe = (const float*)d_in[0];
    const float* xq = (const float*)d_in[1];
    const float* Wq = (const float*)d_in[2];
    const float* bq = (const float*)d_in[3];
    const float* Wk = (const float*)d_in[4];
    const float* bk = (const float*)d_in[5];
    const float* Wv = (const float*)d_in[6];
    const float* bv = (const float*)d_in[7];
    const float* g1 = (const float*)d_in[8];
    const float* g2 = (const float*)d_in[9];
    float* out = (float*)d_out;

    float *pqT, *pkT, *pv, *pvT, *pqk1, *pqk2, *pbqk;
    __half *pxqh, *pxql, *pxeh, *pxel, *pwqkh, *pwqkl, *pwvh, *pwvl;
    cudaGetSymbolAddress((void**)&pqT,  g_qT);
    cudaGetSymbolAddress((void**)&pkT,  g_kT);
    cudaGetSymbolAddress((void**)&pv,   g_v);
    cudaGetSymbolAddress((void**)&pvT,  g_vT);
    cudaGetSymbolAddress((void**)&pqk1, g_qk1);
    cudaGetSymbolAddress((void**)&pqk2, g_qk2);
    cudaGetSymbolAddress((void**)&pbqk, g_bqk);
    cudaGetSymbolAddress((void**)&pxqh, g_xqh);
    cudaGetSymbolAddress((void**)&pxql, g_xql);
    cudaGetSymbolAddress((void**)&pxeh, g_xeh);
    cudaGetSymbolAddress((void**)&pxel, g_xel);
    cudaGetSymbolAddress((void**)&pwqkh, g_wqkh);
    cudaGetSymbolAddress((void**)&pwqkl, g_wqkl);
    cudaGetSymbolAddress((void**)&pwvh, g_wvh);
    cudaGetSymbolAddress((void**)&pwvl, g_wvl);

    cudaFuncSetAttribute(gemm_mma_kernel,
                         cudaFuncAttributeMaxDynamicSharedMemorySize, GSM);

    // split inputs & weights to fp16 hi/lo
    split_transpose_kernel<<<dim3(HWV / 32, CCH / 32, BB), dim3(32, 8)>>>(pxqh, pxql, xq);
    split_transpose_kernel<<<dim3(HWV / 32, CCH / 32, BB), dim3(32, 8)>>>(pxeh, pxel, xe);
    split_plain_kernel<<<(64 * CCH + 255) / 256, 256>>>(pwqkh, pwqkl, Wq, 64 * CCH);
    split_plain_kernel<<<(64 * CCH + 255) / 256, 256>>>(pwqkh + 64 * CCH, pwqkl + 64 * CCH, Wk, 64 * CCH);
    split_plain_kernel<<<(CCH * CCH + 255) / 256, 256>>>(pwvh, pwvl, Wv, CCH * CCH);
    pack_bias_kernel<<<1, 128>>>(pbqk, bq, bk);

    // tensor-core projections
    gemm_mma_kernel<<<dim3(HWV / 128, 1, BB), 256, GSM>>>(
        pqk1, pwqkh, pwqkl, pxqh, pxql, pbqk, (size_t)128 * HWV);
    gemm_mma_kernel<<<dim3(HWV / 128, 1, BB), 256, GSM>>>(
        pqk2, pwqkh, pwqkl, pxeh, pxel, pbqk, (size_t)128 * HWV);
    gemm_mma_kernel<<<dim3(HWV / 128, CCH / 128, BB), 256, GSM>>>(
        pv, pwvh, pwvl, pxeh, pxel, bv, (size_t)CCH * HWV);

    // transposes for column-attention access
    transpose_hw_kernel<<<dim3(4, 4, BB * C8),  dim3(32, 8)>>>(pqT, pqk1, C8, (size_t)128 * HWV);
    transpose_hw_kernel<<<dim3(4, 4, BB * C8),  dim3(32, 8)>>>(pkT, pqk2 + (size_t)64 * HWV, C8, (size_t)128 * HWV);
    transpose_hw_kernel<<<dim3(4, 4, BB * CCH), dim3(32, 8)>>>(pvT, pv, CCH, (size_t)CCH * HWV);

    // energies + fused softmax over concat(256)
    energy_h_kernel<<<dim3(WW, BB), 256>>>();
    energy_w_kernel<<<dim3(HH, BB), 256>>>(pqk1, pqk2 + (size_t)64 * HWV, (size_t)128 * HWV);
    softmax_kernel<<<(BB * HH * WW) / 8, 256>>>();

    // attention outputs
    out_h_kernel<<<dim3(CCH / 128, WW, BB), 256>>>();
    out_w_kernel<<<dim3(CCH / 128, HH, BB), 256>>>();

    // combine: gamma*(out_H + out_W + 2) + residuals  (diagonal branch == +2)
    combine_kernel<<<dim3(4, 4, BB * CCH), dim3(32, 8)>>>(out, xe, xq, g1, g2);
}

// round 5
// speedup vs baseline: 2.3990x; 1.4947x over previous
#include <cuda_runtime.h>
#include <cuda_fp16.h>
#include <math_constants.h>
#include <cstdint>
#include <cstddef>

#define BB 4
#define CCH 512
#define C8 64
#define HH 128
#define WW 128
#define HWV (HH*WW)

static const size_t NTOT = (size_t)BB * CCH * HWV;   // 33,554,432

// ---------------- scratch (device globals; no runtime allocation) ----------
__device__ __align__(16) float g_qT [BB*C8 *HWV];                 // [b][w][c][h]
__device__ __align__(16) float g_kT [BB*C8 *HWV];                 // [b][w][c][h]
__device__ __align__(16) float g_att[(size_t)BB*HH*WW*256];       // energies fp32
__device__ __align__(16) float g_s1 [(size_t)BB*CCH*HWV];         // out_H [b][c][w][h]
__device__ __align__(16) float g_s2 [(size_t)BB*CCH*HWV];         // out_W [b][c][h][w]
// fp16 v (written by gemm) and its transpose
__device__ __align__(16) __half g_vh [(size_t)BB*CCH*HWV];        // [b][c][h][w]
__device__ __align__(16) __half g_vTh[(size_t)BB*CCH*HWV];        // [b][w][c][h(=j)]
// fp16 attention maps in GEMM-friendly layouts
__device__ __align__(16) __half g_attH[(size_t)BB*HWV*HH];        // [b][w][h][j]
__device__ __align__(16) __half g_attW[(size_t)BB*HWV*WW];        // [b][h][w][j]
// fp16 split planes of x (transposed to [b][n][c])
__device__ __align__(16) __half g_xqh[(size_t)BB*HWV*CCH];
__device__ __align__(16) __half g_xql[(size_t)BB*HWV*CCH];
__device__ __align__(16) __half g_xeh[(size_t)BB*HWV*CCH];
__device__ __align__(16) __half g_xel[(size_t)BB*HWV*CCH];
// packed weights (fp16 hi/lo)
__device__ __align__(16) __half g_wqkh[128*CCH], g_wqkl[128*CCH];
__device__ __align__(16) __half g_wvh[CCH*CCH],  g_wvl[CCH*CCH];
__device__ float g_bqk[128];
// q/k GEMM outputs (fp32): qk1 rows 0-63 = q; qk2 rows 64-127 = k
__device__ __align__(16) float g_qk1[(size_t)BB*128*HWV];
__device__ __align__(16) float g_qk2[(size_t)BB*128*HWV];

// ---------------- PTX helpers (plain sm_80/90 features only) ---------------
__device__ __forceinline__ uint32_t smem_u32(const void* p) {
    uint32_t a;
    asm("{ .reg .u64 t; cvta.to.shared.u64 t, %1; cvt.u32.u64 %0, t; }" : "=r"(a) : "l"(p));
    return a;
}
#define LDMATRIX_X4(r0,r1,r2,r3,addr) \
    asm volatile("ldmatrix.sync.aligned.m8n8.x4.shared.b16 {%0,%1,%2,%3}, [%4];" \
                 : "=r"(r0),"=r"(r1),"=r"(r2),"=r"(r3) : "r"(addr))
#define MMA16816(d,a0,a1,a2,a3,b0,b1) \
    asm volatile("mma.sync.aligned.m16n8k16.row.col.f32.f16.f16.f32 " \
                 "{%0,%1,%2,%3},{%4,%5,%6,%7},{%8,%9},{%0,%1,%2,%3};" \
                 : "+f"((d)[0]),"+f"((d)[1]),"+f"((d)[2]),"+f"((d)[3]) \
                 : "r"(a0),"r"(a1),"r"(a2),"r"(a3),"r"(b0),"r"(b1))
#define CP_ASYNC16(dst,src) \
    asm volatile("cp.async.cg.shared.global [%0], [%1], 16;" :: "r"(dst),"l"(src))
#define CP_COMMIT() asm volatile("cp.async.commit_group;" ::: "memory")
#define CP_WAIT1()  asm volatile("cp.async.wait_group 1;" ::: "memory")
#define CP_WAIT0()  asm volatile("cp.async.wait_group 0;" ::: "memory")

// ---------------- split/transpose: x[b][c][n] fp32 -> [b][n][c] fp16 hi/lo -
__global__ void split_transpose_kernel(__half* __restrict__ oh,
                                       __half* __restrict__ ol,
                                       const float* __restrict__ x) {
    __shared__ float tile[32][33];
    int b = blockIdx.z;
    int n0 = blockIdx.x * 32, c0 = blockIdx.y * 32;
    int tx = threadIdx.x, ty = threadIdx.y;
    const float* xp = x + ((size_t)b * CCH + c0) * HWV + n0;
#pragma unroll
    for (int r = 0; r < 4; r++)
        tile[ty + r * 8][tx] = xp[(size_t)(ty + r * 8) * HWV + tx];
    __syncthreads();
#pragma unroll
    for (int r = 0; r < 4; r++) {
        int nl = ty + r * 8, cl = tx;
        float v = tile[cl][nl];
        __half hi = __float2half_rn(v);
        __half lo = __float2half_rn(v - __half2float(hi));
        size_t o = ((size_t)b * HWV + n0 + nl) * CCH + c0 + cl;
        oh[o] = hi; ol[o] = lo;
    }
}

// ---------------- plain split (weights) -------------------------------------
__global__ void split_plain_kernel(__half* __restrict__ oh,
                                   __half* __restrict__ ol,
                                   const float* __restrict__ src, int n) {
    int i = blockIdx.x * 256 + threadIdx.x;
    if (i < n) {
        float v = src[i];
        __half hi = __float2half_rn(v);
        oh[i] = hi;
        ol[i] = __float2half_rn(v - __half2float(hi));
    }
}
__global__ void pack_bias_kernel(float* __restrict__ dst,
                                 const float* __restrict__ b0,
                                 const float* __restrict__ b1) {
    int i = threadIdx.x;
    dst[i] = (i < 64) ? b0[i] : b1[i - 64];
}

// ---------------- tensor-core GEMM via mma.sync (fp16 hi/lo split) ----------
// out[b][m][n] = bias[m] + sum_k A[m,k] * B[b][n,k]
#define LDR   80
#define PLN   (128*LDR)
#define GBUF  (4*PLN)
#define GSM   (2*GBUF)

__global__ void __launch_bounds__(256, 1) gemm_mma_kernel(
    float* __restrict__ outF, __half* __restrict__ outH16,
    const __half* __restrict__ Ah, const __half* __restrict__ Al,
    const __half* __restrict__ Bh, const __half* __restrict__ Bl,
    const float* __restrict__ bias, size_t outBatch)
{
    extern __shared__ char smem[];
    uint32_t sbase = smem_u32(smem);
    int tid = threadIdx.x, wid = tid >> 5, lane = tid & 31;
    int n0 = blockIdx.x * 128, m0 = blockIdx.y * 128, b = blockIdx.z;
    int wm = wid & 3, wn = wid >> 2;

    const __half* Ahb = Ah + (size_t)m0 * CCH;
    const __half* Alb = Al + (size_t)m0 * CCH;
    const __half* Bhb = Bh + ((size_t)b * HWV + n0) * CCH;
    const __half* Blb = Bl + ((size_t)b * HWV + n0) * CCH;
    const __half* planes[4] = {Ahb, Alb, Bhb, Blb};

    float acc[2][8][4];
#pragma unroll
    for (int i = 0; i < 2; i++)
#pragma unroll
        for (int j = 0; j < 8; j++)
#pragma unroll
            for (int k = 0; k < 4; k++) acc[i][j][k] = 0.f;

    int lg = lane >> 3, lr = lane & 7;

    auto issue = [&](int c, int buf) {
        int kc0 = c * 32;
#pragma unroll
        for (int i = 0; i < 8; i++) {
            int idx = i * 256 + tid;
            int plane = i >> 1;
            int j = idx & 511;
            int r = j >> 2, seg = j & 3;
            const __half* src = planes[plane] + (size_t)r * CCH + kc0 + seg * 8;
            uint32_t dst = sbase + buf * GBUF + plane * PLN + r * LDR + seg * 16;
            CP_ASYNC16(dst, src);
        }
        CP_COMMIT();
    };

    issue(0, 0);
    for (int c = 0; c < 16; c++) {
        int buf = c & 1;
        if (c < 15) { issue(c + 1, buf ^ 1); CP_WAIT1(); } else { CP_WAIT0(); }
        __syncthreads();
        uint32_t sAh = sbase + buf * GBUF;
        uint32_t sAl = sAh + PLN;
        uint32_t sBh = sAl + PLN;
        uint32_t sBl = sBh + PLN;
#pragma unroll
        for (int ks = 0; ks < 2; ks++) {
            uint32_t ah[2][4], al[2][4];
#pragma unroll
            for (int mf = 0; mf < 2; mf++) {
                uint32_t roff = (wm * 32 + mf * 16 + lr + (lg & 1) * 8) * LDR
                              + (ks * 16 + (lg >> 1) * 8) * 2;
                LDMATRIX_X4(ah[mf][0], ah[mf][1], ah[mf][2], ah[mf][3], sAh + roff);
                LDMATRIX_X4(al[mf][0], al[mf][1], al[mf][2], al[mf][3], sAl + roff);
            }
            uint32_t bh[8][2], bl[8][2];
#pragma unroll
            for (int np = 0; np < 4; np++) {
                uint32_t roff = (wn * 64 + np * 16 + (lg >> 1) * 8 + lr) * LDR
                              + (ks * 16 + (lg & 1) * 8) * 2;
                uint32_t r0, r1, r2, r3;
                LDMATRIX_X4(r0, r1, r2, r3, sBh + roff);
                bh[np * 2][0] = r0; bh[np * 2][1] = r1;
                bh[np * 2 + 1][0] = r2; bh[np * 2 + 1][1] = r3;
                LDMATRIX_X4(r0, r1, r2, r3, sBl + roff);
                bl[np * 2][0] = r0; bl[np * 2][1] = r1;
                bl[np * 2 + 1][0] = r2; bl[np * 2 + 1][1] = r3;
            }
#pragma unroll
            for (int mf = 0; mf < 2; mf++)
#pragma unroll
                for (int nf = 0; nf < 8; nf++) {
                    MMA16816(acc[mf][nf], ah[mf][0], ah[mf][1], ah[mf][2], ah[mf][3],
                             bh[nf][0], bh[nf][1]);
                    MMA16816(acc[mf][nf], ah[mf][0], ah[mf][1], ah[mf][2], ah[mf][3],
                             bl[nf][0], bl[nf][1]);
                    MMA16816(acc[mf][nf], al[mf][0], al[mf][1], al[mf][2], al[mf][3],
                             bh[nf][0], bh[nf][1]);
                }
        }
        __syncthreads();
    }

#pragma unroll
    for (int mf = 0; mf < 2; mf++) {
        int row = m0 + wm * 32 + mf * 16 + (lane >> 2);
        float bv0 = bias[row], bv1 = bias[row + 8];
        size_t off0 = (size_t)b * outBatch + (size_t)row * HWV
                    + n0 + wn * 64 + (lane & 3) * 2;
        size_t off1 = off0 + (size_t)8 * HWV;
        if (outH16) {
#pragma unroll
            for (int nf = 0; nf < 8; nf++) {
                __half2 r0 = __floats2half2_rn(acc[mf][nf][0] + bv0, acc[mf][nf][1] + bv0);
                __half2 r1 = __floats2half2_rn(acc[mf][nf][2] + bv1, acc[mf][nf][3] + bv1);
                *(__half2*)(outH16 + off0 + nf * 8) = r0;
                *(__half2*)(outH16 + off1 + nf * 8) = r1;
            }
        } else {
#pragma unroll
            for (int nf = 0; nf < 8; nf++) {
                float2 r0 = make_float2(acc[mf][nf][0] + bv0, acc[mf][nf][1] + bv0);
                float2 r1 = make_float2(acc[mf][nf][2] + bv1, acc[mf][nf][3] + bv1);
                *(float2*)(outF + off0 + nf * 8) = r0;
                *(float2*)(outF + off1 + nf * 8) = r1;
            }
        }
    }
}

// ---------------- attention output GEMM (fp16 mma) --------------------------
// S[c, n] = sum_j A[c, j] * B[n, j], M=128, N=128, K=128 single pass.
#define LDT 272    // 256B row + 16B pad

__global__ void __launch_bounds__(256) attn_out_kernel(
    float* __restrict__ out,
    const __half* __restrict__ A, size_t aRow, size_t ASf, size_t ASb,
    const __half* __restrict__ Bm)
{
    extern __shared__ char smem[];
    uint32_t sA = smem_u32(smem);
    uint32_t sB = sA + 128 * LDT;
    int tid = threadIdx.x, wid = tid >> 5, lane = tid & 31;
    int ct = blockIdx.x, f = blockIdx.y, b = blockIdx.z;
    int wm = wid & 3, wn = wid >> 2;

    const __half* Ac = A + (size_t)b * ASb + (size_t)f * ASf + (size_t)ct * 128 * aRow;
    const __half* Bc = Bm + ((size_t)b * 128 + f) * 16384;

    // 128 rows x 256B = 16 segments of 16B per row
#pragma unroll
    for (int i = 0; i < 8; i++) {
        int idx = i * 256 + tid;
        int r = idx >> 4, seg = idx & 15;
        CP_ASYNC16(sA + r * LDT + seg * 16, Ac + (size_t)r * aRow + seg * 8);
    }
#pragma unroll
    for (int i = 0; i < 8; i++) {
        int idx = i * 256 + tid;
        int r = idx >> 4, seg = idx & 15;
        CP_ASYNC16(sB + r * LDT + seg * 16, Bc + (size_t)r * 128 + seg * 8);
    }
    CP_COMMIT(); CP_WAIT0();
    __syncthreads();

    float acc[2][8][4];
#pragma unroll
    for (int i = 0; i < 2; i++)
#pragma unroll
        for (int j = 0; j < 8; j++)
#pragma unroll
            for (int k = 0; k < 4; k++) acc[i][j][k] = 0.f;

    int lg = lane >> 3, lr = lane & 7;
#pragma unroll
    for (int kk = 0; kk < 8; kk++) {
        uint32_t a[2][4];
#pragma unroll
        for (int mf = 0; mf < 2; mf++) {
            uint32_t roff = (wm * 32 + mf * 16 + lr + (lg & 1) * 8) * LDT
                          + (kk * 16 + (lg >> 1) * 8) * 2;
            LDMATRIX_X4(a[mf][0], a[mf][1], a[mf][2], a[mf][3], sA + roff);
        }
        uint32_t bf[8][2];
#pragma unroll
        for (int np = 0; np < 4; np++) {
            uint32_t roff = (wn * 64 + np * 16 + (lg >> 1) * 8 + lr) * LDT
                          + (kk * 16 + (lg & 1) * 8) * 2;
            uint32_t r0, r1, r2, r3;
            LDMATRIX_X4(r0, r1, r2, r3, sB + roff);
            bf[np * 2][0] = r0; bf[np * 2][1] = r1;
            bf[np * 2 + 1][0] = r2; bf[np * 2 + 1][1] = r3;
        }
#pragma unroll
        for (int mf = 0; mf < 2; mf++)
#pragma unroll
            for (int nf = 0; nf < 8; nf++)
                MMA16816(acc[mf][nf], a[mf][0], a[mf][1], a[mf][2], a[mf][3],
                         bf[nf][0], bf[nf][1]);
    }

    float* oc = out + (size_t)b * ((size_t)CCH * HWV) + (size_t)f * 128
              + (size_t)ct * 128 * HWV;
#pragma unroll
    for (int mf = 0; mf < 2; mf++) {
        int row = wm * 32 + mf * 16 + (lane >> 2);
        float* op0 = oc + (size_t)row * HWV + wn * 64 + (lane & 3) * 2;
        float* op1 = op0 + (size_t)8 * HWV;
#pragma unroll
        for (int nf = 0; nf < 8; nf++) {
            *(float2*)(op0 + nf * 8) = make_float2(acc[mf][nf][0], acc[mf][nf][1]);
            *(float2*)(op1 + nf * 8) = make_float2(acc[mf][nf][2], acc[mf][nf][3]);
        }
    }
}

// ---------------- transpose fp32: src[b][c][h][w] -> dst[b][w][c][h] -------
__global__ void transpose_hw_kernel(float* __restrict__ dst,
                                    const float* __restrict__ src,
                                    int planes, size_t srcBatchStride) {
    __shared__ float tile[32][33];
    int p = blockIdx.z;
    int b = p / planes, c = p % planes;
    int w0 = blockIdx.x * 32, h0 = blockIdx.y * 32;
    int tx = threadIdx.x, ty = threadIdx.y;
    const float* s = src + (size_t)b * srcBatchStride + (size_t)c * HWV;
#pragma unroll
    for (int r = 0; r < 4; r++) {
        int h = h0 + ty + r * 8;
        tile[ty + r * 8][tx] = s[(size_t)h * WW + w0 + tx];
    }
    __syncthreads();
#pragma unroll
    for (int r = 0; r < 4; r++) {
        int w = w0 + ty + r * 8;
        dst[(((size_t)b * WW + w) * planes + c) * HH + h0 + tx] = tile[tx][ty + r * 8];
    }
}

// ---------------- transpose fp16: g_vh[b][c][h][w] -> g_vTh[b][w][c][h] ----
__global__ void transpose_hw_half_kernel() {
    __shared__ __half tile[32][36];
    int p = blockIdx.z;
    int b = p >> 9, c = p & 511;
    int w0 = blockIdx.x * 32, h0 = blockIdx.y * 32;
    int tx = threadIdx.x, ty = threadIdx.y;
    const __half* s = g_vh + ((size_t)b * CCH + c) * HWV;
#pragma unroll
    for (int r = 0; r < 4; r++) {
        int h = h0 + ty + r * 8;
        tile[ty + r * 8][tx] = s[(size_t)h * WW + w0 + tx];
    }
    __syncthreads();
#pragma unroll
    for (int r = 0; r < 4; r++) {
        int w = w0 + ty + r * 8;
        g_vTh[(((size_t)b * WW + w) * CCH + c) * HH + h0 + tx] = tile[tx][ty + r * 8];
    }
}

// ---------------- energy_H: per (b,w), e[h,j] = sum_c qT[c,h]*kT[c,j] ------
__global__ void energy_h_kernel() {
    __shared__ float As[16][128];
    __shared__ float Bs[16][128];
    int w = blockIdx.x, b = blockIdx.y;
    int tid = threadIdx.x;
    int tx = tid & 15, ty = tid >> 4;
    int m0 = ty * 8, n0 = tx * 8;
    const float* qT = g_qT + ((size_t)(b * WW + w)) * C8 * HH;
    const float* kT = g_kT + ((size_t)(b * WW + w)) * C8 * HH;
    float acc[8][8];
#pragma unroll
    for (int i = 0; i < 8; i++)
#pragma unroll
        for (int j = 0; j < 8; j++) acc[i][j] = 0.f;

    for (int k0 = 0; k0 < C8; k0 += 16) {
#pragma unroll
        for (int i = 0; i < 8; i++) {
            int idx = tid + i * 256;
            int cc = idx >> 7, hh = idx & 127;
            As[cc][hh] = qT[(k0 + cc) * HH + hh];
            Bs[cc][hh] = kT[(k0 + cc) * HH + hh];
        }
        __syncthreads();
#pragma unroll
        for (int kk = 0; kk < 16; kk++) {
            float a[8], bb[8];
            *(float4*)&a[0]  = *(const float4*)&As[kk][m0];
            *(float4*)&a[4]  = *(const float4*)&As[kk][m0 + 4];
            *(float4*)&bb[0] = *(const float4*)&Bs[kk][n0];
            *(float4*)&bb[4] = *(const float4*)&Bs[kk][n0 + 4];
#pragma unroll
            for (int i = 0; i < 8; i++)
#pragma unroll
                for (int j = 0; j < 8; j++) acc[i][j] += a[i] * bb[j];
        }
        __syncthreads();
    }
#pragma unroll
    for (int i = 0; i < 8; i++) {
        int h = m0 + i;
        float* row = g_att + (((size_t)b * HH + h) * WW + w) * 256;
#pragma unroll
        for (int j = 0; j < 8; j++) {
            int jj = n0 + j;
            row[jj] = (jj == h) ? -CUDART_INF_F : acc[i][j];
        }
    }
}

// ---------------- energy_W: per (b,h), e[w,j] = sum_c q[c,w]*k[c,j] --------
__global__ void energy_w_kernel(const float* __restrict__ qbase,
                                const float* __restrict__ kbase,
                                size_t bstride) {
    __shared__ float As[16][128];
    __shared__ float Bs[16][128];
    int h = blockIdx.x, b = blockIdx.y;
    int tid = threadIdx.x;
    int tx = tid & 15, ty = tid >> 4;
    int m0 = ty * 8, n0 = tx * 8;
    const float* qp = qbase + (size_t)b * bstride + (size_t)h * WW;
    const float* kp = kbase + (size_t)b * bstride + (size_t)h * WW;
    float acc[8][8];
#pragma unroll
    for (int i = 0; i < 8; i++)
#pragma unroll
        for (int j = 0; j < 8; j++) acc[i][j] = 0.f;

    for (int k0 = 0; k0 < C8; k0 += 16) {
#pragma unroll
        for (int i = 0; i < 8; i++) {
            int idx = tid + i * 256;
            int cc = idx >> 7, nn = idx & 127;
            As[cc][nn] = qp[(size_t)(k0 + cc) * HWV + nn];
            Bs[cc][nn] = kp[(size_t)(k0 + cc) * HWV + nn];
        }
        __syncthreads();
#pragma unroll
        for (int kk = 0; kk < 16; kk++) {
            float a[8], bb[8];
            *(float4*)&a[0]  = *(const float4*)&As[kk][m0];
            *(float4*)&a[4]  = *(const float4*)&As[kk][m0 + 4];
            *(float4*)&bb[0] = *(const float4*)&Bs[kk][n0];
            *(float4*)&bb[4] = *(const float4*)&Bs[kk][n0 + 4];
#pragma unroll
            for (int i = 0; i < 8; i++)
#pragma unroll
                for (int j = 0; j < 8; j++) acc[i][j] += a[i] * bb[j];
        }
        __syncthreads();
    }
#pragma unroll
    for (int i = 0; i < 8; i++) {
        int wv = m0 + i;
        float* row = g_att + (((size_t)b * HH + h) * WW + wv) * 256 + 128;
#pragma unroll
        for (int j = 0; j < 8; j++) row[n0 + j] = acc[i][j];
    }
}

// ---------------- softmax: 256-row softmax -> fp16 att in two layouts ------
__global__ void softmax_kernel() {
    int row  = blockIdx.x * 8 + (threadIdx.x >> 5);
    int lane = threadIdx.x & 31;
    const float* p = g_att + (size_t)row * 256;
    int b = row >> 14, h = (row >> 7) & 127, w = row & 127;
    float v[8];
    float m = -CUDART_INF_F;
#pragma unroll
    for (int i = 0; i < 8; i++) { v[i] = p[lane + 32 * i]; m = fmaxf(m, v[i]); }
#pragma unroll
    for (int o = 16; o > 0; o >>= 1) m = fmaxf(m, __shfl_xor_sync(0xffffffffu, m, o));
    float s = 0.f;
#pragma unroll
    for (int i = 0; i < 8; i++) { v[i] = __expf(v[i] - m); s += v[i]; }
#pragma unroll
    for (int o = 16; o > 0; o >>= 1) s += __shfl_xor_sync(0xffffffffu, s, o);
    float inv = 1.0f / s;
    __half* pH = g_attH + (((size_t)b * WW + w) * HH + h) * 128;
    __half* pW = g_attW + (size_t)row * 128;
#pragma unroll
    for (int i = 0; i < 4; i++) pH[lane + 32 * i] = __float2half(v[i] * inv);
#pragma unroll
    for (int i = 4; i < 8; i++) pW[lane + 32 * (i - 4)] = __float2half(v[i] * inv);
}

// ---------------- combine: out1/out2 = gamma*(S1+S2+2) + residuals ---------
__global__ void combine_kernel(float* __restrict__ out,
                               const float* __restrict__ xe,
                               const float* __restrict__ xq,
                               const float* __restrict__ g1p,
                               const float* __restrict__ g2p) {
    __shared__ float tile[32][33];
    int bc = blockIdx.z;
    int w0 = blockIdx.x * 32, h0 = blockIdx.y * 32;
    int tx = threadIdx.x, ty = threadIdx.y;
    size_t base = (size_t)bc * HWV;
#pragma unroll
    for (int r = 0; r < 4; r++) {
        int wv = w0 + ty + r * 8;
        tile[ty + r * 8][tx] = g_s1[base + (size_t)wv * HH + h0 + tx];
    }
    __syncthreads();
    float gam1 = g1p[0], gam2 = g2p[0];
#pragma unroll
    for (int r = 0; r < 4; r++) {
        int h = h0 + ty + r * 8;
        int wv = w0 + tx;
        size_t idx = base + (size_t)h * WW + wv;
        float t = tile[tx][ty + r * 8] + g_s2[idx] + 2.0f;
        out[idx]        = fmaf(gam1, t, xe[idx]);
        out[NTOT + idx] = fmaf(gam2, t, xq[idx]);
    }
}

// ---------------- launch ----------------------------------------------------
extern "C" void kernel_launch(void* const* d_in, const int* in_sizes, int n_in,
                              void* d_out, int out_size) {
    const float* xe = (const float*)d_in[0];
    const float* xq = (const float*)d_in[1];
    const float* Wq = (const float*)d_in[2];
    const float* bq = (const float*)d_in[3];
    const float* Wk = (const float*)d_in[4];
    const float* bk = (const float*)d_in[5];
    const float* Wv = (const float*)d_in[6];
    const float* bv = (const float*)d_in[7];
    const float* g1 = (const float*)d_in[8];
    const float* g2 = (const float*)d_in[9];
    float* out = (float*)d_out;

    float *pqT, *pkT, *pqk1, *pqk2, *pbqk, *ps1, *ps2;
    __half *pxqh, *pxql, *pxeh, *pxel, *pwqkh, *pwqkl, *pwvh, *pwvl;
    __half *pvh, *pvTh, *pattH, *pattW;
    cudaGetSymbolAddress((void**)&pqT,  g_qT);
    cudaGetSymbolAddress((void**)&pkT,  g_kT);
    cudaGetSymbolAddress((void**)&pqk1, g_qk1);
    cudaGetSymbolAddress((void**)&pqk2, g_qk2);
    cudaGetSymbolAddress((void**)&pbqk, g_bqk);
    cudaGetSymbolAddress((void**)&ps1,  g_s1);
    cudaGetSymbolAddress((void**)&ps2,  g_s2);
    cudaGetSymbolAddress((void**)&pxqh, g_xqh);
    cudaGetSymbolAddress((void**)&pxql, g_xql);
    cudaGetSymbolAddress((void**)&pxeh, g_xeh);
    cudaGetSymbolAddress((void**)&pxel, g_xel);
    cudaGetSymbolAddress((void**)&pwqkh, g_wqkh);
    cudaGetSymbolAddress((void**)&pwqkl, g_wqkl);
    cudaGetSymbolAddress((void**)&pwvh, g_wvh);
    cudaGetSymbolAddress((void**)&pwvl, g_wvl);
    cudaGetSymbolAddress((void**)&pvh,  g_vh);
    cudaGetSymbolAddress((void**)&pvTh, g_vTh);
    cudaGetSymbolAddress((void**)&pattH, g_attH);
    cudaGetSymbolAddress((void**)&pattW, g_attW);

    cudaFuncSetAttribute(gemm_mma_kernel,
                         cudaFuncAttributeMaxDynamicSharedMemorySize, GSM);
    cudaFuncSetAttribute(attn_out_kernel,
                         cudaFuncAttributeMaxDynamicSharedMemorySize, 2 * 128 * LDT);

    // split inputs & weights to fp16 hi/lo
    split_transpose_kernel<<<dim3(HWV / 32, CCH / 32, BB), dim3(32, 8)>>>(pxqh, pxql, xq);
    split_transpose_kernel<<<dim3(HWV / 32, CCH / 32, BB), dim3(32, 8)>>>(pxeh, pxel, xe);
    split_plain_kernel<<<(64 * CCH + 255) / 256, 256>>>(pwqkh, pwqkl, Wq, 64 * CCH);
    split_plain_kernel<<<(64 * CCH + 255) / 256, 256>>>(pwqkh + 64 * CCH, pwqkl + 64 * CCH, Wk, 64 * CCH);
    split_plain_kernel<<<(CCH * CCH + 255) / 256, 256>>>(pwvh, pwvl, Wv, CCH * CCH);
    pack_bias_kernel<<<1, 128>>>(pbqk, bq, bk);

    // tensor-core projections: q, k fp32; v directly fp16
    gemm_mma_kernel<<<dim3(HWV / 128, 1, BB), 256, GSM>>>(
        pqk1, nullptr, pwqkh, pwqkl, pxqh, pxql, pbqk, (size_t)128 * HWV);
    gemm_mma_kernel<<<dim3(HWV / 128, 1, BB), 256, GSM>>>(
        pqk2, nullptr, pwqkh, pwqkl, pxeh, pxel, pbqk, (size_t)128 * HWV);
    gemm_mma_kernel<<<dim3(HWV / 128, CCH / 128, BB), 256, GSM>>>(
        nullptr, pvh, pwvh, pwvl, pxeh, pxel, bv, (size_t)CCH * HWV);

    // transposes
    transpose_hw_kernel<<<dim3(4, 4, BB * C8), dim3(32, 8)>>>(pqT, pqk1, C8, (size_t)128 * HWV);
    transpose_hw_kernel<<<dim3(4, 4, BB * C8), dim3(32, 8)>>>(pkT, pqk2 + (size_t)64 * HWV, C8, (size_t)128 * HWV);
    transpose_hw_half_kernel<<<dim3(4, 4, BB * CCH), dim3(32, 8)>>>();

    // energies + softmax (fp16 att outputs in GEMM layouts)
    energy_h_kernel<<<dim3(WW, BB), 256>>>();
    energy_w_kernel<<<dim3(HH, BB), 256>>>(pqk1, pqk2 + (size_t)64 * HWV, (size_t)128 * HWV);
    softmax_kernel<<<(BB * HH * WW) / 8, 256>>>();

    // attention outputs on tensor cores
    attn_out_kernel<<<dim3(CCH / 128, WW, BB), 256, 2 * 128 * LDT>>>(
        ps1, pvTh, 128, (size_t)CCH * 128, (size_t)WW * CCH * 128, pattH);
    attn_out_kernel<<<dim3(CCH / 128, HH, BB), 256, 2 * 128 * LDT>>>(
        ps2, pvh, HWV, 128, (size_t)CCH * HWV, pattW);

    // combine
    combine_kernel<<<dim3(4, 4, BB * CCH), dim3(32, 8)>>>(out, xe, xq, g1, g2);
}

// round 6
// speedup vs baseline: 3.3411x; 1.3927x over previous
#include <cuda_runtime.h>
#include <cuda_fp16.h>
#include <math_constants.h>
#include <cstdint>
#include <cstddef>

#define BB 4
#define CCH 512
#define C8 64
#define HH 128
#define WW 128
#define HWV (HH*WW)

static const size_t NTOT = (size_t)BB * CCH * HWV;

// ---------------- scratch ----------------------------------------------------
__device__ __align__(16) float g_q  [BB*C8*HWV];                  // [b][c<64][hw]
__device__ __align__(16) float g_k  [BB*C8*HWV];
__device__ __align__(16) float g_qT [BB*C8*HWV];                  // [b][w][c][h]
__device__ __align__(16) float g_kT [BB*C8*HWV];
__device__ __align__(16) float g_att[(size_t)BB*HH*WW*256];
__device__ __align__(16) __half g_s1h[(size_t)BB*CCH*HWV];        // out_H [b][c][w][h]
__device__ __align__(16) __half g_s2h[(size_t)BB*CCH*HWV];        // out_W [b][c][h][w]
__device__ __align__(16) __half g_vh [(size_t)BB*CCH*HWV];        // [b][c][h][w]
__device__ __align__(16) __half g_vTh[(size_t)BB*CCH*HWV];        // [b][w][c][h]
__device__ __align__(16) __half g_attH[(size_t)BB*HWV*HH];        // [b][w][h][j]
__device__ __align__(16) __half g_attW[(size_t)BB*HWV*WW];        // [b][h][w][j]
__device__ __align__(16) __half g_xqh[(size_t)BB*HWV*CCH];
__device__ __align__(16) __half g_xql[(size_t)BB*HWV*CCH];
__device__ __align__(16) __half g_xeh[(size_t)BB*HWV*CCH];
__device__ __align__(16) __half g_xel[(size_t)BB*HWV*CCH];
__device__ __align__(16) __half g_wqkh[128*CCH], g_wqkl[128*CCH];
__device__ __align__(16) __half g_wvh[CCH*CCH];

// ---------------- PTX helpers ------------------------------------------------
__device__ __forceinline__ uint32_t smem_u32(const void* p) {
    uint32_t a;
    asm("{ .reg .u64 t; cvta.to.shared.u64 t, %1; cvt.u32.u64 %0, t; }" : "=r"(a) : "l"(p));
    return a;
}
#define LDMATRIX_X4(r0,r1,r2,r3,addr) \
    asm volatile("ldmatrix.sync.aligned.m8n8.x4.shared.b16 {%0,%1,%2,%3}, [%4];" \
                 : "=r"(r0),"=r"(r1),"=r"(r2),"=r"(r3) : "r"(addr))
#define MMA16816(d,a0,a1,a2,a3,b0,b1) \
    asm volatile("mma.sync.aligned.m16n8k16.row.col.f32.f16.f16.f32 " \
                 "{%0,%1,%2,%3},{%4,%5,%6,%7},{%8,%9},{%0,%1,%2,%3};" \
                 : "+f"((d)[0]),"+f"((d)[1]),"+f"((d)[2]),"+f"((d)[3]) \
                 : "r"(a0),"r"(a1),"r"(a2),"r"(a3),"r"(b0),"r"(b1))
#define CP_ASYNC16(dst,src) \
    asm volatile("cp.async.cg.shared.global [%0], [%1], 16;" :: "r"(dst),"l"(src))
#define CP_COMMIT() asm volatile("cp.async.commit_group;" ::: "memory")
#define CP_WAIT1()  asm volatile("cp.async.wait_group 1;" ::: "memory")
#define CP_WAIT0()  asm volatile("cp.async.wait_group 0;" ::: "memory")

// ---------------- split/transpose: x[b][c][n] -> [b][n][c] fp16 hi/lo ------
__global__ void split_transpose_kernel(__half* __restrict__ oh,
                                       __half* __restrict__ ol,
                                       const float* __restrict__ x) {
    __shared__ float tile[32][33];
    int b = blockIdx.z;
    int n0 = blockIdx.x * 32, c0 = blockIdx.y * 32;
    int tx = threadIdx.x, ty = threadIdx.y;
    const float* xp = x + ((size_t)b * CCH + c0) * HWV + n0;
#pragma unroll
    for (int r = 0; r < 4; r++)
        tile[ty + r * 8][tx] = xp[(size_t)(ty + r * 8) * HWV + tx];
    __syncthreads();
#pragma unroll
    for (int r = 0; r < 4; r++) {
        int nl = ty + r * 8, cl = tx;
        float v = tile[cl][nl];
        __half hi = __float2half_rn(v);
        __half lo = __float2half_rn(v - __half2float(hi));
        size_t o = ((size_t)b * HWV + n0 + nl) * CCH + c0 + cl;
        oh[o] = hi; ol[o] = lo;
    }
}

__global__ void split_plain_kernel(__half* __restrict__ oh,
                                   __half* __restrict__ ol,
                                   const float* __restrict__ src, int n) {
    int i = blockIdx.x * 256 + threadIdx.x;
    if (i < n) {
        float v = src[i];
        __half hi = __float2half_rn(v);
        oh[i] = hi;
        ol[i] = __float2half_rn(v - __half2float(hi));
    }
}
__global__ void convert_plain_kernel(__half* __restrict__ o,
                                     const float* __restrict__ s, int n) {
    int i = blockIdx.x * 256 + threadIdx.x;
    if (i < n) o[i] = __float2half_rn(s[i]);
}

// ---------------- gemm64: out[b][m<64][n] = bias[m] + A[m,:]·B[b][n,:] ------
// M=64 tile, N=128, K=512, 3 MMA terms (fp32-grade). fp32 output.
#define LDR     80
#define PLNA64  (64*LDR)
#define PLNB    (128*LDR)
#define GBUF64  (2*PLNA64 + 2*PLNB)
#define GSM64   (2*GBUF64)

__global__ void __launch_bounds__(256, 1) gemm64_mma_kernel(
    float* __restrict__ out,
    const __half* __restrict__ Ah, const __half* __restrict__ Al,
    const __half* __restrict__ Bh, const __half* __restrict__ Bl,
    const float* __restrict__ bias)
{
    extern __shared__ char smem[];
    uint32_t sbase = smem_u32(smem);
    int tid = threadIdx.x, wid = tid >> 5, lane = tid & 31;
    int n0 = blockIdx.x * 128, b = blockIdx.z;
    int wm = wid & 1, wn = wid >> 1;

    const __half* Bhb = Bh + ((size_t)b * HWV + n0) * CCH;
    const __half* Blb = Bl + ((size_t)b * HWV + n0) * CCH;

    float acc[2][4][4];
#pragma unroll
    for (int i = 0; i < 2; i++)
#pragma unroll
        for (int j = 0; j < 4; j++)
#pragma unroll
            for (int k = 0; k < 4; k++) acc[i][j][k] = 0.f;

    int lg = lane >> 3, lr = lane & 7;

    auto issue = [&](int c, int buf) {
        int kc0 = c * 32;
#pragma unroll
        for (int i = 0; i < 2; i++) {
            int idx = i * 256 + tid;
            int plane = idx >> 8, j = idx & 255;
            int r = j >> 2, seg = j & 3;
            const __half* src = (plane ? Al : Ah) + (size_t)r * CCH + kc0 + seg * 8;
            uint32_t dst = sbase + buf * GBUF64 + plane * PLNA64 + r * LDR + seg * 16;
            CP_ASYNC16(dst, src);
        }
#pragma unroll
        for (int i = 0; i < 4; i++) {
            int idx = i * 256 + tid;
            int plane = idx >> 9, j = idx & 511;
            int r = j >> 2, seg = j & 3;
            const __half* src = (plane ? Blb : Bhb) + (size_t)r * CCH + kc0 + seg * 8;
            uint32_t dst = sbase + buf * GBUF64 + 2 * PLNA64 + plane * PLNB
                         + r * LDR + seg * 16;
            CP_ASYNC16(dst, src);
        }
        CP_COMMIT();
    };

    issue(0, 0);
    for (int c = 0; c < 16; c++) {
        int buf = c & 1;
        if (c < 15) { issue(c + 1, buf ^ 1); CP_WAIT1(); } else { CP_WAIT0(); }
        __syncthreads();
        uint32_t sAh = sbase + buf * GBUF64;
        uint32_t sAl = sAh + PLNA64;
        uint32_t sBh = sAl + PLNA64;
        uint32_t sBl = sBh + PLNB;
#pragma unroll
        for (int ks = 0; ks < 2; ks++) {
            uint32_t ah[2][4], al[2][4];
#pragma unroll
            for (int mf = 0; mf < 2; mf++) {
                uint32_t roff = (wm * 32 + mf * 16 + lr + (lg & 1) * 8) * LDR
                              + (ks * 16 + (lg >> 1) * 8) * 2;
                LDMATRIX_X4(ah[mf][0], ah[mf][1], ah[mf][2], ah[mf][3], sAh + roff);
                LDMATRIX_X4(al[mf][0], al[mf][1], al[mf][2], al[mf][3], sAl + roff);
            }
            uint32_t bh[4][2], bl[4][2];
#pragma unroll
            for (int np = 0; np < 2; np++) {
                uint32_t roff = (wn * 32 + np * 16 + (lg >> 1) * 8 + lr) * LDR
                              + (ks * 16 + (lg & 1) * 8) * 2;
                uint32_t r0, r1, r2, r3;
                LDMATRIX_X4(r0, r1, r2, r3, sBh + roff);
                bh[np * 2][0] = r0; bh[np * 2][1] = r1;
                bh[np * 2 + 1][0] = r2; bh[np * 2 + 1][1] = r3;
                LDMATRIX_X4(r0, r1, r2, r3, sBl + roff);
                bl[np * 2][0] = r0; bl[np * 2][1] = r1;
                bl[np * 2 + 1][0] = r2; bl[np * 2 + 1][1] = r3;
            }
#pragma unroll
            for (int mf = 0; mf < 2; mf++)
#pragma unroll
                for (int nf = 0; nf < 4; nf++) {
                    MMA16816(acc[mf][nf], ah[mf][0], ah[mf][1], ah[mf][2], ah[mf][3],
                             bh[nf][0], bh[nf][1]);
                    MMA16816(acc[mf][nf], ah[mf][0], ah[mf][1], ah[mf][2], ah[mf][3],
                             bl[nf][0], bl[nf][1]);
                    MMA16816(acc[mf][nf], al[mf][0], al[mf][1], al[mf][2], al[mf][3],
                             bh[nf][0], bh[nf][1]);
                }
        }
        __syncthreads();
    }

#pragma unroll
    for (int mf = 0; mf < 2; mf++) {
        int row = wm * 32 + mf * 16 + (lane >> 2);
        float bv0 = bias[row], bv1 = bias[row + 8];
        float* op0 = out + (size_t)b * ((size_t)C8 * HWV) + (size_t)row * HWV
                   + n0 + wn * 32 + (lane & 3) * 2;
        float* op1 = op0 + (size_t)8 * HWV;
#pragma unroll
        for (int nf = 0; nf < 4; nf++) {
            *(float2*)(op0 + nf * 8) = make_float2(acc[mf][nf][0] + bv0, acc[mf][nf][1] + bv0);
            *(float2*)(op1 + nf * 8) = make_float2(acc[mf][nf][2] + bv1, acc[mf][nf][3] + bv1);
        }
    }
}

// ---------------- gemmv: single-term fp16 GEMM, fp16 output -----------------
#define GBUFV (2*PLNB)
#define GSMV  (2*GBUFV)

__global__ void __launch_bounds__(256, 1) gemmv_mma_kernel(
    __half* __restrict__ out,
    const __half* __restrict__ Ah, const __half* __restrict__ Bh,
    const float* __restrict__ bias)
{
    extern __shared__ char smem[];
    uint32_t sbase = smem_u32(smem);
    int tid = threadIdx.x, wid = tid >> 5, lane = tid & 31;
    int n0 = blockIdx.x * 128, m0 = blockIdx.y * 128, b = blockIdx.z;
    int wm = wid & 3, wn = wid >> 2;

    const __half* Ahb = Ah + (size_t)m0 * CCH;
    const __half* Bhb = Bh + ((size_t)b * HWV + n0) * CCH;

    float acc[2][8][4];
#pragma unroll
    for (int i = 0; i < 2; i++)
#pragma unroll
        for (int j = 0; j < 8; j++)
#pragma unroll
            for (int k = 0; k < 4; k++) acc[i][j][k] = 0.f;

    int lg = lane >> 3, lr = lane & 7;

    auto issue = [&](int c, int buf) {
        int kc0 = c * 32;
#pragma unroll
        for (int i = 0; i < 4; i++) {
            int idx = i * 256 + tid;
            int plane = idx >> 9, j = idx & 511;
            int r = j >> 2, seg = j & 3;
            const __half* src = (plane ? Bhb : Ahb) + (size_t)r * CCH + kc0 + seg * 8;
            uint32_t dst = sbase + buf * GBUFV + plane * PLNB + r * LDR + seg * 16;
            CP_ASYNC16(dst, src);
        }
        CP_COMMIT();
    };

    issue(0, 0);
    for (int c = 0; c < 16; c++) {
        int buf = c & 1;
        if (c < 15) { issue(c + 1, buf ^ 1); CP_WAIT1(); } else { CP_WAIT0(); }
        __syncthreads();
        uint32_t sA = sbase + buf * GBUFV;
        uint32_t sB = sA + PLNB;
#pragma unroll
        for (int ks = 0; ks < 2; ks++) {
            uint32_t ah[2][4];
#pragma unroll
            for (int mf = 0; mf < 2; mf++) {
                uint32_t roff = (wm * 32 + mf * 16 + lr + (lg & 1) * 8) * LDR
                              + (ks * 16 + (lg >> 1) * 8) * 2;
                LDMATRIX_X4(ah[mf][0], ah[mf][1], ah[mf][2], ah[mf][3], sA + roff);
            }
            uint32_t bh[8][2];
#pragma unroll
            for (int np = 0; np < 4; np++) {
                uint32_t roff = (wn * 64 + np * 16 + (lg >> 1) * 8 + lr) * LDR
                              + (ks * 16 + (lg & 1) * 8) * 2;
                uint32_t r0, r1, r2, r3;
                LDMATRIX_X4(r0, r1, r2, r3, sB + roff);
                bh[np * 2][0] = r0; bh[np * 2][1] = r1;
                bh[np * 2 + 1][0] = r2; bh[np * 2 + 1][1] = r3;
            }
#pragma unroll
            for (int mf = 0; mf < 2; mf++)
#pragma unroll
                for (int nf = 0; nf < 8; nf++)
                    MMA16816(acc[mf][nf], ah[mf][0], ah[mf][1], ah[mf][2], ah[mf][3],
                             bh[nf][0], bh[nf][1]);
        }
        __syncthreads();
    }

#pragma unroll
    for (int mf = 0; mf < 2; mf++) {
        int row = m0 + wm * 32 + mf * 16 + (lane >> 2);
        float bv0 = bias[row], bv1 = bias[row + 8];
        __half* op0 = out + (size_t)b * ((size_t)CCH * HWV) + (size_t)row * HWV
                    + n0 + wn * 64 + (lane & 3) * 2;
        __half* op1 = op0 + (size_t)8 * HWV;
#pragma unroll
        for (int nf = 0; nf < 8; nf++) {
            *(__half2*)(op0 + nf * 8) = __floats2half2_rn(acc[mf][nf][0] + bv0, acc[mf][nf][1] + bv0);
            *(__half2*)(op1 + nf * 8) = __floats2half2_rn(acc[mf][nf][2] + bv1, acc[mf][nf][3] + bv1);
        }
    }
}

// ---------------- attention output GEMM (fp16 mma, fp16 out) ----------------
#define LDT 272

__global__ void __launch_bounds__(256) attn_out_kernel(
    __half* __restrict__ out,
    const __half* __restrict__ A, size_t aRow, size_t ASf, size_t ASb,
    const __half* __restrict__ Bm)
{
    extern __shared__ char smem[];
    uint32_t sA = smem_u32(smem);
    uint32_t sB = sA + 128 * LDT;
    int tid = threadIdx.x, wid = tid >> 5, lane = tid & 31;
    int ct = blockIdx.x, f = blockIdx.y, b = blockIdx.z;
    int wm = wid & 3, wn = wid >> 2;

    const __half* Ac = A + (size_t)b * ASb + (size_t)f * ASf + (size_t)ct * 128 * aRow;
    const __half* Bc = Bm + ((size_t)b * 128 + f) * 16384;

#pragma unroll
    for (int i = 0; i < 8; i++) {
        int idx = i * 256 + tid;
        int r = idx >> 4, seg = idx & 15;
        CP_ASYNC16(sA + r * LDT + seg * 16, Ac + (size_t)r * aRow + seg * 8);
    }
#pragma unroll
    for (int i = 0; i < 8; i++) {
        int idx = i * 256 + tid;
        int r = idx >> 4, seg = idx & 15;
        CP_ASYNC16(sB + r * LDT + seg * 16, Bc + (size_t)r * 128 + seg * 8);
    }
    CP_COMMIT(); CP_WAIT0();
    __syncthreads();

    float acc[2][8][4];
#pragma unroll
    for (int i = 0; i < 2; i++)
#pragma unroll
        for (int j = 0; j < 8; j++)
#pragma unroll
            for (int k = 0; k < 4; k++) acc[i][j][k] = 0.f;

    int lg = lane >> 3, lr = lane & 7;
#pragma unroll
    for (int kk = 0; kk < 8; kk++) {
        uint32_t a[2][4];
#pragma unroll
        for (int mf = 0; mf < 2; mf++) {
            uint32_t roff = (wm * 32 + mf * 16 + lr + (lg & 1) * 8) * LDT
                          + (kk * 16 + (lg >> 1) * 8) * 2;
            LDMATRIX_X4(a[mf][0], a[mf][1], a[mf][2], a[mf][3], sA + roff);
        }
        uint32_t bf[8][2];
#pragma unroll
        for (int np = 0; np < 4; np++) {
            uint32_t roff = (wn * 64 + np * 16 + (lg >> 1) * 8 + lr) * LDT
                          + (kk * 16 + (lg & 1) * 8) * 2;
            uint32_t r0, r1, r2, r3;
            LDMATRIX_X4(r0, r1, r2, r3, sB + roff);
            bf[np * 2][0] = r0; bf[np * 2][1] = r1;
            bf[np * 2 + 1][0] = r2; bf[np * 2 + 1][1] = r3;
        }
#pragma unroll
        for (int mf = 0; mf < 2; mf++)
#pragma unroll
            for (int nf = 0; nf < 8; nf++)
                MMA16816(acc[mf][nf], a[mf][0], a[mf][1], a[mf][2], a[mf][3],
                         bf[nf][0], bf[nf][1]);
    }

    __half* oc = out + (size_t)b * ((size_t)CCH * HWV) + (size_t)f * 128
               + (size_t)ct * 128 * HWV;
#pragma unroll
    for (int mf = 0; mf < 2; mf++) {
        int row = wm * 32 + mf * 16 + (lane >> 2);
        __half* op0 = oc + (size_t)row * HWV + wn * 64 + (lane & 3) * 2;
        __half* op1 = op0 + (size_t)8 * HWV;
#pragma unroll
        for (int nf = 0; nf < 8; nf++) {
            *(__half2*)(op0 + nf * 8) = __floats2half2_rn(acc[mf][nf][0], acc[mf][nf][1]);
            *(__half2*)(op1 + nf * 8) = __floats2half2_rn(acc[mf][nf][2], acc[mf][nf][3]);
        }
    }
}

// ---------------- transpose fp32 ---------------------------------------------
__global__ void transpose_hw_kernel(float* __restrict__ dst,
                                    const float* __restrict__ src,
                                    int planes, size_t srcBatchStride) {
    __shared__ float tile[32][33];
    int p = blockIdx.z;
    int b = p / planes, c = p % planes;
    int w0 = blockIdx.x * 32, h0 = blockIdx.y * 32;
    int tx = threadIdx.x, ty = threadIdx.y;
    const float* s = src + (size_t)b * srcBatchStride + (size_t)c * HWV;
#pragma unroll
    for (int r = 0; r < 4; r++) {
        int h = h0 + ty + r * 8;
        tile[ty + r * 8][tx] = s[(size_t)h * WW + w0 + tx];
    }
    __syncthreads();
#pragma unroll
    for (int r = 0; r < 4; r++) {
        int w = w0 + ty + r * 8;
        dst[(((size_t)b * WW + w) * planes + c) * HH + h0 + tx] = tile[tx][ty + r * 8];
    }
}

// ---------------- transpose fp16: g_vh -> g_vTh -----------------------------
__global__ void transpose_hw_half_kernel() {
    __shared__ __half tile[32][36];
    int p = blockIdx.z;
    int b = p >> 9, c = p & 511;
    int w0 = blockIdx.x * 32, h0 = blockIdx.y * 32;
    int tx = threadIdx.x, ty = threadIdx.y;
    const __half* s = g_vh + ((size_t)b * CCH + c) * HWV;
#pragma unroll
    for (int r = 0; r < 4; r++) {
        int h = h0 + ty + r * 8;
        tile[ty + r * 8][tx] = s[(size_t)h * WW + w0 + tx];
    }
    __syncthreads();
#pragma unroll
    for (int r = 0; r < 4; r++) {
        int w = w0 + ty + r * 8;
        g_vTh[(((size_t)b * WW + w) * CCH + c) * HH + h0 + tx] = tile[tx][ty + r * 8];
    }
}

// ---------------- energy_H ---------------------------------------------------
__global__ void energy_h_kernel() {
    __shared__ float As[16][128];
    __shared__ float Bs[16][128];
    int w = blockIdx.x, b = blockIdx.y;
    int tid = threadIdx.x;
    int tx = tid & 15, ty = tid >> 4;
    int m0 = ty * 8, n0 = tx * 8;
    const float* qT = g_qT + ((size_t)(b * WW + w)) * C8 * HH;
    const float* kT = g_kT + ((size_t)(b * WW + w)) * C8 * HH;
    float acc[8][8];
#pragma unroll
    for (int i = 0; i < 8; i++)
#pragma unroll
        for (int j = 0; j < 8; j++) acc[i][j] = 0.f;

    for (int k0 = 0; k0 < C8; k0 += 16) {
#pragma unroll
        for (int i = 0; i < 8; i++) {
            int idx = tid + i * 256;
            int cc = idx >> 7, hh = idx & 127;
            As[cc][hh] = qT[(k0 + cc) * HH + hh];
            Bs[cc][hh] = kT[(k0 + cc) * HH + hh];
        }
        __syncthreads();
#pragma unroll
        for (int kk = 0; kk < 16; kk++) {
            float a[8], bb[8];
            *(float4*)&a[0]  = *(const float4*)&As[kk][m0];
            *(float4*)&a[4]  = *(const float4*)&As[kk][m0 + 4];
            *(float4*)&bb[0] = *(const float4*)&Bs[kk][n0];
            *(float4*)&bb[4] = *(const float4*)&Bs[kk][n0 + 4];
#pragma unroll
            for (int i = 0; i < 8; i++)
#pragma unroll
                for (int j = 0; j < 8; j++) acc[i][j] += a[i] * bb[j];
        }
        __syncthreads();
    }
#pragma unroll
    for (int i = 0; i < 8; i++) {
        int h = m0 + i;
        float* row = g_att + (((size_t)b * HH + h) * WW + w) * 256;
#pragma unroll
        for (int j = 0; j < 8; j++) {
            int jj = n0 + j;
            row[jj] = (jj == h) ? -CUDART_INF_F : acc[i][j];
        }
    }
}

// ---------------- energy_W ---------------------------------------------------
__global__ void energy_w_kernel() {
    __shared__ float As[16][128];
    __shared__ float Bs[16][128];
    int h = blockIdx.x, b = blockIdx.y;
    int tid = threadIdx.x;
    int tx = tid & 15, ty = tid >> 4;
    int m0 = ty * 8, n0 = tx * 8;
    const float* qp = g_q + (size_t)b * C8 * HWV + (size_t)h * WW;
    const float* kp = g_k + (size_t)b * C8 * HWV + (size_t)h * WW;
    float acc[8][8];
#pragma unroll
    for (int i = 0; i < 8; i++)
#pragma unroll
        for (int j = 0; j < 8; j++) acc[i][j] = 0.f;

    for (int k0 = 0; k0 < C8; k0 += 16) {
#pragma unroll
        for (int i = 0; i < 8; i++) {
            int idx = tid + i * 256;
            int cc = idx >> 7, nn = idx & 127;
            As[cc][nn] = qp[(size_t)(k0 + cc) * HWV + nn];
            Bs[cc][nn] = kp[(size_t)(k0 + cc) * HWV + nn];
        }
        __syncthreads();
#pragma unroll
        for (int kk = 0; kk < 16; kk++) {
            float a[8], bb[8];
            *(float4*)&a[0]  = *(const float4*)&As[kk][m0];
            *(float4*)&a[4]  = *(const float4*)&As[kk][m0 + 4];
            *(float4*)&bb[0] = *(const float4*)&Bs[kk][n0];
            *(float4*)&bb[4] = *(const float4*)&Bs[kk][n0 + 4];
#pragma unroll
            for (int i = 0; i < 8; i++)
#pragma unroll
                for (int j = 0; j < 8; j++) acc[i][j] += a[i] * bb[j];
        }
        __syncthreads();
    }
#pragma unroll
    for (int i = 0; i < 8; i++) {
        int wv = m0 + i;
        float* row = g_att + (((size_t)b * HH + h) * WW + wv) * 256 + 128;
#pragma unroll
        for (int j = 0; j < 8; j++) row[n0 + j] = acc[i][j];
    }
}

// ---------------- softmax -> fp16 att ---------------------------------------
__global__ void softmax_kernel() {
    int row  = blockIdx.x * 8 + (threadIdx.x >> 5);
    int lane = threadIdx.x & 31;
    const float* p = g_att + (size_t)row * 256;
    int b = row >> 14, h = (row >> 7) & 127, w = row & 127;
    float v[8];
    float m = -CUDART_INF_F;
#pragma unroll
    for (int i = 0; i < 8; i++) { v[i] = p[lane + 32 * i]; m = fmaxf(m, v[i]); }
#pragma unroll
    for (int o = 16; o > 0; o >>= 1) m = fmaxf(m, __shfl_xor_sync(0xffffffffu, m, o));
    float s = 0.f;
#pragma unroll
    for (int i = 0; i < 8; i++) { v[i] = __expf(v[i] - m); s += v[i]; }
#pragma unroll
    for (int o = 16; o > 0; o >>= 1) s += __shfl_xor_sync(0xffffffffu, s, o);
    float inv = 1.0f / s;
    __half* pH = g_attH + (((size_t)b * WW + w) * HH + h) * 128;
    __half* pW = g_attW + (size_t)row * 128;
#pragma unroll
    for (int i = 0; i < 4; i++) pH[lane + 32 * i] = __float2half(v[i] * inv);
#pragma unroll
    for (int i = 4; i < 8; i++) pW[lane + 32 * (i - 4)] = __float2half(v[i] * inv);
}

// ---------------- combine ----------------------------------------------------
__global__ void combine_kernel(float* __restrict__ out,
                               const float* __restrict__ xe,
                               const float* __restrict__ xq,
                               const float* __restrict__ g1p,
                               const float* __restrict__ g2p) {
    __shared__ __half tile[32][36];
    int bc = blockIdx.z;
    int w0 = blockIdx.x * 32, h0 = blockIdx.y * 32;
    int tx = threadIdx.x, ty = threadIdx.y;
    size_t base = (size_t)bc * HWV;
#pragma unroll
    for (int r = 0; r < 4; r++) {
        int wv = w0 + ty + r * 8;
        tile[ty + r * 8][tx] = g_s1h[base + (size_t)wv * HH + h0 + tx];
    }
    __syncthreads();
    float gam1 = g1p[0], gam2 = g2p[0];
#pragma unroll
    for (int r = 0; r < 4; r++) {
        int h = h0 + ty + r * 8;
        int wv = w0 + tx;
        size_t idx = base + (size_t)h * WW + wv;
        float t = __half2float(tile[tx][ty + r * 8]) + __half2float(g_s2h[idx]) + 2.0f;
        out[idx]        = fmaf(gam1, t, xe[idx]);
        out[NTOT + idx] = fmaf(gam2, t, xq[idx]);
    }
}

// ---------------- launch ------------------------------------------------------
extern "C" void kernel_launch(void* const* d_in, const int* in_sizes, int n_in,
                              void* d_out, int out_size) {
    const float* xe = (const float*)d_in[0];
    const float* xq = (const float*)d_in[1];
    const float* Wq = (const float*)d_in[2];
    const float* bq = (const float*)d_in[3];
    const float* Wk = (const float*)d_in[4];
    const float* bk = (const float*)d_in[5];
    const float* Wv = (const float*)d_in[6];
    const float* bv = (const float*)d_in[7];
    const float* g1 = (const float*)d_in[8];
    const float* g2 = (const float*)d_in[9];
    float* out = (float*)d_out;

    float *pq, *pk, *pqT, *pkT;
    __half *pxqh, *pxql, *pxeh, *pxel, *pwqkh, *pwqkl, *pwvh;
    __half *pvh, *pvTh, *pattH, *pattW, *ps1h, *ps2h;
    cudaGetSymbolAddress((void**)&pq,   g_q);
    cudaGetSymbolAddress((void**)&pk,   g_k);
    cudaGetSymbolAddress((void**)&pqT,  g_qT);
    cudaGetSymbolAddress((void**)&pkT,  g_kT);
    cudaGetSymbolAddress((void**)&pxqh, g_xqh);
    cudaGetSymbolAddress((void**)&pxql, g_xql);
    cudaGetSymbolAddress((void**)&pxeh, g_xeh);
    cudaGetSymbolAddress((void**)&pxel, g_xel);
    cudaGetSymbolAddress((void**)&pwqkh, g_wqkh);
    cudaGetSymbolAddress((void**)&pwqkl, g_wqkl);
    cudaGetSymbolAddress((void**)&pwvh, g_wvh);
    cudaGetSymbolAddress((void**)&pvh,  g_vh);
    cudaGetSymbolAddress((void**)&pvTh, g_vTh);
    cudaGetSymbolAddress((void**)&pattH, g_attH);
    cudaGetSymbolAddress((void**)&pattW, g_attW);
    cudaGetSymbolAddress((void**)&ps1h, g_s1h);
    cudaGetSymbolAddress((void**)&ps2h, g_s2h);

    cudaFuncSetAttribute(gemm64_mma_kernel,
                         cudaFuncAttributeMaxDynamicSharedMemorySize, GSM64);
    cudaFuncSetAttribute(gemmv_mma_kernel,
                         cudaFuncAttributeMaxDynamicSharedMemorySize, GSMV);
    cudaFuncSetAttribute(attn_out_kernel,
                         cudaFuncAttributeMaxDynamicSharedMemorySize, 2 * 128 * LDT);

    // splits / converts
    split_transpose_kernel<<<dim3(HWV / 32, CCH / 32, BB), dim3(32, 8)>>>(pxqh, pxql, xq);
    split_transpose_kernel<<<dim3(HWV / 32, CCH / 32, BB), dim3(32, 8)>>>(pxeh, pxel, xe);
    split_plain_kernel<<<(64 * CCH + 255) / 256, 256>>>(pwqkh, pwqkl, Wq, 64 * CCH);
    split_plain_kernel<<<(64 * CCH + 255) / 256, 256>>>(pwqkh + 64 * CCH, pwqkl + 64 * CCH, Wk, 64 * CCH);
    convert_plain_kernel<<<(CCH * CCH + 255) / 256, 256>>>(pwvh, Wv, CCH * CCH);

    // projections
    gemm64_mma_kernel<<<dim3(HWV / 128, 1, BB), 256, GSM64>>>(
        pq, pwqkh, pwqkl, pxqh, pxql, bq);
    gemm64_mma_kernel<<<dim3(HWV / 128, 1, BB), 256, GSM64>>>(
        pk, pwqkh + 64 * CCH, pwqkl + 64 * CCH, pxeh, pxel, bk);
    gemmv_mma_kernel<<<dim3(HWV / 128, CCH / 128, BB), 256, GSMV>>>(
        pvh, pwvh, pxeh, bv);

    // transposes
    transpose_hw_kernel<<<dim3(4, 4, BB * C8), dim3(32, 8)>>>(pqT, pq, C8, (size_t)C8 * HWV);
    transpose_hw_kernel<<<dim3(4, 4, BB * C8), dim3(32, 8)>>>(pkT, pk, C8, (size_t)C8 * HWV);
    transpose_hw_half_kernel<<<dim3(4, 4, BB * CCH), dim3(32, 8)>>>();

    // energies + softmax
    energy_h_kernel<<<dim3(WW, BB), 256>>>();
    energy_w_kernel<<<dim3(HH, BB), 256>>>();
    softmax_kernel<<<(BB * HH * WW) / 8, 256>>>();

    // attention outputs
    attn_out_kernel<<<dim3(CCH / 128, WW, BB), 256, 2 * 128 * LDT>>>(
        ps1h, pvTh, 128, (size_t)CCH * 128, (size_t)WW * CCH * 128, pattH);
    attn_out_kernel<<<dim3(CCH / 128, HH, BB), 256, 2 * 128 * LDT>>>(
        ps2h, pvh, HWV, 128, (size_t)CCH * HWV, pattW);

    // combine
    combine_kernel<<<dim3(4, 4, BB * CCH), dim3(32, 8)>>>(out, xe, xq, g1, g2);
}

// round 7
// speedup vs baseline: 3.7041x; 1.1086x over previous
#include <cuda_runtime.h>
#include <cuda_fp16.h>
#include <math_constants.h>
#include <cstdint>
#include <cstddef>

#define BB 4
#define CCH 512
#define C8 64
#define HH 128
#define WW 128
#define HWV (HH*WW)

static const size_t NTOT = (size_t)BB * CCH * HWV;

// ---------------- scratch ----------------------------------------------------
__device__ __align__(16) float g_q  [BB*C8*HWV];                  // [b][c<64][hw]
__device__ __align__(16) float g_k  [BB*C8*HWV];
__device__ __align__(16) float g_qT [BB*C8*HWV];                  // [b][w][c][h]
__device__ __align__(16) float g_kT [BB*C8*HWV];
__device__ __align__(16) float g_att[(size_t)BB*HH*WW*256];
__device__ __align__(16) __half g_s1h[(size_t)BB*CCH*HWV];        // out_H [b][c][w][h]
__device__ __align__(16) __half g_s2h[(size_t)BB*CCH*HWV];        // out_W [b][c][h][w]
__device__ __align__(16) __half g_vh [(size_t)BB*CCH*HWV];        // [b][c][h][w]
__device__ __align__(16) __half g_vTh[(size_t)BB*CCH*HWV];        // [b][w][c][h]
__device__ __align__(16) __half g_attH[(size_t)BB*HWV*HH];        // [b][w][h][j]
__device__ __align__(16) __half g_attW[(size_t)BB*HWV*WW];        // [b][h][w][j]
__device__ __align__(16) __half g_wqkh[128*CCH], g_wqkl[128*CCH];
__device__ __align__(16) __half g_wvh[CCH*CCH];

// ---------------- PTX helpers ------------------------------------------------
__device__ __forceinline__ uint32_t smem_u32(const void* p) {
    uint32_t a;
    asm("{ .reg .u64 t; cvta.to.shared.u64 t, %1; cvt.u32.u64 %0, t; }" : "=r"(a) : "l"(p));
    return a;
}
__device__ __forceinline__ uint32_t pkh(__half a, __half b) {
    __half2 t = __halves2half2(a, b);
    return *reinterpret_cast<uint32_t*>(&t);
}
#define LDMATRIX_X4(r0,r1,r2,r3,addr) \
    asm volatile("ldmatrix.sync.aligned.m8n8.x4.shared.b16 {%0,%1,%2,%3}, [%4];" \
                 : "=r"(r0),"=r"(r1),"=r"(r2),"=r"(r3) : "r"(addr))
#define LDMATRIX_X4_T(r0,r1,r2,r3,addr) \
    asm volatile("ldmatrix.sync.aligned.m8n8.x4.trans.shared.b16 {%0,%1,%2,%3}, [%4];" \
                 : "=r"(r0),"=r"(r1),"=r"(r2),"=r"(r3) : "r"(addr))
#define MMA16816(d,a0,a1,a2,a3,b0,b1) \
    asm volatile("mma.sync.aligned.m16n8k16.row.col.f32.f16.f16.f32 " \
                 "{%0,%1,%2,%3},{%4,%5,%6,%7},{%8,%9},{%0,%1,%2,%3};" \
                 : "+f"((d)[0]),"+f"((d)[1]),"+f"((d)[2]),"+f"((d)[3]) \
                 : "r"(a0),"r"(a1),"r"(a2),"r"(a3),"r"(b0),"r"(b1))
#define CP_ASYNC16(dst,src) \
    asm volatile("cp.async.cg.shared.global [%0], [%1], 16;" :: "r"(dst),"l"(src))
#define CP_COMMIT() asm volatile("cp.async.commit_group;" ::: "memory")
#define CP_WAIT1()  asm volatile("cp.async.wait_group 1;" ::: "memory")
#define CP_WAIT0()  asm volatile("cp.async.wait_group 0;" ::: "memory")

// ---------------- weight prep ------------------------------------------------
__global__ void split_plain_kernel(__half* __restrict__ oh,
                                   __half* __restrict__ ol,
                                   const float* __restrict__ src, int n) {
    int i = blockIdx.x * 256 + threadIdx.x;
    if (i < n) {
        float v = src[i];
        __half hi = __float2half_rn(v);
        oh[i] = hi;
        ol[i] = __float2half_rn(v - __half2float(hi));
    }
}
__global__ void convert_plain_kernel(__half* __restrict__ o,
                                     const float* __restrict__ s, int n) {
    int i = blockIdx.x * 256 + threadIdx.x;
    if (i < n) o[i] = __float2half_rn(s[i]);
}

// ---------------- gemm64 (fused conversion): q/k projections ----------------
// out[b][m<64][n] = bias[m] + sum_k W[m,k] * x[b][k][n]; x read as fp32,
// converted in-kernel to fp16 hi/lo; B frags via ldmatrix.trans from [k][n].
#define LDR    80
#define LDB    272
// smem offsets (gemm64)
#define G64_A    0                       // buf*10240 + plane*5120, pitch 80
#define G64_STG  20480                   // buf*16384, pitch 512
#define G64_BH   53248
#define G64_BL   61952
#define G64_SM   70656

__global__ void __launch_bounds__(256, 1) gemm64_mma_kernel(
    float* __restrict__ out,
    const __half* __restrict__ Ah, const __half* __restrict__ Al,
    const float* __restrict__ X, const float* __restrict__ bias)
{
    extern __shared__ char smem[];
    uint32_t sbase = smem_u32(smem);
    int tid = threadIdx.x, wid = tid >> 5, lane = tid & 31;
    int n0 = blockIdx.x * 128, b = blockIdx.z;
    int wm = wid & 1, wn = wid >> 1;

    const float* Xb = X + (size_t)b * CCH * HWV + n0;

    float acc[2][4][4];
#pragma unroll
    for (int i = 0; i < 2; i++)
#pragma unroll
        for (int j = 0; j < 4; j++)
#pragma unroll
            for (int k = 0; k < 4; k++) acc[i][j][k] = 0.f;

    int lg = lane >> 3, lr = lane & 7;

    auto issue = [&](int c, int buf) {
        int kc0 = c * 32;
        // A hi/lo: 64 rows x 4 segs x 2 planes = 512
#pragma unroll
        for (int i = 0; i < 2; i++) {
            int idx = i * 256 + tid;
            int plane = idx >> 8, j = idx & 255;
            int r = j >> 2, seg = j & 3;
            const __half* src = (plane ? Al : Ah) + (size_t)r * CCH + kc0 + seg * 8;
            uint32_t dst = sbase + G64_A + buf * 10240 + plane * 5120 + r * LDR + seg * 16;
            CP_ASYNC16(dst, src);
        }
        // B staging fp32: 32 rows x 32 segs(16B) = 1024
#pragma unroll
        for (int i = 0; i < 4; i++) {
            int idx = i * 256 + tid;
            int r = idx >> 5, seg = idx & 31;
            const float* src = Xb + (size_t)(kc0 + r) * HWV + seg * 4;
            uint32_t dst = sbase + G64_STG + buf * 16384 + r * 512 + seg * 16;
            CP_ASYNC16(dst, src);
        }
        CP_COMMIT();
    };

    issue(0, 0);
    for (int c = 0; c < 16; c++) {
        int buf = c & 1;
        if (c < 15) { issue(c + 1, buf ^ 1); CP_WAIT1(); } else { CP_WAIT0(); }
        __syncthreads();
        // convert staging -> B hi/lo [k=32][n=128] pitch 272
        {
            const char* stg = smem + G64_STG + buf * 16384;
#pragma unroll
            for (int i = 0; i < 4; i++) {
                int idx = i * 256 + tid;
                int r = idx >> 5, cc = idx & 31;
                float4 f = *(const float4*)(stg + r * 512 + cc * 16);
                __half h0 = __float2half_rn(f.x), h1 = __float2half_rn(f.y);
                __half h2 = __float2half_rn(f.z), h3 = __float2half_rn(f.w);
                __half l0 = __float2half_rn(f.x - __half2float(h0));
                __half l1 = __float2half_rn(f.y - __half2float(h1));
                __half l2 = __float2half_rn(f.z - __half2float(h2));
                __half l3 = __float2half_rn(f.w - __half2float(h3));
                uint2 hv = make_uint2(pkh(h0, h1), pkh(h2, h3));
                uint2 lv = make_uint2(pkh(l0, l1), pkh(l2, l3));
                *(uint2*)(smem + G64_BH + r * LDB + cc * 8) = hv;
                *(uint2*)(smem + G64_BL + r * LDB + cc * 8) = lv;
            }
        }
        __syncthreads();
        uint32_t sAh = sbase + G64_A + buf * 10240;
        uint32_t sAl = sAh + 5120;
        uint32_t sBH = sbase + G64_BH;
        uint32_t sBL = sbase + G64_BL;
#pragma unroll
        for (int ks = 0; ks < 2; ks++) {
            uint32_t ah[2][4], al[2][4];
#pragma unroll
            for (int mf = 0; mf < 2; mf++) {
                uint32_t roff = (wm * 32 + mf * 16 + lr + (lg & 1) * 8) * LDR
                              + (ks * 16 + (lg >> 1) * 8) * 2;
                LDMATRIX_X4(ah[mf][0], ah[mf][1], ah[mf][2], ah[mf][3], sAh + roff);
                LDMATRIX_X4(al[mf][0], al[mf][1], al[mf][2], al[mf][3], sAl + roff);
            }
            uint32_t trow = ks * 16 + ((lane >> 3) & 1) * 8 + (lane & 7);
            uint32_t bh[4][2], bl[4][2];
#pragma unroll
            for (int np = 0; np < 2; np++) {
                uint32_t tcol = wn * 32 + np * 16 + (lane >> 4) * 8;
                uint32_t addr = trow * LDB + tcol * 2;
                uint32_t r0, r1, r2, r3;
                LDMATRIX_X4_T(r0, r1, r2, r3, sBH + addr);
                bh[np * 2][0] = r0; bh[np * 2][1] = r1;
                bh[np * 2 + 1][0] = r2; bh[np * 2 + 1][1] = r3;
                LDMATRIX_X4_T(r0, r1, r2, r3, sBL + addr);
                bl[np * 2][0] = r0; bl[np * 2][1] = r1;
                bl[np * 2 + 1][0] = r2; bl[np * 2 + 1][1] = r3;
            }
#pragma unroll
            for (int mf = 0; mf < 2; mf++)
#pragma unroll
                for (int nf = 0; nf < 4; nf++) {
                    MMA16816(acc[mf][nf], ah[mf][0], ah[mf][1], ah[mf][2], ah[mf][3],
                             bh[nf][0], bh[nf][1]);
                    MMA16816(acc[mf][nf], ah[mf][0], ah[mf][1], ah[mf][2], ah[mf][3],
                             bl[nf][0], bl[nf][1]);
                    MMA16816(acc[mf][nf], al[mf][0], al[mf][1], al[mf][2], al[mf][3],
                             bh[nf][0], bh[nf][1]);
                }
        }
        __syncthreads();
    }

#pragma unroll
    for (int mf = 0; mf < 2; mf++) {
        int row = wm * 32 + mf * 16 + (lane >> 2);
        float bv0 = bias[row], bv1 = bias[row + 8];
        float* op0 = out + (size_t)b * ((size_t)C8 * HWV) + (size_t)row * HWV
                   + n0 + wn * 32 + (lane & 3) * 2;
        float* op1 = op0 + (size_t)8 * HWV;
#pragma unroll
        for (int nf = 0; nf < 4; nf++) {
            *(float2*)(op0 + nf * 8) = make_float2(acc[mf][nf][0] + bv0, acc[mf][nf][1] + bv0);
            *(float2*)(op1 + nf * 8) = make_float2(acc[mf][nf][2] + bv1, acc[mf][nf][3] + bv1);
        }
    }
}

// ---------------- gemmv (fused conversion, single-term, fp16 out) -----------
#define GV_A    0                        // buf*10240, pitch 80 (128 rows)
#define GV_STG  20480                    // buf*16384
#define GV_BH   53248
#define GV_SM   61952

__global__ void __launch_bounds__(256, 1) gemmv_mma_kernel(
    __half* __restrict__ out,
    const __half* __restrict__ Ah, const float* __restrict__ X,
    const float* __restrict__ bias)
{
    extern __shared__ char smem[];
    uint32_t sbase = smem_u32(smem);
    int tid = threadIdx.x, wid = tid >> 5, lane = tid & 31;
    int m0 = blockIdx.x * 128, n0 = blockIdx.y * 128, b = blockIdx.z;
    int wm = wid & 3, wn = wid >> 2;

    const __half* Ahb = Ah + (size_t)m0 * CCH;
    const float* Xb = X + (size_t)b * CCH * HWV + n0;

    float acc[2][8][4];
#pragma unroll
    for (int i = 0; i < 2; i++)
#pragma unroll
        for (int j = 0; j < 8; j++)
#pragma unroll
            for (int k = 0; k < 4; k++) acc[i][j][k] = 0.f;

    int lg = lane >> 3, lr = lane & 7;

    auto issue = [&](int c, int buf) {
        int kc0 = c * 32;
        // A: 128 rows x 4 segs = 512
#pragma unroll
        for (int i = 0; i < 2; i++) {
            int idx = i * 256 + tid;
            int r = idx >> 2, seg = idx & 3;
            const __half* src = Ahb + (size_t)r * CCH + kc0 + seg * 8;
            uint32_t dst = sbase + GV_A + buf * 10240 + r * LDR + seg * 16;
            CP_ASYNC16(dst, src);
        }
        // B staging fp32: 32 rows x 32 segs
#pragma unroll
        for (int i = 0; i < 4; i++) {
            int idx = i * 256 + tid;
            int r = idx >> 5, seg = idx & 31;
            const float* src = Xb + (size_t)(kc0 + r) * HWV + seg * 4;
            uint32_t dst = sbase + GV_STG + buf * 16384 + r * 512 + seg * 16;
            CP_ASYNC16(dst, src);
        }
        CP_COMMIT();
    };

    issue(0, 0);
    for (int c = 0; c < 16; c++) {
        int buf = c & 1;
        if (c < 15) { issue(c + 1, buf ^ 1); CP_WAIT1(); } else { CP_WAIT0(); }
        __syncthreads();
        {
            const char* stg = smem + GV_STG + buf * 16384;
#pragma unroll
            for (int i = 0; i < 4; i++) {
                int idx = i * 256 + tid;
                int r = idx >> 5, cc = idx & 31;
                float4 f = *(const float4*)(stg + r * 512 + cc * 16);
                uint2 hv = make_uint2(
                    pkh(__float2half_rn(f.x), __float2half_rn(f.y)),
                    pkh(__float2half_rn(f.z), __float2half_rn(f.w)));
                *(uint2*)(smem + GV_BH + r * LDB + cc * 8) = hv;
            }
        }
        __syncthreads();
        uint32_t sA = sbase + GV_A + buf * 10240;
        uint32_t sBH = sbase + GV_BH;
#pragma unroll
        for (int ks = 0; ks < 2; ks++) {
            uint32_t ah[2][4];
#pragma unroll
            for (int mf = 0; mf < 2; mf++) {
                uint32_t roff = (wm * 32 + mf * 16 + lr + (lg & 1) * 8) * LDR
                              + (ks * 16 + (lg >> 1) * 8) * 2;
                LDMATRIX_X4(ah[mf][0], ah[mf][1], ah[mf][2], ah[mf][3], sA + roff);
            }
            uint32_t trow = ks * 16 + ((lane >> 3) & 1) * 8 + (lane & 7);
            uint32_t bh[8][2];
#pragma unroll
            for (int np = 0; np < 4; np++) {
                uint32_t tcol = wn * 64 + np * 16 + (lane >> 4) * 8;
                uint32_t r0, r1, r2, r3;
                LDMATRIX_X4_T(r0, r1, r2, r3, sBH + trow * LDB + tcol * 2);
                bh[np * 2][0] = r0; bh[np * 2][1] = r1;
                bh[np * 2 + 1][0] = r2; bh[np * 2 + 1][1] = r3;
            }
#pragma unroll
            for (int mf = 0; mf < 2; mf++)
#pragma unroll
                for (int nf = 0; nf < 8; nf++)
                    MMA16816(acc[mf][nf], ah[mf][0], ah[mf][1], ah[mf][2], ah[mf][3],
                             bh[nf][0], bh[nf][1]);
        }
        __syncthreads();
    }

#pragma unroll
    for (int mf = 0; mf < 2; mf++) {
        int row = m0 + wm * 32 + mf * 16 + (lane >> 2);
        float bv0 = bias[row], bv1 = bias[row + 8];
        __half* op0 = out + (size_t)b * ((size_t)CCH * HWV) + (size_t)row * HWV
                    + n0 + wn * 64 + (lane & 3) * 2;
        __half* op1 = op0 + (size_t)8 * HWV;
#pragma unroll
        for (int nf = 0; nf < 8; nf++) {
            *(__half2*)(op0 + nf * 8) = __floats2half2_rn(acc[mf][nf][0] + bv0, acc[mf][nf][1] + bv0);
            *(__half2*)(op1 + nf * 8) = __floats2half2_rn(acc[mf][nf][2] + bv1, acc[mf][nf][3] + bv1);
        }
    }
}

// ---------------- attention output GEMM (fp16 mma, fp16 out) ----------------
#define LDT 272

__global__ void __launch_bounds__(256) attn_out_kernel(
    __half* __restrict__ out,
    const __half* __restrict__ A, size_t aRow, size_t ASf, size_t ASb,
    const __half* __restrict__ Bm)
{
    extern __shared__ char smem[];
    uint32_t sA = smem_u32(smem);
    uint32_t sB = sA + 128 * LDT;
    int tid = threadIdx.x, wid = tid >> 5, lane = tid & 31;
    int ct = blockIdx.x, f = blockIdx.y, b = blockIdx.z;
    int wm = wid & 3, wn = wid >> 2;

    const __half* Ac = A + (size_t)b * ASb + (size_t)f * ASf + (size_t)ct * 128 * aRow;
    const __half* Bc = Bm + ((size_t)b * 128 + f) * 16384;

#pragma unroll
    for (int i = 0; i < 8; i++) {
        int idx = i * 256 + tid;
        int r = idx >> 4, seg = idx & 15;
        CP_ASYNC16(sA + r * LDT + seg * 16, Ac + (size_t)r * aRow + seg * 8);
    }
#pragma unroll
    for (int i = 0; i < 8; i++) {
        int idx = i * 256 + tid;
        int r = idx >> 4, seg = idx & 15;
        CP_ASYNC16(sB + r * LDT + seg * 16, Bc + (size_t)r * 128 + seg * 8);
    }
    CP_COMMIT(); CP_WAIT0();
    __syncthreads();

    float acc[2][8][4];
#pragma unroll
    for (int i = 0; i < 2; i++)
#pragma unroll
        for (int j = 0; j < 8; j++)
#pragma unroll
            for (int k = 0; k < 4; k++) acc[i][j][k] = 0.f;

    int lg = lane >> 3, lr = lane & 7;
#pragma unroll
    for (int kk = 0; kk < 8; kk++) {
        uint32_t a[2][4];
#pragma unroll
        for (int mf = 0; mf < 2; mf++) {
            uint32_t roff = (wm * 32 + mf * 16 + lr + (lg & 1) * 8) * LDT
                          + (kk * 16 + (lg >> 1) * 8) * 2;
            LDMATRIX_X4(a[mf][0], a[mf][1], a[mf][2], a[mf][3], sA + roff);
        }
        uint32_t bf[8][2];
#pragma unroll
        for (int np = 0; np < 4; np++) {
            uint32_t roff = (wn * 64 + np * 16 + (lg >> 1) * 8 + lr) * LDT
                          + (kk * 16 + (lg & 1) * 8) * 2;
            uint32_t r0, r1, r2, r3;
            LDMATRIX_X4(r0, r1, r2, r3, sB + roff);
            bf[np * 2][0] = r0; bf[np * 2][1] = r1;
            bf[np * 2 + 1][0] = r2; bf[np * 2 + 1][1] = r3;
        }
#pragma unroll
        for (int mf = 0; mf < 2; mf++)
#pragma unroll
            for (int nf = 0; nf < 8; nf++)
                MMA16816(acc[mf][nf], a[mf][0], a[mf][1], a[mf][2], a[mf][3],
                         bf[nf][0], bf[nf][1]);
    }

    __half* oc = out + (size_t)b * ((size_t)CCH * HWV) + (size_t)f * 128
               + (size_t)ct * 128 * HWV;
#pragma unroll
    for (int mf = 0; mf < 2; mf++) {
        int row = wm * 32 + mf * 16 + (lane >> 2);
        __half* op0 = oc + (size_t)row * HWV + wn * 64 + (lane & 3) * 2;
        __half* op1 = op0 + (size_t)8 * HWV;
#pragma unroll
        for (int nf = 0; nf < 8; nf++) {
            *(__half2*)(op0 + nf * 8) = __floats2half2_rn(acc[mf][nf][0], acc[mf][nf][1]);
            *(__half2*)(op1 + nf * 8) = __floats2half2_rn(acc[mf][nf][2], acc[mf][nf][3]);
        }
    }
}

// ---------------- transpose fp32 ---------------------------------------------
__global__ void transpose_hw_kernel(float* __restrict__ dst,
                                    const float* __restrict__ src,
                                    int planes, size_t srcBatchStride) {
    __shared__ float tile[32][33];
    int p = blockIdx.z;
    int b = p / planes, c = p % planes;
    int w0 = blockIdx.x * 32, h0 = blockIdx.y * 32;
    int tx = threadIdx.x, ty = threadIdx.y;
    const float* s = src + (size_t)b * srcBatchStride + (size_t)c * HWV;
#pragma unroll
    for (int r = 0; r < 4; r++) {
        int h = h0 + ty + r * 8;
        tile[ty + r * 8][tx] = s[(size_t)h * WW + w0 + tx];
    }
    __syncthreads();
#pragma unroll
    for (int r = 0; r < 4; r++) {
        int w = w0 + ty + r * 8;
        dst[(((size_t)b * WW + w) * planes + c) * HH + h0 + tx] = tile[tx][ty + r * 8];
    }
}

// ---------------- transpose fp16: g_vh -> g_vTh -----------------------------
__global__ void transpose_hw_half_kernel() {
    __shared__ __half tile[32][36];
    int p = blockIdx.z;
    int b = p >> 9, c = p & 511;
    int w0 = blockIdx.x * 32, h0 = blockIdx.y * 32;
    int tx = threadIdx.x, ty = threadIdx.y;
    const __half* s = g_vh + ((size_t)b * CCH + c) * HWV;
#pragma unroll
    for (int r = 0; r < 4; r++) {
        int h = h0 + ty + r * 8;
        tile[ty + r * 8][tx] = s[(size_t)h * WW + w0 + tx];
    }
    __syncthreads();
#pragma unroll
    for (int r = 0; r < 4; r++) {
        int w = w0 + ty + r * 8;
        g_vTh[(((size_t)b * WW + w) * CCH + c) * HH + h0 + tx] = tile[tx][ty + r * 8];
    }
}

// ---------------- energy_H ---------------------------------------------------
__global__ void energy_h_kernel() {
    __shared__ float As[16][128];
    __shared__ float Bs[16][128];
    int w = blockIdx.x, b = blockIdx.y;
    int tid = threadIdx.x;
    int tx = tid & 15, ty = tid >> 4;
    int m0 = ty * 8, n0 = tx * 8;
    const float* qT = g_qT + ((size_t)(b * WW + w)) * C8 * HH;
    const float* kT = g_kT + ((size_t)(b * WW + w)) * C8 * HH;
    float acc[8][8];
#pragma unroll
    for (int i = 0; i < 8; i++)
#pragma unroll
        for (int j = 0; j < 8; j++) acc[i][j] = 0.f;

    for (int k0 = 0; k0 < C8; k0 += 16) {
#pragma unroll
        for (int i = 0; i < 8; i++) {
            int idx = tid + i * 256;
            int cc = idx >> 7, hh = idx & 127;
            As[cc][hh] = qT[(k0 + cc) * HH + hh];
            Bs[cc][hh] = kT[(k0 + cc) * HH + hh];
        }
        __syncthreads();
#pragma unroll
        for (int kk = 0; kk < 16; kk++) {
            float a[8], bb[8];
            *(float4*)&a[0]  = *(const float4*)&As[kk][m0];
            *(float4*)&a[4]  = *(const float4*)&As[kk][m0 + 4];
            *(float4*)&bb[0] = *(const float4*)&Bs[kk][n0];
            *(float4*)&bb[4] = *(const float4*)&Bs[kk][n0 + 4];
#pragma unroll
            for (int i = 0; i < 8; i++)
#pragma unroll
                for (int j = 0; j < 8; j++) acc[i][j] += a[i] * bb[j];
        }
        __syncthreads();
    }
#pragma unroll
    for (int i = 0; i < 8; i++) {
        int h = m0 + i;
        float* row = g_att + (((size_t)b * HH + h) * WW + w) * 256;
#pragma unroll
        for (int j = 0; j < 8; j++) {
            int jj = n0 + j;
            row[jj] = (jj == h) ? -CUDART_INF_F : acc[i][j];
        }
    }
}

// ---------------- energy_W ---------------------------------------------------
__global__ void energy_w_kernel() {
    __shared__ float As[16][128];
    __shared__ float Bs[16][128];
    int h = blockIdx.x, b = blockIdx.y;
    int tid = threadIdx.x;
    int tx = tid & 15, ty = tid >> 4;
    int m0 = ty * 8, n0 = tx * 8;
    const float* qp = g_q + (size_t)b * C8 * HWV + (size_t)h * WW;
    const float* kp = g_k + (size_t)b * C8 * HWV + (size_t)h * WW;
    float acc[8][8];
#pragma unroll
    for (int i = 0; i < 8; i++)
#pragma unroll
        for (int j = 0; j < 8; j++) acc[i][j] = 0.f;

    for (int k0 = 0; k0 < C8; k0 += 16) {
#pragma unroll
        for (int i = 0; i < 8; i++) {
            int idx = tid + i * 256;
            int cc = idx >> 7, nn = idx & 127;
            As[cc][nn] = qp[(size_t)(k0 + cc) * HWV + nn];
            Bs[cc][nn] = kp[(size_t)(k0 + cc) * HWV + nn];
        }
        __syncthreads();
#pragma unroll
        for (int kk = 0; kk < 16; kk++) {
            float a[8], bb[8];
            *(float4*)&a[0]  = *(const float4*)&As[kk][m0];
            *(float4*)&a[4]  = *(const float4*)&As[kk][m0 + 4];
            *(float4*)&bb[0] = *(const float4*)&Bs[kk][n0];
            *(float4*)&bb[4] = *(const float4*)&Bs[kk][n0 + 4];
#pragma unroll
            for (int i = 0; i < 8; i++)
#pragma unroll
                for (int j = 0; j < 8; j++) acc[i][j] += a[i] * bb[j];
        }
        __syncthreads();
    }
#pragma unroll
    for (int i = 0; i < 8; i++) {
        int wv = m0 + i;
        float* row = g_att + (((size_t)b * HH + h) * WW + wv) * 256 + 128;
#pragma unroll
        for (int j = 0; j < 8; j++) row[n0 + j] = acc[i][j];
    }
}

// ---------------- softmax -> fp16 att ---------------------------------------
__global__ void softmax_kernel() {
    int row  = blockIdx.x * 8 + (threadIdx.x >> 5);
    int lane = threadIdx.x & 31;
    const float* p = g_att + (size_t)row * 256;
    int b = row >> 14, h = (row >> 7) & 127, w = row & 127;
    float v[8];
    float m = -CUDART_INF_F;
#pragma unroll
    for (int i = 0; i < 8; i++) { v[i] = p[lane + 32 * i]; m = fmaxf(m, v[i]); }
#pragma unroll
    for (int o = 16; o > 0; o >>= 1) m = fmaxf(m, __shfl_xor_sync(0xffffffffu, m, o));
    float s = 0.f;
#pragma unroll
    for (int i = 0; i < 8; i++) { v[i] = __expf(v[i] - m); s += v[i]; }
#pragma unroll
    for (int o = 16; o > 0; o >>= 1) s += __shfl_xor_sync(0xffffffffu, s, o);
    float inv = 1.0f / s;
    __half* pH = g_attH + (((size_t)b * WW + w) * HH + h) * 128;
    __half* pW = g_attW + (size_t)row * 128;
#pragma unroll
    for (int i = 0; i < 4; i++) pH[lane + 32 * i] = __float2half(v[i] * inv);
#pragma unroll
    for (int i = 4; i < 8; i++) pW[lane + 32 * (i - 4)] = __float2half(v[i] * inv);
}

// ---------------- combine ----------------------------------------------------
__global__ void combine_kernel(float* __restrict__ out,
                               const float* __restrict__ xe,
                               const float* __restrict__ xq,
                               const float* __restrict__ g1p,
                               const float* __restrict__ g2p) {
    __shared__ __half tile[32][36];
    int bc = blockIdx.z;
    int w0 = blockIdx.x * 32, h0 = blockIdx.y * 32;
    int tx = threadIdx.x, ty = threadIdx.y;
    size_t base = (size_t)bc * HWV;
#pragma unroll
    for (int r = 0; r < 4; r++) {
        int wv = w0 + ty + r * 8;
        tile[ty + r * 8][tx] = g_s1h[base + (size_t)wv * HH + h0 + tx];
    }
    __syncthreads();
    float gam1 = g1p[0], gam2 = g2p[0];
#pragma unroll
    for (int r = 0; r < 4; r++) {
        int h = h0 + ty + r * 8;
        int wv = w0 + tx;
        size_t idx = base + (size_t)h * WW + wv;
        float t = __half2float(tile[tx][ty + r * 8]) + __half2float(g_s2h[idx]) + 2.0f;
        out[idx]        = fmaf(gam1, t, xe[idx]);
        out[NTOT + idx] = fmaf(gam2, t, xq[idx]);
    }
}

// ---------------- launch ------------------------------------------------------
extern "C" void kernel_launch(void* const* d_in, const int* in_sizes, int n_in,
                              void* d_out, int out_size) {
    const float* xe = (const float*)d_in[0];
    const float* xq = (const float*)d_in[1];
    const float* Wq = (const float*)d_in[2];
    const float* bq = (const float*)d_in[3];
    const float* Wk = (const float*)d_in[4];
    const float* bk = (const float*)d_in[5];
    const float* Wv = (const float*)d_in[6];
    const float* bv = (const float*)d_in[7];
    const float* g1 = (const float*)d_in[8];
    const float* g2 = (const float*)d_in[9];
    float* out = (float*)d_out;

    float *pq, *pk, *pqT, *pkT;
    __half *pwqkh, *pwqkl, *pwvh, *pvh, *pvTh, *pattH, *pattW, *ps1h, *ps2h;
    cudaGetSymbolAddress((void**)&pq,   g_q);
    cudaGetSymbolAddress((void**)&pk,   g_k);
    cudaGetSymbolAddress((void**)&pqT,  g_qT);
    cudaGetSymbolAddress((void**)&pkT,  g_kT);
    cudaGetSymbolAddress((void**)&pwqkh, g_wqkh);
    cudaGetSymbolAddress((void**)&pwqkl, g_wqkl);
    cudaGetSymbolAddress((void**)&pwvh, g_wvh);
    cudaGetSymbolAddress((void**)&pvh,  g_vh);
    cudaGetSymbolAddress((void**)&pvTh, g_vTh);
    cudaGetSymbolAddress((void**)&pattH, g_attH);
    cudaGetSymbolAddress((void**)&pattW, g_attW);
    cudaGetSymbolAddress((void**)&ps1h, g_s1h);
    cudaGetSymbolAddress((void**)&ps2h, g_s2h);

    cudaFuncSetAttribute(gemm64_mma_kernel,
                         cudaFuncAttributeMaxDynamicSharedMemorySize, G64_SM);
    cudaFuncSetAttribute(gemmv_mma_kernel,
                         cudaFuncAttributeMaxDynamicSharedMemorySize, GV_SM);
    cudaFuncSetAttribute(attn_out_kernel,
                         cudaFuncAttributeMaxDynamicSharedMemorySize, 2 * 128 * LDT);

    // weight prep (tiny)
    split_plain_kernel<<<(64 * CCH + 255) / 256, 256>>>(pwqkh, pwqkl, Wq, 64 * CCH);
    split_plain_kernel<<<(64 * CCH + 255) / 256, 256>>>(pwqkh + 64 * CCH, pwqkl + 64 * CCH, Wk, 64 * CCH);
    convert_plain_kernel<<<(CCH * CCH + 255) / 256, 256>>>(pwvh, Wv, CCH * CCH);

    // projections (fused fp32->fp16 conversion inside)
    gemm64_mma_kernel<<<dim3(HWV / 128, 1, BB), 256, G64_SM>>>(
        pq, pwqkh, pwqkl, xq, bq);
    gemm64_mma_kernel<<<dim3(HWV / 128, 1, BB), 256, G64_SM>>>(
        pk, pwqkh + 64 * CCH, pwqkl + 64 * CCH, xe, bk);
    gemmv_mma_kernel<<<dim3(CCH / 128, HWV / 128, BB), 256, GV_SM>>>(
        pvh, pwvh, xe, bv);

    // transposes
    transpose_hw_kernel<<<dim3(4, 4, BB * C8), dim3(32, 8)>>>(pqT, pq, C8, (size_t)C8 * HWV);
    transpose_hw_kernel<<<dim3(4, 4, BB * C8), dim3(32, 8)>>>(pkT, pk, C8, (size_t)C8 * HWV);
    transpose_hw_half_kernel<<<dim3(4, 4, BB * CCH), dim3(32, 8)>>>();

    // energies + softmax
    energy_h_kernel<<<dim3(WW, BB), 256>>>();
    energy_w_kernel<<<dim3(HH, BB), 256>>>();
    softmax_kernel<<<(BB * HH * WW) / 8, 256>>>();

    // attention outputs
    attn_out_kernel<<<dim3(CCH / 128, WW, BB), 256, 2 * 128 * LDT>>>(
        ps1h, pvTh, 128, (size_t)CCH * 128, (size_t)WW * CCH * 128, pattH);
    attn_out_kernel<<<dim3(CCH / 128, HH, BB), 256, 2 * 128 * LDT>>>(
        ps2h, pvh, HWV, 128, (size_t)CCH * HWV, pattW);

    // combine
    combine_kernel<<<dim3(4, 4, BB * CCH), dim3(32, 8)>>>(out, xe, xq, g1, g2);
}

// round 8
// speedup vs baseline: 4.0692x; 1.0986x over previous
#include <cuda_runtime.h>
#include <cuda_fp16.h>
#include <math_constants.h>
#include <cstdint>
#include <cstddef>

#define BB 4
#define CCH 512
#define C8 64
#define HH 128
#define WW 128
#define HWV (HH*WW)

static const size_t NTOT = (size_t)BB * CCH * HWV;

// ---------------- scratch ----------------------------------------------------
__device__ __align__(16) __half g_q16 [BB*C8*HWV];          // [b][c][hw]
__device__ __align__(16) __half g_k16 [BB*C8*HWV];
__device__ __align__(16) __half g_qT16[BB*C8*HWV];          // [b][w][c][h]
__device__ __align__(16) __half g_kT16[BB*C8*HWV];
__device__ __align__(16) __half g_vh  [(size_t)BB*CCH*HWV]; // [b][c][h][w]
__device__ __align__(16) __half g_vTh [(size_t)BB*CCH*HWV]; // [b][w][c][h]
__device__ __align__(16) __half g_eH  [(size_t)BB*HWV*HH];  // [b][w][h][j] raw energy
__device__ __align__(16) __half g_eW  [(size_t)BB*HWV*WW];  // [b][h][w][j]
__device__ __align__(16) __half g_s1h [(size_t)BB*CCH*HWV]; // out_H [b][c][w][h]
__device__ __align__(16) __half g_s2h [(size_t)BB*CCH*HWV]; // out_W [b][c][h][w]
__device__ __align__(16) float2 g_stats[(size_t)BB*HWV];    // (max, 1/sum)
__device__ __align__(16) __half g_wq16[C8*CCH];
__device__ __align__(16) __half g_wvk [640*CCH];            // rows 0-511 Wv, 512-575 Wk, 576-639 zero
__device__ float g_bvk[640];

// ---------------- PTX helpers ------------------------------------------------
__device__ __forceinline__ uint32_t smem_u32(const void* p) {
    uint32_t a;
    asm("{ .reg .u64 t; cvta.to.shared.u64 t, %1; cvt.u32.u64 %0, t; }" : "=r"(a) : "l"(p));
    return a;
}
__device__ __forceinline__ uint32_t pkh(__half a, __half b) {
    __half2 t = __halves2half2(a, b);
    return *reinterpret_cast<uint32_t*>(&t);
}
#define LDMATRIX_X4(r0,r1,r2,r3,addr) \
    asm volatile("ldmatrix.sync.aligned.m8n8.x4.shared.b16 {%0,%1,%2,%3}, [%4];" \
                 : "=r"(r0),"=r"(r1),"=r"(r2),"=r"(r3) : "r"(addr))
#define LDMATRIX_X4_T(r0,r1,r2,r3,addr) \
    asm volatile("ldmatrix.sync.aligned.m8n8.x4.trans.shared.b16 {%0,%1,%2,%3}, [%4];" \
                 : "=r"(r0),"=r"(r1),"=r"(r2),"=r"(r3) : "r"(addr))
#define MMA16816(d,a0,a1,a2,a3,b0,b1) \
    asm volatile("mma.sync.aligned.m16n8k16.row.col.f32.f16.f16.f32 " \
                 "{%0,%1,%2,%3},{%4,%5,%6,%7},{%8,%9},{%0,%1,%2,%3};" \
                 : "+f"((d)[0]),"+f"((d)[1]),"+f"((d)[2]),"+f"((d)[3]) \
                 : "r"(a0),"r"(a1),"r"(a2),"r"(a3),"r"(b0),"r"(b1))
#define CP_ASYNC16(dst,src) \
    asm volatile("cp.async.cg.shared.global [%0], [%1], 16;" :: "r"(dst),"l"(src))
#define CP_COMMIT() asm volatile("cp.async.commit_group;" ::: "memory")
#define CP_WAIT1()  asm volatile("cp.async.wait_group 1;" ::: "memory")
#define CP_WAIT0()  asm volatile("cp.async.wait_group 0;" ::: "memory")

#define LDR 80
#define LDB 272
#define LDT 272

// ---------------- weight/bias prep -------------------------------------------
__global__ void convert_plain_kernel(__half* __restrict__ o,
                                     const float* __restrict__ s, int n) {
    int i = blockIdx.x * 256 + threadIdx.x;
    if (i < n) o[i] = __float2half_rn(s[i]);
}
__global__ void zero_half_kernel(__half* __restrict__ o, int n) {
    int i = blockIdx.x * 256 + threadIdx.x;
    if (i < n) o[i] = __float2half(0.f);
}
__global__ void fill_bvk_kernel(float* __restrict__ dst,
                                const float* __restrict__ bv,
                                const float* __restrict__ bk) {
    int i = blockIdx.x * 256 + threadIdx.x;
    if (i < 512) dst[i] = bv[i];
    else if (i < 576) dst[i] = bk[i - 512];
    else if (i < 640) dst[i] = 0.f;
}

// ---------------- gemmQ: q16[b][m<64][n] = bq[m] + Wq·x, single fp16 term ---
#define GQ_A    0          // 2 x 5120
#define GQ_STG  10240      // 2 x 16384
#define GQ_BH   43008      // 8704
#define GQ_SM   51712

__global__ void __launch_bounds__(256, 1) gemmq_mma_kernel(
    __half* __restrict__ out, const __half* __restrict__ Aw,
    const float* __restrict__ X, const float* __restrict__ bias)
{
    extern __shared__ char smem[];
    uint32_t sbase = smem_u32(smem);
    int tid = threadIdx.x, wid = tid >> 5, lane = tid & 31;
    int n0 = blockIdx.x * 128, b = blockIdx.z;
    int wm = wid & 1, wn = wid >> 1;
    const float* Xb = X + (size_t)b * CCH * HWV + n0;

    float acc[2][4][4];
#pragma unroll
    for (int i = 0; i < 2; i++)
#pragma unroll
        for (int j = 0; j < 4; j++)
#pragma unroll
            for (int k = 0; k < 4; k++) acc[i][j][k] = 0.f;

    int lg = lane >> 3, lr = lane & 7;

    auto issue = [&](int c, int buf) {
        int kc0 = c * 32;
        { // A: 64 rows x 4 segs
            int r = tid >> 2, seg = tid & 3;
            CP_ASYNC16(sbase + GQ_A + buf * 5120 + r * LDR + seg * 16,
                       Aw + (size_t)r * CCH + kc0 + seg * 8);
        }
#pragma unroll
        for (int i = 0; i < 4; i++) {
            int idx = i * 256 + tid;
            int r = idx >> 5, seg = idx & 31;
            CP_ASYNC16(sbase + GQ_STG + buf * 16384 + r * 512 + seg * 16,
                       Xb + (size_t)(kc0 + r) * HWV + seg * 4);
        }
        CP_COMMIT();
    };

    issue(0, 0);
    for (int c = 0; c < 16; c++) {
        int buf = c & 1;
        if (c < 15) { issue(c + 1, buf ^ 1); CP_WAIT1(); } else { CP_WAIT0(); }
        __syncthreads();
        {
            const char* stg = smem + GQ_STG + buf * 16384;
#pragma unroll
            for (int i = 0; i < 4; i++) {
                int idx = i * 256 + tid;
                int r = idx >> 5, cc = idx & 31;
                float4 f = *(const float4*)(stg + r * 512 + cc * 16);
                uint2 hv = make_uint2(
                    pkh(__float2half_rn(f.x), __float2half_rn(f.y)),
                    pkh(__float2half_rn(f.z), __float2half_rn(f.w)));
                *(uint2*)(smem + GQ_BH + r * LDB + cc * 8) = hv;
            }
        }
        __syncthreads();
        uint32_t sA = sbase + GQ_A + buf * 5120;
        uint32_t sBH = sbase + GQ_BH;
#pragma unroll
        for (int ks = 0; ks < 2; ks++) {
            uint32_t ah[2][4];
#pragma unroll
            for (int mf = 0; mf < 2; mf++) {
                uint32_t roff = (wm * 32 + mf * 16 + lr + (lg & 1) * 8) * LDR
                              + (ks * 16 + (lg >> 1) * 8) * 2;
                LDMATRIX_X4(ah[mf][0], ah[mf][1], ah[mf][2], ah[mf][3], sA + roff);
            }
            uint32_t trow = ks * 16 + ((lane >> 3) & 1) * 8 + lr;
            uint32_t bh[4][2];
#pragma unroll
            for (int np = 0; np < 2; np++) {
                uint32_t tcol = wn * 32 + np * 16 + ((lane >> 4) & 1) * 8;
                uint32_t r0, r1, r2, r3;
                LDMATRIX_X4_T(r0, r1, r2, r3, sBH + trow * LDB + tcol * 2);
                bh[np * 2][0] = r0; bh[np * 2][1] = r1;
                bh[np * 2 + 1][0] = r2; bh[np * 2 + 1][1] = r3;
            }
#pragma unroll
            for (int mf = 0; mf < 2; mf++)
#pragma unroll
                for (int nf = 0; nf < 4; nf++)
                    MMA16816(acc[mf][nf], ah[mf][0], ah[mf][1], ah[mf][2], ah[mf][3],
                             bh[nf][0], bh[nf][1]);
        }
        __syncthreads();
    }
#pragma unroll
    for (int mf = 0; mf < 2; mf++) {
        int row = wm * 32 + mf * 16 + (lane >> 2);
        float bv0 = bias[row], bv1 = bias[row + 8];
        __half* op0 = out + (size_t)b * C8 * HWV + (size_t)row * HWV
                    + n0 + wn * 32 + (lane & 3) * 2;
        __half* op1 = op0 + (size_t)8 * HWV;
#pragma unroll
        for (int nf = 0; nf < 4; nf++) {
            *(__half2*)(op0 + nf * 8) = __floats2half2_rn(acc[mf][nf][0] + bv0, acc[mf][nf][1] + bv0);
            *(__half2*)(op1 + nf * 8) = __floats2half2_rn(acc[mf][nf][2] + bv1, acc[mf][nf][3] + bv1);
        }
    }
}

// ---------------- gemmVK: [Wv;Wk]·xe, M tiles 128 (grid x 5) ------------------
#define GV_A    0
#define GV_STG  20480
#define GV_BH   53248
#define GV_SM   61952

__global__ void __launch_bounds__(256, 1) gemmvk_mma_kernel(
    __half* __restrict__ outV, __half* __restrict__ outK,
    const __half* __restrict__ Aw, const float* __restrict__ X,
    const float* __restrict__ bias)
{
    extern __shared__ char smem[];
    uint32_t sbase = smem_u32(smem);
    int tid = threadIdx.x, wid = tid >> 5, lane = tid & 31;
    int m0 = blockIdx.x * 128, n0 = blockIdx.y * 128, b = blockIdx.z;
    int wm = wid & 3, wn = wid >> 2;

    const __half* Ahb = Aw + (size_t)m0 * CCH;
    const float* Xb = X + (size_t)b * CCH * HWV + n0;

    float acc[2][8][4];
#pragma unroll
    for (int i = 0; i < 2; i++)
#pragma unroll
        for (int j = 0; j < 8; j++)
#pragma unroll
            for (int k = 0; k < 4; k++) acc[i][j][k] = 0.f;

    int lg = lane >> 3, lr = lane & 7;

    auto issue = [&](int c, int buf) {
        int kc0 = c * 32;
#pragma unroll
        for (int i = 0; i < 2; i++) {
            int idx = i * 256 + tid;
            int r = idx >> 2, seg = idx & 3;
            CP_ASYNC16(sbase + GV_A + buf * 10240 + r * LDR + seg * 16,
                       Ahb + (size_t)r * CCH + kc0 + seg * 8);
        }
#pragma unroll
        for (int i = 0; i < 4; i++) {
            int idx = i * 256 + tid;
            int r = idx >> 5, seg = idx & 31;
            CP_ASYNC16(sbase + GV_STG + buf * 16384 + r * 512 + seg * 16,
                       Xb + (size_t)(kc0 + r) * HWV + seg * 4);
        }
        CP_COMMIT();
    };

    issue(0, 0);
    for (int c = 0; c < 16; c++) {
        int buf = c & 1;
        if (c < 15) { issue(c + 1, buf ^ 1); CP_WAIT1(); } else { CP_WAIT0(); }
        __syncthreads();
        {
            const char* stg = smem + GV_STG + buf * 16384;
#pragma unroll
            for (int i = 0; i < 4; i++) {
                int idx = i * 256 + tid;
                int r = idx >> 5, cc = idx & 31;
                float4 f = *(const float4*)(stg + r * 512 + cc * 16);
                uint2 hv = make_uint2(
                    pkh(__float2half_rn(f.x), __float2half_rn(f.y)),
                    pkh(__float2half_rn(f.z), __float2half_rn(f.w)));
                *(uint2*)(smem + GV_BH + r * LDB + cc * 8) = hv;
            }
        }
        __syncthreads();
        uint32_t sA = sbase + GV_A + buf * 10240;
        uint32_t sBH = sbase + GV_BH;
#pragma unroll
        for (int ks = 0; ks < 2; ks++) {
            uint32_t ah[2][4];
#pragma unroll
            for (int mf = 0; mf < 2; mf++) {
                uint32_t roff = (wm * 32 + mf * 16 + lr + (lg & 1) * 8) * LDR
                              + (ks * 16 + (lg >> 1) * 8) * 2;
                LDMATRIX_X4(ah[mf][0], ah[mf][1], ah[mf][2], ah[mf][3], sA + roff);
            }
            uint32_t trow = ks * 16 + ((lane >> 3) & 1) * 8 + lr;
            uint32_t bh[8][2];
#pragma unroll
            for (int np = 0; np < 4; np++) {
                uint32_t tcol = wn * 64 + np * 16 + ((lane >> 4) & 1) * 8;
                uint32_t r0, r1, r2, r3;
                LDMATRIX_X4_T(r0, r1, r2, r3, sBH + trow * LDB + tcol * 2);
                bh[np * 2][0] = r0; bh[np * 2][1] = r1;
                bh[np * 2 + 1][0] = r2; bh[np * 2 + 1][1] = r3;
            }
#pragma unroll
            for (int mf = 0; mf < 2; mf++)
#pragma unroll
                for (int nf = 0; nf < 8; nf++)
                    MMA16816(acc[mf][nf], ah[mf][0], ah[mf][1], ah[mf][2], ah[mf][3],
                             bh[nf][0], bh[nf][1]);
        }
        __syncthreads();
    }

#pragma unroll
    for (int mf = 0; mf < 2; mf++) {
        int row = m0 + wm * 32 + mf * 16 + (lane >> 2);
        if (row >= 576) continue;
        float bv0 = bias[row], bv1 = bias[row + 8];
        __half* base;
        int r;
        if (row < 512) { base = outV + (size_t)b * CCH * HWV; r = row; }
        else           { base = outK + (size_t)b * C8 * HWV;  r = row - 512; }
        __half* op0 = base + (size_t)r * HWV + n0 + wn * 64 + (lane & 3) * 2;
        __half* op1 = op0 + (size_t)8 * HWV;
#pragma unroll
        for (int nf = 0; nf < 8; nf++) {
            *(__half2*)(op0 + nf * 8) = __floats2half2_rn(acc[mf][nf][0] + bv0, acc[mf][nf][1] + bv0);
            *(__half2*)(op1 + nf * 8) = __floats2half2_rn(acc[mf][nf][2] + bv1, acc[mf][nf][3] + bv1);
        }
    }
}

// ---------------- fp16 transpose [b][c][h][w] -> [b][w][c][h] ----------------
__global__ void transpose_hw_half_p(__half* __restrict__ dst,
                                    const __half* __restrict__ src, int planes) {
    __shared__ __half tile[32][36];
    int p = blockIdx.z;
    int b = p / planes, c = p % planes;
    int w0 = blockIdx.x * 32, h0 = blockIdx.y * 32;
    int tx = threadIdx.x, ty = threadIdx.y;
    const __half* s = src + ((size_t)b * planes + c) * HWV;
#pragma unroll
    for (int r = 0; r < 4; r++) {
        int h = h0 + ty + r * 8;
        tile[ty + r * 8][tx] = s[(size_t)h * WW + w0 + tx];
    }
    __syncthreads();
#pragma unroll
    for (int r = 0; r < 4; r++) {
        int w = w0 + ty + r * 8;
        dst[(((size_t)b * WW + w) * planes + c) * HH + h0 + tx] = tile[tx][ty + r * 8];
    }
}

// ---------------- energy kernels (tensor core, trans-A/B) --------------------
// e[m][n] = sum_c A16[c][m] * B16[c][n]   (K=64)
__global__ void __launch_bounds__(256) energy_h_tc() {
    __shared__ __align__(16) char smh[2 * 64 * LDT];
    uint32_t sA = smem_u32(smh);
    uint32_t sB = sA + 64 * LDT;
    int tid = threadIdx.x, wid = tid >> 5, lane = tid & 31;
    int w = blockIdx.x, b = blockIdx.y;
    int wm = wid & 3, wn = wid >> 2;
    const __half* qt = g_qT16 + ((size_t)(b * WW + w)) * C8 * HH;
    const __half* kt = g_kT16 + ((size_t)(b * WW + w)) * C8 * HH;
#pragma unroll
    for (int i = 0; i < 4; i++) {
        int idx = i * 256 + tid;
        int r = idx >> 4, seg = idx & 15;
        CP_ASYNC16(sA + r * LDT + seg * 16, qt + (size_t)r * HH + seg * 8);
        CP_ASYNC16(sB + r * LDT + seg * 16, kt + (size_t)r * HH + seg * 8);
    }
    CP_COMMIT(); CP_WAIT0();
    __syncthreads();

    float acc[2][8][4];
#pragma unroll
    for (int i = 0; i < 2; i++)
#pragma unroll
        for (int j = 0; j < 8; j++)
#pragma unroll
            for (int k = 0; k < 4; k++) acc[i][j][k] = 0.f;

    int lr = lane & 7;
#pragma unroll
    for (int kk = 0; kk < 4; kk++) {
        uint32_t a[2][4];
#pragma unroll
        for (int mf = 0; mf < 2; mf++) {
            uint32_t krow = kk * 16 + ((lane >> 4) & 1) * 8 + lr;
            uint32_t mcol = wm * 32 + mf * 16 + ((lane >> 3) & 1) * 8;
            LDMATRIX_X4_T(a[mf][0], a[mf][1], a[mf][2], a[mf][3],
                          sA + krow * LDT + mcol * 2);
        }
        uint32_t bf[8][2];
#pragma unroll
        for (int np = 0; np < 4; np++) {
            uint32_t krow = kk * 16 + ((lane >> 3) & 1) * 8 + lr;
            uint32_t ncol = wn * 64 + np * 16 + ((lane >> 4) & 1) * 8;
            uint32_t r0, r1, r2, r3;
            LDMATRIX_X4_T(r0, r1, r2, r3, sB + krow * LDT + ncol * 2);
            bf[np * 2][0] = r0; bf[np * 2][1] = r1;
            bf[np * 2 + 1][0] = r2; bf[np * 2 + 1][1] = r3;
        }
#pragma unroll
        for (int mf = 0; mf < 2; mf++)
#pragma unroll
            for (int nf = 0; nf < 8; nf++)
                MMA16816(acc[mf][nf], a[mf][0], a[mf][1], a[mf][2], a[mf][3],
                         bf[nf][0], bf[nf][1]);
    }
    __half* base = g_eH + (((size_t)b * WW + w) * HH) * 128;
#pragma unroll
    for (int mf = 0; mf < 2; mf++) {
        int h0 = wm * 32 + mf * 16 + (lane >> 2);
        int h1 = h0 + 8;
#pragma unroll
        for (int nf = 0; nf < 8; nf++) {
            int j0 = wn * 64 + nf * 8 + (lane & 3) * 2;
            float v00 = (j0 == h0)     ? -30000.f : acc[mf][nf][0];
            float v01 = (j0 + 1 == h0) ? -30000.f : acc[mf][nf][1];
            float v10 = (j0 == h1)     ? -30000.f : acc[mf][nf][2];
            float v11 = (j0 + 1 == h1) ? -30000.f : acc[mf][nf][3];
            *(__half2*)(base + (size_t)h0 * 128 + j0) = __floats2half2_rn(v00, v01);
            *(__half2*)(base + (size_t)h1 * 128 + j0) = __floats2half2_rn(v10, v11);
        }
    }
}

__global__ void __launch_bounds__(256) energy_w_tc() {
    __shared__ __align__(16) char smh[2 * 64 * LDT];
    uint32_t sA = smem_u32(smh);
    uint32_t sB = sA + 64 * LDT;
    int tid = threadIdx.x, wid = tid >> 5, lane = tid & 31;
    int h = blockIdx.x, b = blockIdx.y;
    int wm = wid & 3, wn = wid >> 2;
    const __half* qp = g_q16 + (size_t)b * C8 * HWV + (size_t)h * WW;
    const __half* kp = g_k16 + (size_t)b * C8 * HWV + (size_t)h * WW;
#pragma unroll
    for (int i = 0; i < 4; i++) {
        int idx = i * 256 + tid;
        int r = idx >> 4, seg = idx & 15;
        CP_ASYNC16(sA + r * LDT + seg * 16, qp + (size_t)r * HWV + seg * 8);
        CP_ASYNC16(sB + r * LDT + seg * 16, kp + (size_t)r * HWV + seg * 8);
    }
    CP_COMMIT(); CP_WAIT0();
    __syncthreads();

    float acc[2][8][4];
#pragma unroll
    for (int i = 0; i < 2; i++)
#pragma unroll
        for (int j = 0; j < 8; j++)
#pragma unroll
            for (int k = 0; k < 4; k++) acc[i][j][k] = 0.f;

    int lr = lane & 7;
#pragma unroll
    for (int kk = 0; kk < 4; kk++) {
        uint32_t a[2][4];
#pragma unroll
        for (int mf = 0; mf < 2; mf++) {
            uint32_t krow = kk * 16 + ((lane >> 4) & 1) * 8 + lr;
            uint32_t mcol = wm * 32 + mf * 16 + ((lane >> 3) & 1) * 8;
            LDMATRIX_X4_T(a[mf][0], a[mf][1], a[mf][2], a[mf][3],
                          sA + krow * LDT + mcol * 2);
        }
        uint32_t bf[8][2];
#pragma unroll
        for (int np = 0; np < 4; np++) {
            uint32_t krow = kk * 16 + ((lane >> 3) & 1) * 8 + lr;
            uint32_t ncol = wn * 64 + np * 16 + ((lane >> 4) & 1) * 8;
            uint32_t r0, r1, r2, r3;
            LDMATRIX_X4_T(r0, r1, r2, r3, sB + krow * LDT + ncol * 2);
            bf[np * 2][0] = r0; bf[np * 2][1] = r1;
            bf[np * 2 + 1][0] = r2; bf[np * 2 + 1][1] = r3;
        }
#pragma unroll
        for (int mf = 0; mf < 2; mf++)
#pragma unroll
            for (int nf = 0; nf < 8; nf++)
                MMA16816(acc[mf][nf], a[mf][0], a[mf][1], a[mf][2], a[mf][3],
                         bf[nf][0], bf[nf][1]);
    }
    __half* base = g_eW + (((size_t)b * HH + h) * WW) * 128;
#pragma unroll
    for (int mf = 0; mf < 2; mf++) {
        int w0 = wm * 32 + mf * 16 + (lane >> 2);
        int w1 = w0 + 8;
#pragma unroll
        for (int nf = 0; nf < 8; nf++) {
            int j0 = wn * 64 + nf * 8 + (lane & 3) * 2;
            *(__half2*)(base + (size_t)w0 * 128 + j0) = __floats2half2_rn(acc[mf][nf][0], acc[mf][nf][1]);
            *(__half2*)(base + (size_t)w1 * 128 + j0) = __floats2half2_rn(acc[mf][nf][2], acc[mf][nf][3]);
        }
    }
}

// ---------------- stats: per softmax-row (b,h,w): max, 1/sum -----------------
__global__ void stats_kernel() {
    int row  = blockIdx.x * 8 + (threadIdx.x >> 5);
    int lane = threadIdx.x & 31;
    int b = row >> 14, h = (row >> 7) & 127, w = row & 127;
    const __half* pH = g_eH + (((size_t)b * WW + w) * HH + h) * 128;
    const __half* pW = g_eW + (size_t)row * 128;
    float v[8];
    float m = -CUDART_INF_F;
#pragma unroll
    for (int i = 0; i < 4; i++) { v[i] = __half2float(pH[lane + 32 * i]); m = fmaxf(m, v[i]); }
#pragma unroll
    for (int i = 4; i < 8; i++) { v[i] = __half2float(pW[lane + 32 * (i - 4)]); m = fmaxf(m, v[i]); }
#pragma unroll
    for (int o = 16; o > 0; o >>= 1) m = fmaxf(m, __shfl_xor_sync(0xffffffffu, m, o));
    float s = 0.f;
#pragma unroll
    for (int i = 0; i < 8; i++) s += __expf(v[i] - m);
#pragma unroll
    for (int o = 16; o > 0; o >>= 1) s += __shfl_xor_sync(0xffffffffu, s, o);
    if (lane == 0) g_stats[row] = make_float2(m, 1.0f / s);
}

// ---------------- attn out (fused softmax-apply, 4 c-tiles per block) --------
#define AT_A   0            // 2 x 34816
#define AT_B   69632        // 34816
#define AT_ST  104448       // 1024
#define AT_SM  105472

__global__ void __launch_bounds__(256, 1) attn_fused_kernel(
    __half* __restrict__ out,
    const __half* __restrict__ A, size_t aF, size_t aRow,
    const __half* __restrict__ Bm, int sOffF, int sStrN)
{
    extern __shared__ char smem[];
    uint32_t sbase = smem_u32(smem);
    float2* sStat = (float2*)(smem + AT_ST);
    int tid = threadIdx.x, wid = tid >> 5, lane = tid & 31;
    int f = blockIdx.x, b = blockIdx.y;
    int wm = wid & 3, wn = wid >> 2;

    const __half* Ab = A + (size_t)b * CCH * HWV + (size_t)f * aF;
    const __half* Bc = Bm + ((size_t)b * 128 + f) * 16384;

    if (tid < 128)
        sStat[tid] = g_stats[(size_t)b * 16384 + (size_t)f * sOffF + (size_t)tid * sStrN];

    auto issueA = [&](int ct, int buf) {
#pragma unroll
        for (int i = 0; i < 8; i++) {
            int idx = i * 256 + tid;
            int r = idx >> 4, seg = idx & 15;
            CP_ASYNC16(sbase + AT_A + buf * 34816 + r * LDT + seg * 16,
                       Ab + (size_t)(ct * 128 + r) * aRow + seg * 8);
        }
    };

    issueA(0, 0);
#pragma unroll
    for (int i = 0; i < 8; i++) {
        int idx = i * 256 + tid;
        int r = idx >> 4, seg = idx & 15;
        CP_ASYNC16(sbase + AT_B + r * LDT + seg * 16, Bc + (size_t)r * 128 + seg * 8);
    }
    CP_COMMIT(); CP_WAIT0();
    __syncthreads();

    // convert B: att = exp(e - m) * inv_s  (in place, fp16)
#pragma unroll
    for (int i = 0; i < 32; i++) {
        int idx = i * 256 + tid;
        int r = idx >> 6, cp2 = idx & 63;
        char* p = smem + AT_B + r * LDT + cp2 * 4;
        __half2 hv = *(__half2*)p;
        float2 st = sStat[r];
        float e0 = __expf(__low2float(hv) - st.x) * st.y;
        float e1 = __expf(__high2float(hv) - st.x) * st.y;
        *(__half2*)p = __floats2half2_rn(e0, e1);
    }
    __syncthreads();

    int lg = lane >> 3, lr = lane & 7;
    uint32_t sB = sbase + AT_B;

    for (int ct = 0; ct < 4; ct++) {
        int buf = ct & 1;
        if (ct < 3) { issueA(ct + 1, buf ^ 1); CP_COMMIT(); }

        float acc[2][8][4];
#pragma unroll
        for (int i = 0; i < 2; i++)
#pragma unroll
            for (int j = 0; j < 8; j++)
#pragma unroll
                for (int k = 0; k < 4; k++) acc[i][j][k] = 0.f;

        uint32_t sA = sbase + AT_A + buf * 34816;
#pragma unroll
        for (int kk = 0; kk < 8; kk++) {
            uint32_t a[2][4];
#pragma unroll
            for (int mf = 0; mf < 2; mf++) {
                uint32_t roff = (wm * 32 + mf * 16 + lr + (lg & 1) * 8) * LDT
                              + (kk * 16 + (lg >> 1) * 8) * 2;
                LDMATRIX_X4(a[mf][0], a[mf][1], a[mf][2], a[mf][3], sA + roff);
            }
            uint32_t bf[8][2];
#pragma unroll
            for (int np = 0; np < 4; np++) {
                uint32_t roff = (wn * 64 + np * 16 + (lg >> 1) * 8 + lr) * LDT
                              + (kk * 16 + (lg & 1) * 8) * 2;
                uint32_t r0, r1, r2, r3;
                LDMATRIX_X4(r0, r1, r2, r3, sB + roff);
                bf[np * 2][0] = r0; bf[np * 2][1] = r1;
                bf[np * 2 + 1][0] = r2; bf[np * 2 + 1][1] = r3;
            }
#pragma unroll
            for (int mf = 0; mf < 2; mf++)
#pragma unroll
                for (int nf = 0; nf < 8; nf++)
                    MMA16816(acc[mf][nf], a[mf][0], a[mf][1], a[mf][2], a[mf][3],
                             bf[nf][0], bf[nf][1]);
        }

        __half* oc = out + (size_t)b * CCH * HWV + (size_t)f * 128
                   + (size_t)ct * 128 * HWV;
#pragma unroll
        for (int mf = 0; mf < 2; mf++) {
            int row = wm * 32 + mf * 16 + (lane >> 2);
            __half* op0 = oc + (size_t)row * HWV + wn * 64 + (lane & 3) * 2;
            __half* op1 = op0 + (size_t)8 * HWV;
#pragma unroll
            for (int nf = 0; nf < 8; nf++) {
                *(__half2*)(op0 + nf * 8) = __floats2half2_rn(acc[mf][nf][0], acc[mf][nf][1]);
                *(__half2*)(op1 + nf * 8) = __floats2half2_rn(acc[mf][nf][2], acc[mf][nf][3]);
            }
        }
        if (ct < 3) CP_WAIT0();
        __syncthreads();
    }
}

// ---------------- combine ----------------------------------------------------
__global__ void combine_kernel(float* __restrict__ out,
                               const float* __restrict__ xe,
                               const float* __restrict__ xq,
                               const float* __restrict__ g1p,
                               const float* __restrict__ g2p) {
    __shared__ __half tile[32][36];
    int bc = blockIdx.z;
    int w0 = blockIdx.x * 32, h0 = blockIdx.y * 32;
    int tx = threadIdx.x, ty = threadIdx.y;
    size_t base = (size_t)bc * HWV;
#pragma unroll
    for (int r = 0; r < 4; r++) {
        int wv = w0 + ty + r * 8;
        tile[ty + r * 8][tx] = g_s1h[base + (size_t)wv * HH + h0 + tx];
    }
    __syncthreads();
    float gam1 = g1p[0], gam2 = g2p[0];
#pragma unroll
    for (int r = 0; r < 4; r++) {
        int h = h0 + ty + r * 8;
        int wv = w0 + tx;
        size_t idx = base + (size_t)h * WW + wv;
        float t = __half2float(tile[tx][ty + r * 8]) + __half2float(g_s2h[idx]) + 2.0f;
        out[idx]        = fmaf(gam1, t, xe[idx]);
        out[NTOT + idx] = fmaf(gam2, t, xq[idx]);
    }
}

// ---------------- launch ------------------------------------------------------
extern "C" void kernel_launch(void* const* d_in, const int* in_sizes, int n_in,
                              void* d_out, int out_size) {
    const float* xe = (const float*)d_in[0];
    const float* xq = (const float*)d_in[1];
    const float* Wq = (const float*)d_in[2];
    const float* bq = (const float*)d_in[3];
    const float* Wk = (const float*)d_in[4];
    const float* bk = (const float*)d_in[5];
    const float* Wv = (const float*)d_in[6];
    const float* bv = (const float*)d_in[7];
    const float* g1 = (const float*)d_in[8];
    const float* g2 = (const float*)d_in[9];
    float* out = (float*)d_out;

    __half *pq16, *pk16, *pqT, *pkT, *pvh, *pvTh, *peH, *peW, *ps1h, *ps2h;
    __half *pwq, *pwvk;
    float* pbvk;
    cudaGetSymbolAddress((void**)&pq16, g_q16);
    cudaGetSymbolAddress((void**)&pk16, g_k16);
    cudaGetSymbolAddress((void**)&pqT,  g_qT16);
    cudaGetSymbolAddress((void**)&pkT,  g_kT16);
    cudaGetSymbolAddress((void**)&pvh,  g_vh);
    cudaGetSymbolAddress((void**)&pvTh, g_vTh);
    cudaGetSymbolAddress((void**)&peH,  g_eH);
    cudaGetSymbolAddress((void**)&peW,  g_eW);
    cudaGetSymbolAddress((void**)&ps1h, g_s1h);
    cudaGetSymbolAddress((void**)&ps2h, g_s2h);
    cudaGetSymbolAddress((void**)&pwq,  g_wq16);
    cudaGetSymbolAddress((void**)&pwvk, g_wvk);
    cudaGetSymbolAddress((void**)&pbvk, g_bvk);

    cudaFuncSetAttribute(gemmq_mma_kernel,
                         cudaFuncAttributeMaxDynamicSharedMemorySize, GQ_SM);
    cudaFuncSetAttribute(gemmvk_mma_kernel,
                         cudaFuncAttributeMaxDynamicSharedMemorySize, GV_SM);
    cudaFuncSetAttribute(attn_fused_kernel,
                         cudaFuncAttributeMaxDynamicSharedMemorySize, AT_SM);

    // weight/bias prep (tiny)
    convert_plain_kernel<<<(C8 * CCH + 255) / 256, 256>>>(pwq, Wq, C8 * CCH);
    convert_plain_kernel<<<(CCH * CCH + 255) / 256, 256>>>(pwvk, Wv, CCH * CCH);
    convert_plain_kernel<<<(C8 * CCH + 255) / 256, 256>>>(pwvk + 512 * CCH, Wk, C8 * CCH);
    zero_half_kernel<<<(64 * CCH + 255) / 256, 256>>>(pwvk + 576 * CCH, 64 * CCH);
    fill_bvk_kernel<<<3, 256>>>(pbvk, bv, bk);

    // projections (single-term fp16, fused conversion)
    gemmq_mma_kernel<<<dim3(HWV / 128, 1, BB), 256, GQ_SM>>>(pq16, pwq, xq, bq);
    gemmvk_mma_kernel<<<dim3(5, HWV / 128, BB), 256, GV_SM>>>(pvh, pk16, pwvk, xe, pbvk);

    // fp16 transposes
    transpose_hw_half_p<<<dim3(4, 4, BB * C8),  dim3(32, 8)>>>(pqT, pq16, C8);
    transpose_hw_half_p<<<dim3(4, 4, BB * C8),  dim3(32, 8)>>>(pkT, pk16, C8);
    transpose_hw_half_p<<<dim3(4, 4, BB * CCH), dim3(32, 8)>>>(pvTh, pvh, CCH);

    // energies on tensor cores (fp16 raw energies in att layouts)
    energy_h_tc<<<dim3(WW, BB), 256>>>();
    energy_w_tc<<<dim3(HH, BB), 256>>>();
    stats_kernel<<<(BB * HH * WW) / 8, 256>>>();

    // attention outputs with fused softmax-apply
    attn_fused_kernel<<<dim3(WW, BB), 256, AT_SM>>>(
        ps1h, pvTh, (size_t)CCH * 128, 128, peH, 1, 128);
    attn_fused_kernel<<<dim3(HH, BB), 256, AT_SM>>>(
        ps2h, pvh, 128, (size_t)HWV, peW, 128, 1);

    // combine
    combine_kernel<<<dim3(4, 4, BB * CCH), dim3(32, 8)>>>(out, xe, xq, g1, g2);
}

// round 9
// speedup vs baseline: 4.1470x; 1.0191x over previous
#include <cuda_runtime.h>
#include <cuda_fp16.h>
#include <math_constants.h>
#include <cstdint>
#include <cstddef>

#define BB 4
#define CCH 512
#define C8 64
#define HH 128
#define WW 128
#define HWV (HH*WW)

static const size_t NTOT = (size_t)BB * CCH * HWV;

// ---------------- scratch ----------------------------------------------------
__device__ __align__(16) __half g_q16 [BB*C8*HWV];          // [b][c][hw]
__device__ __align__(16) __half g_k16 [BB*C8*HWV];
__device__ __align__(16) __half g_qT16[BB*C8*HWV];          // [b][w][c][h]
__device__ __align__(16) __half g_kT16[BB*C8*HWV];
__device__ __align__(16) __half g_vh  [(size_t)BB*CCH*HWV]; // [b][c][h][w]
__device__ __align__(16) __half g_vTh [(size_t)BB*CCH*HWV]; // [b][w][c][h]
__device__ __align__(16) __half g_eH  [(size_t)BB*HWV*HH];  // [b][w][h][j]
__device__ __align__(16) __half g_eW  [(size_t)BB*HWV*WW];  // [b][h][w][j]
__device__ __align__(16) __half g_s1h [(size_t)BB*CCH*HWV]; // [b][c][w][h]
__device__ __align__(16) __half g_s2h [(size_t)BB*CCH*HWV]; // [b][c][h][w]
__device__ __align__(16) float2 g_stats[(size_t)BB*HWV];
__device__ __align__(16) __half g_wq16[C8*CCH];
__device__ __align__(16) __half g_wvk [640*CCH];
__device__ float g_bvk[640];

// ---------------- PTX helpers ------------------------------------------------
__device__ __forceinline__ uint32_t smem_u32(const void* p) {
    uint32_t a;
    asm("{ .reg .u64 t; cvta.to.shared.u64 t, %1; cvt.u32.u64 %0, t; }" : "=r"(a) : "l"(p));
    return a;
}
__device__ __forceinline__ uint32_t pkh(__half a, __half b) {
    __half2 t = __halves2half2(a, b);
    return *reinterpret_cast<uint32_t*>(&t);
}
#define LDMATRIX_X4(r0,r1,r2,r3,addr) \
    asm volatile("ldmatrix.sync.aligned.m8n8.x4.shared.b16 {%0,%1,%2,%3}, [%4];" \
                 : "=r"(r0),"=r"(r1),"=r"(r2),"=r"(r3) : "r"(addr))
#define LDMATRIX_X4_T(r0,r1,r2,r3,addr) \
    asm volatile("ldmatrix.sync.aligned.m8n8.x4.trans.shared.b16 {%0,%1,%2,%3}, [%4];" \
                 : "=r"(r0),"=r"(r1),"=r"(r2),"=r"(r3) : "r"(addr))
#define MMA16816(d,a0,a1,a2,a3,b0,b1) \
    asm volatile("mma.sync.aligned.m16n8k16.row.col.f32.f16.f16.f32 " \
                 "{%0,%1,%2,%3},{%4,%5,%6,%7},{%8,%9},{%0,%1,%2,%3};" \
                 : "+f"((d)[0]),"+f"((d)[1]),"+f"((d)[2]),"+f"((d)[3]) \
                 : "r"(a0),"r"(a1),"r"(a2),"r"(a3),"r"(b0),"r"(b1))
#define CP_ASYNC16(dst,src) \
    asm volatile("cp.async.cg.shared.global [%0], [%1], 16;" :: "r"(dst),"l"(src))
#define CP_COMMIT() asm volatile("cp.async.commit_group;" ::: "memory")
#define CP_WAIT1()  asm volatile("cp.async.wait_group 1;" ::: "memory")
#define CP_WAIT0()  asm volatile("cp.async.wait_group 0;" ::: "memory")

#define LDR 80
#define LDB 272
#define LDT 272

// ---------------- merged weight/bias prep ------------------------------------
__global__ void prep_kernel(const float* __restrict__ Wq,
                            const float* __restrict__ Wv,
                            const float* __restrict__ Wk,
                            const float* __restrict__ bv,
                            const float* __restrict__ bk) {
    int i = blockIdx.x * 256 + threadIdx.x;
    if (i < C8 * CCH) { g_wq16[i] = __float2half_rn(Wq[i]); return; }
    i -= C8 * CCH;
    if (i < CCH * CCH) { g_wvk[i] = __float2half_rn(Wv[i]); return; }
    i -= CCH * CCH;
    if (i < C8 * CCH) { g_wvk[512 * CCH + i] = __float2half_rn(Wk[i]); return; }
    i -= C8 * CCH;
    if (i < C8 * CCH) { g_wvk[576 * CCH + i] = __float2half(0.f); return; }
    i -= C8 * CCH;
    if (i < 640) g_bvk[i] = (i < 512) ? bv[i] : (i < 576 ? bk[i - 512] : 0.f);
}
#define PREP_N (C8*CCH + CCH*CCH + C8*CCH + C8*CCH + 640)

// ---------------- gemmQ: 3-stage pipeline, single sync/chunk -----------------
#define GQ_A    0           // 3 x 5120
#define GQ_STG  15360       // 3 x 16384
#define GQ_BH   64512       // 2 x 8704
#define GQ_SM   81920

__global__ void __launch_bounds__(256, 1) gemmq_mma_kernel(
    __half* __restrict__ out, const __half* __restrict__ Aw,
    const float* __restrict__ X, const float* __restrict__ bias)
{
    extern __shared__ char smem[];
    uint32_t sbase = smem_u32(smem);
    int tid = threadIdx.x, wid = tid >> 5, lane = tid & 31;
    int n0 = blockIdx.x * 128, b = blockIdx.z;
    int wm = wid & 1, wn = wid >> 1;
    const float* Xb = X + (size_t)b * CCH * HWV + n0;

    float acc[2][4][4];
#pragma unroll
    for (int i = 0; i < 2; i++)
#pragma unroll
        for (int j = 0; j < 4; j++)
#pragma unroll
            for (int k = 0; k < 4; k++) acc[i][j][k] = 0.f;

    int lg = lane >> 3, lr = lane & 7;

    auto issue = [&](int c, int sb) {
        int kc0 = c * 32;
        { // A: 64 rows x 4 segs = 256
            int r = tid >> 2, seg = tid & 3;
            CP_ASYNC16(sbase + GQ_A + sb * 5120 + r * LDR + seg * 16,
                       Aw + (size_t)r * CCH + kc0 + seg * 8);
        }
#pragma unroll
        for (int i = 0; i < 4; i++) {
            int idx = i * 256 + tid;
            int r = idx >> 5, seg = idx & 31;
            CP_ASYNC16(sbase + GQ_STG + sb * 16384 + r * 512 + seg * 16,
                       Xb + (size_t)(kc0 + r) * HWV + seg * 4);
        }
        CP_COMMIT();
    };

    issue(0, 0); issue(1, 1);
    for (int c = 0; c < 16; c++) {
        int sb = c % 3, hb = c & 1;
        if (c < 15) CP_WAIT1(); else CP_WAIT0();
        // convert own staged bytes -> BH[hb]
        {
            const char* stg = smem + GQ_STG + sb * 16384;
            char* bh = smem + GQ_BH + hb * 8704;
#pragma unroll
            for (int i = 0; i < 4; i++) {
                int idx = i * 256 + tid;
                int r = idx >> 5, cc = idx & 31;
                float4 f = *(const float4*)(stg + r * 512 + cc * 16);
                uint2 hv = make_uint2(
                    pkh(__float2half_rn(f.x), __float2half_rn(f.y)),
                    pkh(__float2half_rn(f.z), __float2half_rn(f.w)));
                *(uint2*)(bh + r * LDB + cc * 8) = hv;
            }
        }
        __syncthreads();
        if (c < 14) issue(c + 2, (c + 2) % 3);

        uint32_t sA = sbase + GQ_A + sb * 5120;
        uint32_t sBH = sbase + GQ_BH + hb * 8704;
#pragma unroll
        for (int ks = 0; ks < 2; ks++) {
            uint32_t ah[2][4];
#pragma unroll
            for (int mf = 0; mf < 2; mf++) {
                uint32_t roff = (wm * 32 + mf * 16 + lr + (lg & 1) * 8) * LDR
                              + (ks * 16 + (lg >> 1) * 8) * 2;
                LDMATRIX_X4(ah[mf][0], ah[mf][1], ah[mf][2], ah[mf][3], sA + roff);
            }
            uint32_t trow = ks * 16 + ((lane >> 3) & 1) * 8 + lr;
            uint32_t bh[4][2];
#pragma unroll
            for (int np = 0; np < 2; np++) {
                uint32_t tcol = wn * 32 + np * 16 + ((lane >> 4) & 1) * 8;
                uint32_t r0, r1, r2, r3;
                LDMATRIX_X4_T(r0, r1, r2, r3, sBH + trow * LDB + tcol * 2);
                bh[np * 2][0] = r0; bh[np * 2][1] = r1;
                bh[np * 2 + 1][0] = r2; bh[np * 2 + 1][1] = r3;
            }
#pragma unroll
            for (int mf = 0; mf < 2; mf++)
#pragma unroll
                for (int nf = 0; nf < 4; nf++)
                    MMA16816(acc[mf][nf], ah[mf][0], ah[mf][1], ah[mf][2], ah[mf][3],
                             bh[nf][0], bh[nf][1]);
        }
        __syncthreads();
    }
#pragma unroll
    for (int mf = 0; mf < 2; mf++) {
        int row = wm * 32 + mf * 16 + (lane >> 2);
        float bv0 = bias[row], bv1 = bias[row + 8];
        __half* op0 = out + (size_t)b * C8 * HWV + (size_t)row * HWV
                    + n0 + wn * 32 + (lane & 3) * 2;
        __half* op1 = op0 + (size_t)8 * HWV;
#pragma unroll
        for (int nf = 0; nf < 4; nf++) {
            *(__half2*)(op0 + nf * 8) = __floats2half2_rn(acc[mf][nf][0] + bv0, acc[mf][nf][1] + bv0);
            *(__half2*)(op1 + nf * 8) = __floats2half2_rn(acc[mf][nf][2] + bv1, acc[mf][nf][3] + bv1);
        }
    }
}

// ---------------- gemmVK: 3-stage pipeline -----------------------------------
#define GVK_A    0          // 3 x 10240
#define GVK_STG  30720      // 3 x 16384
#define GVK_BH   79872      // 2 x 8704
#define GVK_SM   97280

__global__ void __launch_bounds__(256, 1) gemmvk_mma_kernel(
    __half* __restrict__ outV, __half* __restrict__ outK,
    const __half* __restrict__ Aw, const float* __restrict__ X,
    const float* __restrict__ bias)
{
    extern __shared__ char smem[];
    uint32_t sbase = smem_u32(smem);
    int tid = threadIdx.x, wid = tid >> 5, lane = tid & 31;
    int m0 = blockIdx.x * 128, n0 = blockIdx.y * 128, b = blockIdx.z;
    int wm = wid & 3, wn = wid >> 2;

    const __half* Ahb = Aw + (size_t)m0 * CCH;
    const float* Xb = X + (size_t)b * CCH * HWV + n0;

    float acc[2][8][4];
#pragma unroll
    for (int i = 0; i < 2; i++)
#pragma unroll
        for (int j = 0; j < 8; j++)
#pragma unroll
            for (int k = 0; k < 4; k++) acc[i][j][k] = 0.f;

    int lg = lane >> 3, lr = lane & 7;

    auto issue = [&](int c, int sb) {
        int kc0 = c * 32;
#pragma unroll
        for (int i = 0; i < 2; i++) {
            int idx = i * 256 + tid;
            int r = idx >> 2, seg = idx & 3;
            CP_ASYNC16(sbase + GVK_A + sb * 10240 + r * LDR + seg * 16,
                       Ahb + (size_t)r * CCH + kc0 + seg * 8);
        }
#pragma unroll
        for (int i = 0; i < 4; i++) {
            int idx = i * 256 + tid;
            int r = idx >> 5, seg = idx & 31;
            CP_ASYNC16(sbase + GVK_STG + sb * 16384 + r * 512 + seg * 16,
                       Xb + (size_t)(kc0 + r) * HWV + seg * 4);
        }
        CP_COMMIT();
    };

    issue(0, 0); issue(1, 1);
    for (int c = 0; c < 16; c++) {
        int sb = c % 3, hb = c & 1;
        if (c < 15) CP_WAIT1(); else CP_WAIT0();
        {
            const char* stg = smem + GVK_STG + sb * 16384;
            char* bh = smem + GVK_BH + hb * 8704;
#pragma unroll
            for (int i = 0; i < 4; i++) {
                int idx = i * 256 + tid;
                int r = idx >> 5, cc = idx & 31;
                float4 f = *(const float4*)(stg + r * 512 + cc * 16);
                uint2 hv = make_uint2(
                    pkh(__float2half_rn(f.x), __float2half_rn(f.y)),
                    pkh(__float2half_rn(f.z), __float2half_rn(f.w)));
                *(uint2*)(bh + r * LDB + cc * 8) = hv;
            }
        }
        __syncthreads();
        if (c < 14) issue(c + 2, (c + 2) % 3);

        uint32_t sA = sbase + GVK_A + sb * 10240;
        uint32_t sBH = sbase + GVK_BH + hb * 8704;
#pragma unroll
        for (int ks = 0; ks < 2; ks++) {
            uint32_t ah[2][4];
#pragma unroll
            for (int mf = 0; mf < 2; mf++) {
                uint32_t roff = (wm * 32 + mf * 16 + lr + (lg & 1) * 8) * LDR
                              + (ks * 16 + (lg >> 1) * 8) * 2;
                LDMATRIX_X4(ah[mf][0], ah[mf][1], ah[mf][2], ah[mf][3], sA + roff);
            }
            uint32_t trow = ks * 16 + ((lane >> 3) & 1) * 8 + lr;
            uint32_t bh[8][2];
#pragma unroll
            for (int np = 0; np < 4; np++) {
                uint32_t tcol = wn * 64 + np * 16 + ((lane >> 4) & 1) * 8;
                uint32_t r0, r1, r2, r3;
                LDMATRIX_X4_T(r0, r1, r2, r3, sBH + trow * LDB + tcol * 2);
                bh[np * 2][0] = r0; bh[np * 2][1] = r1;
                bh[np * 2 + 1][0] = r2; bh[np * 2 + 1][1] = r3;
            }
#pragma unroll
            for (int mf = 0; mf < 2; mf++)
#pragma unroll
                for (int nf = 0; nf < 8; nf++)
                    MMA16816(acc[mf][nf], ah[mf][0], ah[mf][1], ah[mf][2], ah[mf][3],
                             bh[nf][0], bh[nf][1]);
        }
        __syncthreads();
    }

#pragma unroll
    for (int mf = 0; mf < 2; mf++) {
        int row = m0 + wm * 32 + mf * 16 + (lane >> 2);
        if (row >= 576) continue;
        float bv0 = bias[row], bv1 = bias[row + 8];
        __half* base;
        int r;
        if (row < 512) { base = outV + (size_t)b * CCH * HWV; r = row; }
        else           { base = outK + (size_t)b * C8 * HWV;  r = row - 512; }
        __half* op0 = base + (size_t)r * HWV + n0 + wn * 64 + (lane & 3) * 2;
        __half* op1 = op0 + (size_t)8 * HWV;
#pragma unroll
        for (int nf = 0; nf < 8; nf++) {
            *(__half2*)(op0 + nf * 8) = __floats2half2_rn(acc[mf][nf][0] + bv0, acc[mf][nf][1] + bv0);
            *(__half2*)(op1 + nf * 8) = __floats2half2_rn(acc[mf][nf][2] + bv1, acc[mf][nf][3] + bv1);
        }
    }
}

// ---------------- fp16 transpose [b][c][h][w] -> [b][w][c][h] ----------------
__global__ void transpose_hw_half_p(__half* __restrict__ dst,
                                    const __half* __restrict__ src, int planes) {
    __shared__ __half tile[32][36];
    int p = blockIdx.z;
    int b = p / planes, c = p % planes;
    int w0 = blockIdx.x * 32, h0 = blockIdx.y * 32;
    int tx = threadIdx.x, ty = threadIdx.y;
    const __half* s = src + ((size_t)b * planes + c) * HWV;
#pragma unroll
    for (int r = 0; r < 4; r++) {
        int h = h0 + ty + r * 8;
        tile[ty + r * 8][tx] = s[(size_t)h * WW + w0 + tx];
    }
    __syncthreads();
#pragma unroll
    for (int r = 0; r < 4; r++) {
        int w = w0 + ty + r * 8;
        dst[(((size_t)b * WW + w) * planes + c) * HH + h0 + tx] = tile[tx][ty + r * 8];
    }
}

// ---------------- energy kernels ---------------------------------------------
__global__ void __launch_bounds__(256) energy_h_tc() {
    __shared__ __align__(16) char smh[2 * 64 * LDT];
    uint32_t sA = smem_u32(smh);
    uint32_t sB = sA + 64 * LDT;
    int tid = threadIdx.x, wid = tid >> 5, lane = tid & 31;
    int w = blockIdx.x, b = blockIdx.y;
    int wm = wid & 3, wn = wid >> 2;
    const __half* qt = g_qT16 + ((size_t)(b * WW + w)) * C8 * HH;
    const __half* kt = g_kT16 + ((size_t)(b * WW + w)) * C8 * HH;
#pragma unroll
    for (int i = 0; i < 4; i++) {
        int idx = i * 256 + tid;
        int r = idx >> 4, seg = idx & 15;
        CP_ASYNC16(sA + r * LDT + seg * 16, qt + (size_t)r * HH + seg * 8);
        CP_ASYNC16(sB + r * LDT + seg * 16, kt + (size_t)r * HH + seg * 8);
    }
    CP_COMMIT(); CP_WAIT0();
    __syncthreads();

    float acc[2][8][4];
#pragma unroll
    for (int i = 0; i < 2; i++)
#pragma unroll
        for (int j = 0; j < 8; j++)
#pragma unroll
            for (int k = 0; k < 4; k++) acc[i][j][k] = 0.f;

    int lr = lane & 7;
#pragma unroll
    for (int kk = 0; kk < 4; kk++) {
        uint32_t a[2][4];
#pragma unroll
        for (int mf = 0; mf < 2; mf++) {
            uint32_t krow = kk * 16 + ((lane >> 4) & 1) * 8 + lr;
            uint32_t mcol = wm * 32 + mf * 16 + ((lane >> 3) & 1) * 8;
            LDMATRIX_X4_T(a[mf][0], a[mf][1], a[mf][2], a[mf][3],
                          sA + krow * LDT + mcol * 2);
        }
        uint32_t bf[8][2];
#pragma unroll
        for (int np = 0; np < 4; np++) {
            uint32_t krow = kk * 16 + ((lane >> 3) & 1) * 8 + lr;
            uint32_t ncol = wn * 64 + np * 16 + ((lane >> 4) & 1) * 8;
            uint32_t r0, r1, r2, r3;
            LDMATRIX_X4_T(r0, r1, r2, r3, sB + krow * LDT + ncol * 2);
            bf[np * 2][0] = r0; bf[np * 2][1] = r1;
            bf[np * 2 + 1][0] = r2; bf[np * 2 + 1][1] = r3;
        }
#pragma unroll
        for (int mf = 0; mf < 2; mf++)
#pragma unroll
            for (int nf = 0; nf < 8; nf++)
                MMA16816(acc[mf][nf], a[mf][0], a[mf][1], a[mf][2], a[mf][3],
                         bf[nf][0], bf[nf][1]);
    }
    __half* base = g_eH + (((size_t)b * WW + w) * HH) * 128;
#pragma unroll
    for (int mf = 0; mf < 2; mf++) {
        int h0 = wm * 32 + mf * 16 + (lane >> 2);
        int h1 = h0 + 8;
#pragma unroll
        for (int nf = 0; nf < 8; nf++) {
            int j0 = wn * 64 + nf * 8 + (lane & 3) * 2;
            float v00 = (j0 == h0)     ? -30000.f : acc[mf][nf][0];
            float v01 = (j0 + 1 == h0) ? -30000.f : acc[mf][nf][1];
            float v10 = (j0 == h1)     ? -30000.f : acc[mf][nf][2];
            float v11 = (j0 + 1 == h1) ? -30000.f : acc[mf][nf][3];
            *(__half2*)(base + (size_t)h0 * 128 + j0) = __floats2half2_rn(v00, v01);
            *(__half2*)(base + (size_t)h1 * 128 + j0) = __floats2half2_rn(v10, v11);
        }
    }
}

__global__ void __launch_bounds__(256) energy_w_tc() {
    __shared__ __align__(16) char smh[2 * 64 * LDT];
    uint32_t sA = smem_u32(smh);
    uint32_t sB = sA + 64 * LDT;
    int tid = threadIdx.x, wid = tid >> 5, lane = tid & 31;
    int h = blockIdx.x, b = blockIdx.y;
    int wm = wid & 3, wn = wid >> 2;
    const __half* qp = g_q16 + (size_t)b * C8 * HWV + (size_t)h * WW;
    const __half* kp = g_k16 + (size_t)b * C8 * HWV + (size_t)h * WW;
#pragma unroll
    for (int i = 0; i < 4; i++) {
        int idx = i * 256 + tid;
        int r = idx >> 4, seg = idx & 15;
        CP_ASYNC16(sA + r * LDT + seg * 16, qp + (size_t)r * HWV + seg * 8);
        CP_ASYNC16(sB + r * LDT + seg * 16, kp + (size_t)r * HWV + seg * 8);
    }
    CP_COMMIT(); CP_WAIT0();
    __syncthreads();

    float acc[2][8][4];
#pragma unroll
    for (int i = 0; i < 2; i++)
#pragma unroll
        for (int j = 0; j < 8; j++)
#pragma unroll
            for (int k = 0; k < 4; k++) acc[i][j][k] = 0.f;

    int lr = lane & 7;
#pragma unroll
    for (int kk = 0; kk < 4; kk++) {
        uint32_t a[2][4];
#pragma unroll
        for (int mf = 0; mf < 2; mf++) {
            uint32_t krow = kk * 16 + ((lane >> 4) & 1) * 8 + lr;
            uint32_t mcol = wm * 32 + mf * 16 + ((lane >> 3) & 1) * 8;
            LDMATRIX_X4_T(a[mf][0], a[mf][1], a[mf][2], a[mf][3],
                          sA + krow * LDT + mcol * 2);
        }
        uint32_t bf[8][2];
#pragma unroll
        for (int np = 0; np < 4; np++) {
            uint32_t krow = kk * 16 + ((lane >> 3) & 1) * 8 + lr;
            uint32_t ncol = wn * 64 + np * 16 + ((lane >> 4) & 1) * 8;
            uint32_t r0, r1, r2, r3;
            LDMATRIX_X4_T(r0, r1, r2, r3, sB + krow * LDT + ncol * 2);
            bf[np * 2][0] = r0; bf[np * 2][1] = r1;
            bf[np * 2 + 1][0] = r2; bf[np * 2 + 1][1] = r3;
        }
#pragma unroll
        for (int mf = 0; mf < 2; mf++)
#pragma unroll
            for (int nf = 0; nf < 8; nf++)
                MMA16816(acc[mf][nf], a[mf][0], a[mf][1], a[mf][2], a[mf][3],
                         bf[nf][0], bf[nf][1]);
    }
    __half* base = g_eW + (((size_t)b * HH + h) * WW) * 128;
#pragma unroll
    for (int mf = 0; mf < 2; mf++) {
        int w0 = wm * 32 + mf * 16 + (lane >> 2);
        int w1 = w0 + 8;
#pragma unroll
        for (int nf = 0; nf < 8; nf++) {
            int j0 = wn * 64 + nf * 8 + (lane & 3) * 2;
            *(__half2*)(base + (size_t)w0 * 128 + j0) = __floats2half2_rn(acc[mf][nf][0], acc[mf][nf][1]);
            *(__half2*)(base + (size_t)w1 * 128 + j0) = __floats2half2_rn(acc[mf][nf][2], acc[mf][nf][3]);
        }
    }
}

// ---------------- stats --------------------------------------------------------
__global__ void stats_kernel() {
    int row  = blockIdx.x * 8 + (threadIdx.x >> 5);
    int lane = threadIdx.x & 31;
    int b = row >> 14, h = (row >> 7) & 127, w = row & 127;
    const __half* pH = g_eH + (((size_t)b * WW + w) * HH + h) * 128;
    const __half* pW = g_eW + (size_t)row * 128;
    float v[8];
    float m = -CUDART_INF_F;
#pragma unroll
    for (int i = 0; i < 4; i++) { v[i] = __half2float(pH[lane + 32 * i]); m = fmaxf(m, v[i]); }
#pragma unroll
    for (int i = 4; i < 8; i++) { v[i] = __half2float(pW[lane + 32 * (i - 4)]); m = fmaxf(m, v[i]); }
#pragma unroll
    for (int o = 16; o > 0; o >>= 1) m = fmaxf(m, __shfl_xor_sync(0xffffffffu, m, o));
    float s = 0.f;
#pragma unroll
    for (int i = 0; i < 8; i++) s += __expf(v[i] - m);
#pragma unroll
    for (int o = 16; o > 0; o >>= 1) s += __shfl_xor_sync(0xffffffffu, s, o);
    if (lane == 0) g_stats[row] = make_float2(m, 1.0f / s);
}

// ---------------- attn out (fused softmax-apply) ------------------------------
#define AT_A   0
#define AT_B   69632
#define AT_ST  104448
#define AT_SM  105472

__global__ void __launch_bounds__(256, 1) attn_fused_kernel(
    __half* __restrict__ out,
    const __half* __restrict__ A, size_t aF, size_t aRow,
    const __half* __restrict__ Bm, int sOffF, int sStrN)
{
    extern __shared__ char smem[];
    uint32_t sbase = smem_u32(smem);
    float2* sStat = (float2*)(smem + AT_ST);
    int tid = threadIdx.x, wid = tid >> 5, lane = tid & 31;
    int f = blockIdx.x, b = blockIdx.y;
    int wm = wid & 3, wn = wid >> 2;

    const __half* Ab = A + (size_t)b * CCH * HWV + (size_t)f * aF;
    const __half* Bc = Bm + ((size_t)b * 128 + f) * 16384;

    if (tid < 128)
        sStat[tid] = g_stats[(size_t)b * 16384 + (size_t)f * sOffF + (size_t)tid * sStrN];

    auto issueA = [&](int ct, int buf) {
#pragma unroll
        for (int i = 0; i < 8; i++) {
            int idx = i * 256 + tid;
            int r = idx >> 4, seg = idx & 15;
            CP_ASYNC16(sbase + AT_A + buf * 34816 + r * LDT + seg * 16,
                       Ab + (size_t)(ct * 128 + r) * aRow + seg * 8);
        }
    };

    issueA(0, 0);
#pragma unroll
    for (int i = 0; i < 8; i++) {
        int idx = i * 256 + tid;
        int r = idx >> 4, seg = idx & 15;
        CP_ASYNC16(sbase + AT_B + r * LDT + seg * 16, Bc + (size_t)r * 128 + seg * 8);
    }
    CP_COMMIT(); CP_WAIT0();
    __syncthreads();

#pragma unroll
    for (int i = 0; i < 32; i++) {
        int idx = i * 256 + tid;
        int r = idx >> 6, cp2 = idx & 63;
        char* p = smem + AT_B + r * LDT + cp2 * 4;
        __half2 hv = *(__half2*)p;
        float2 st = sStat[r];
        float e0 = __expf(__low2float(hv) - st.x) * st.y;
        float e1 = __expf(__high2float(hv) - st.x) * st.y;
        *(__half2*)p = __floats2half2_rn(e0, e1);
    }
    __syncthreads();

    int lg = lane >> 3, lr = lane & 7;
    uint32_t sB = sbase + AT_B;

    for (int ct = 0; ct < 4; ct++) {
        int buf = ct & 1;
        if (ct < 3) { issueA(ct + 1, buf ^ 1); CP_COMMIT(); }

        float acc[2][8][4];
#pragma unroll
        for (int i = 0; i < 2; i++)
#pragma unroll
            for (int j = 0; j < 8; j++)
#pragma unroll
                for (int k = 0; k < 4; k++) acc[i][j][k] = 0.f;

        uint32_t sA = sbase + AT_A + buf * 34816;
#pragma unroll
        for (int kk = 0; kk < 8; kk++) {
            uint32_t a[2][4];
#pragma unroll
            for (int mf = 0; mf < 2; mf++) {
                uint32_t roff = (wm * 32 + mf * 16 + lr + (lg & 1) * 8) * LDT
                              + (kk * 16 + (lg >> 1) * 8) * 2;
                LDMATRIX_X4(a[mf][0], a[mf][1], a[mf][2], a[mf][3], sA + roff);
            }
            uint32_t bf[8][2];
#pragma unroll
            for (int np = 0; np < 4; np++) {
                uint32_t roff = (wn * 64 + np * 16 + (lg >> 1) * 8 + lr) * LDT
                              + (kk * 16 + (lg & 1) * 8) * 2;
                uint32_t r0, r1, r2, r3;
                LDMATRIX_X4(r0, r1, r2, r3, sB + roff);
                bf[np * 2][0] = r0; bf[np * 2][1] = r1;
                bf[np * 2 + 1][0] = r2; bf[np * 2 + 1][1] = r3;
            }
#pragma unroll
            for (int mf = 0; mf < 2; mf++)
#pragma unroll
                for (int nf = 0; nf < 8; nf++)
                    MMA16816(acc[mf][nf], a[mf][0], a[mf][1], a[mf][2], a[mf][3],
                             bf[nf][0], bf[nf][1]);
        }

        __half* oc = out + (size_t)b * CCH * HWV + (size_t)f * 128
                   + (size_t)ct * 128 * HWV;
#pragma unroll
        for (int mf = 0; mf < 2; mf++) {
            int row = wm * 32 + mf * 16 + (lane >> 2);
            __half* op0 = oc + (size_t)row * HWV + wn * 64 + (lane & 3) * 2;
            __half* op1 = op0 + (size_t)8 * HWV;
#pragma unroll
            for (int nf = 0; nf < 8; nf++) {
                *(__half2*)(op0 + nf * 8) = __floats2half2_rn(acc[mf][nf][0], acc[mf][nf][1]);
                *(__half2*)(op1 + nf * 8) = __floats2half2_rn(acc[mf][nf][2], acc[mf][nf][3]);
            }
        }
        if (ct < 3) CP_WAIT0();
        __syncthreads();
    }
}

// ---------------- combine ------------------------------------------------------
__global__ void combine_kernel(float* __restrict__ out,
                               const float* __restrict__ xe,
                               const float* __restrict__ xq,
                               const float* __restrict__ g1p,
                               const float* __restrict__ g2p) {
    __shared__ __half tile[32][36];
    int bc = blockIdx.z;
    int w0 = blockIdx.x * 32, h0 = blockIdx.y * 32;
    int tx = threadIdx.x, ty = threadIdx.y;
    size_t base = (size_t)bc * HWV;
#pragma unroll
    for (int r = 0; r < 4; r++) {
        int wv = w0 + ty + r * 8;
        tile[ty + r * 8][tx] = g_s1h[base + (size_t)wv * HH + h0 + tx];
    }
    __syncthreads();
    float gam1 = g1p[0], gam2 = g2p[0];
#pragma unroll
    for (int r = 0; r < 4; r++) {
        int h = h0 + ty + r * 8;
        int wv = w0 + tx;
        size_t idx = base + (size_t)h * WW + wv;
        float t = __half2float(tile[tx][ty + r * 8]) + __half2float(g_s2h[idx]) + 2.0f;
        out[idx]        = fmaf(gam1, t, xe[idx]);
        out[NTOT + idx] = fmaf(gam2, t, xq[idx]);
    }
}

// ---------------- launch ---------------------------------------------------------
extern "C" void kernel_launch(void* const* d_in, const int* in_sizes, int n_in,
                              void* d_out, int out_size) {
    const float* xe = (const float*)d_in[0];
    const float* xq = (const float*)d_in[1];
    const float* Wq = (const float*)d_in[2];
    const float* bq = (const float*)d_in[3];
    const float* Wk = (const float*)d_in[4];
    const float* bk = (const float*)d_in[5];
    const float* Wv = (const float*)d_in[6];
    const float* bv = (const float*)d_in[7];
    const float* g1 = (const float*)d_in[8];
    const float* g2 = (const float*)d_in[9];
    float* out = (float*)d_out;

    __half *pq16, *pk16, *pqT, *pkT, *pvh, *pvTh, *peH, *peW, *ps1h, *ps2h;
    __half *pwq, *pwvk;
    float* pbvk;
    cudaGetSymbolAddress((void**)&pq16, g_q16);
    cudaGetSymbolAddress((void**)&pk16, g_k16);
    cudaGetSymbolAddress((void**)&pqT,  g_qT16);
    cudaGetSymbolAddress((void**)&pkT,  g_kT16);
    cudaGetSymbolAddress((void**)&pvh,  g_vh);
    cudaGetSymbolAddress((void**)&pvTh, g_vTh);
    cudaGetSymbolAddress((void**)&peH,  g_eH);
    cudaGetSymbolAddress((void**)&peW,  g_eW);
    cudaGetSymbolAddress((void**)&ps1h, g_s1h);
    cudaGetSymbolAddress((void**)&ps2h, g_s2h);
    cudaGetSymbolAddress((void**)&pwq,  g_wq16);
    cudaGetSymbolAddress((void**)&pwvk, g_wvk);
    cudaGetSymbolAddress((void**)&pbvk, g_bvk);

    cudaFuncSetAttribute(gemmq_mma_kernel,
                         cudaFuncAttributeMaxDynamicSharedMemorySize, GQ_SM);
    cudaFuncSetAttribute(gemmvk_mma_kernel,
                         cudaFuncAttributeMaxDynamicSharedMemorySize, GVK_SM);
    cudaFuncSetAttribute(attn_fused_kernel,
                         cudaFuncAttributeMaxDynamicSharedMemorySize, AT_SM);

    // merged weight/bias prep
    prep_kernel<<<(PREP_N + 255) / 256, 256>>>(Wq, Wv, Wk, bv, bk);

    // projections
    gemmq_mma_kernel<<<dim3(HWV / 128, 1, BB), 256, GQ_SM>>>(pq16, pwq, xq, bq);
    gemmvk_mma_kernel<<<dim3(5, HWV / 128, BB), 256, GVK_SM>>>(pvh, pk16, pwvk, xe, pbvk);

    // fp16 transposes
    transpose_hw_half_p<<<dim3(4, 4, BB * C8),  dim3(32, 8)>>>(pqT, pq16, C8);
    transpose_hw_half_p<<<dim3(4, 4, BB * C8),  dim3(32, 8)>>>(pkT, pk16, C8);
    transpose_hw_half_p<<<dim3(4, 4, BB * CCH), dim3(32, 8)>>>(pvTh, pvh, CCH);

    // energies + stats
    energy_h_tc<<<dim3(WW, BB), 256>>>();
    energy_w_tc<<<dim3(HH, BB), 256>>>();
    stats_kernel<<<(BB * HH * WW) / 8, 256>>>();

    // attention outputs (fused softmax-apply)
    attn_fused_kernel<<<dim3(WW, BB), 256, AT_SM>>>(
        ps1h, pvTh, (size_t)CCH * 128, 128, peH, 1, 128);
    attn_fused_kernel<<<dim3(HH, BB), 256, AT_SM>>>(
        ps2h, pvh, 128, (size_t)HWV, peW, 128, 1);

    // combine
    combine_kernel<<<dim3(4, 4, BB * CCH), dim3(32, 8)>>>(out, xe, xq, g1, g2);
}